// round 1
// baseline (speedup 1.0000x reference)
#include <cuda_runtime.h>
#include <math.h>

#define BSZ     2
#define SLEN    2048
#define HIDDEN  512
#define FFNDIM  2048
#define HEADS   8
#define KD      64
#define VDIM    1024
#define HSZ     128
#define ROWS    (BSZ*SLEN)          // 4096
#define SCALING 0.125f              // KD^-0.5
#define LN_EPS  1e-5f

// ---------------- scratch (static device globals; no allocs allowed) -------
__device__ float g_q[ROWS*HIDDEN];
__device__ float g_k[ROWS*HIDDEN];
__device__ float g_v[ROWS*VDIM];
__device__ float g_att[ROWS*VDIM];
__device__ float g_proj[ROWS*HIDDEN];
__device__ float g_y[ROWS*HIDDEN];
__device__ float g_f1[ROWS*FFNDIM];
__device__ float g_x[ROWS*HIDDEN];
__device__ float g_scores[(size_t)BSZ*HEADS*SLEN*SLEN];   // 268 MB

// ---------------- shared-tile MMA micro-kernel -----------------------------
// As: [64][17] (row-major, padded), Bs: [16][68] (k-major, padded, 16B-aligned rows)
__device__ __forceinline__ void mma_tile(const float (*As)[17], const float (*Bs)[68],
                                         float acc[4][4], int ty4, int tx4) {
#pragma unroll
    for (int kk = 0; kk < 16; kk++) {
        float a0 = As[ty4 + 0][kk];
        float a1 = As[ty4 + 1][kk];
        float a2 = As[ty4 + 2][kk];
        float a3 = As[ty4 + 3][kk];
        float4 b4 = *(const float4*)&Bs[kk][tx4];
        acc[0][0] += a0*b4.x; acc[0][1] += a0*b4.y; acc[0][2] += a0*b4.z; acc[0][3] += a0*b4.w;
        acc[1][0] += a1*b4.x; acc[1][1] += a1*b4.y; acc[1][2] += a1*b4.z; acc[1][3] += a1*b4.w;
        acc[2][0] += a2*b4.x; acc[2][1] += a2*b4.y; acc[2][2] += a2*b4.z; acc[2][3] += a2*b4.w;
        acc[3][0] += a3*b4.x; acc[3][1] += a3*b4.y; acc[3][2] += a3*b4.z; acc[3][3] += a3*b4.w;
    }
}

// ---------------- generic NN GEMM: C[M,N] = A[M,K] @ B[K,N] (+bias)(relu) --
// M = gridDim.y*64, N = gridDim.x*64. All dims multiples of 64/16, no bounds.
template<bool BIAS, bool RELU>
__global__ __launch_bounds__(256)
void gemm_nn(const float* __restrict__ A, const float* __restrict__ B,
             const float* __restrict__ bias, float* __restrict__ C,
             int K, int lda, int ldb, int ldc) {
    __shared__ float As[64][17];
    __shared__ float Bs[16][68];
    const int bm = blockIdx.y * 64, bn = blockIdx.x * 64;
    const int tid = threadIdx.x;
    const int ty4 = (tid >> 4) * 4, tx4 = (tid & 15) * 4;
    float acc[4][4] = {};

    const int l  = tid * 4;
    const int ra = l >> 4, ca = l & 15;     // A tile: 64 rows x 16 cols
    const int rb = l >> 6, cb = l & 63;     // B tile: 16 rows x 64 cols

    for (int k0 = 0; k0 < K; k0 += 16) {
        float4 va = *(const float4*)&A[(size_t)(bm + ra) * lda + k0 + ca];
        As[ra][ca + 0] = va.x; As[ra][ca + 1] = va.y;
        As[ra][ca + 2] = va.z; As[ra][ca + 3] = va.w;
        float4 vb = *(const float4*)&B[(size_t)(k0 + rb) * ldb + bn + cb];
        *(float4*)&Bs[rb][cb] = vb;
        __syncthreads();
        mma_tile(As, Bs, acc, ty4, tx4);
        __syncthreads();
    }

    const int row0 = bm + ty4, col0 = bn + tx4;
    float4 bb = make_float4(0.f, 0.f, 0.f, 0.f);
    if (BIAS) bb = *(const float4*)&bias[col0];
#pragma unroll
    for (int i = 0; i < 4; i++) {
        float4 o;
        o.x = acc[i][0] + bb.x; o.y = acc[i][1] + bb.y;
        o.z = acc[i][2] + bb.z; o.w = acc[i][3] + bb.w;
        if (RELU) {
            o.x = fmaxf(o.x, 0.f); o.y = fmaxf(o.y, 0.f);
            o.z = fmaxf(o.z, 0.f); o.w = fmaxf(o.w, 0.f);
        }
        *(float4*)&C[(size_t)(row0 + i) * ldc + col0] = o;
    }
}

// ---------------- batched scores: S[b,h,qi,ki] = sum_d q . k (NT) ----------
__global__ __launch_bounds__(256)
void scores_gemm(const float* __restrict__ Q, const float* __restrict__ Kmat,
                 float* __restrict__ S) {
    __shared__ float As[64][17];
    __shared__ float Bs[16][68];
    const int bh = blockIdx.z;
    const int b = bh >> 3, h = bh & 7;
    const float* Ab = Q    + (size_t)b * SLEN * HIDDEN + h * KD;
    const float* Bb = Kmat + (size_t)b * SLEN * HIDDEN + h * KD;
    const int bm = blockIdx.y * 64, bn = blockIdx.x * 64;
    const int tid = threadIdx.x;
    const int ty4 = (tid >> 4) * 4, tx4 = (tid & 15) * 4;
    float acc[4][4] = {};

    const int l = tid * 4;
    const int r = l >> 4, c = l & 15;       // both tiles: 64 seq x 16 d

    for (int k0 = 0; k0 < KD; k0 += 16) {
        float4 va = *(const float4*)&Ab[(size_t)(bm + r) * HIDDEN + k0 + c];
        As[r][c + 0] = va.x; As[r][c + 1] = va.y;
        As[r][c + 2] = va.z; As[r][c + 3] = va.w;
        float4 vb = *(const float4*)&Bb[(size_t)(bn + r) * HIDDEN + k0 + c];
        Bs[c + 0][r] = vb.x; Bs[c + 1][r] = vb.y;   // transpose into [k][n]
        Bs[c + 2][r] = vb.z; Bs[c + 3][r] = vb.w;
        __syncthreads();
        mma_tile(As, Bs, acc, ty4, tx4);
        __syncthreads();
    }

    float* Cb = S + (size_t)bh * SLEN * SLEN;
#pragma unroll
    for (int i = 0; i < 4; i++) {
        float4 o = make_float4(acc[i][0], acc[i][1], acc[i][2], acc[i][3]);
        *(float4*)&Cb[(size_t)(bm + ty4 + i) * SLEN + bn + tx4] = o;
    }
}

// ---------------- batched P @ V: O[b,s,h*128+vd] ---------------------------
__global__ __launch_bounds__(256)
void attv_gemm(const float* __restrict__ S, const float* __restrict__ V,
               float* __restrict__ O) {
    __shared__ float As[64][17];
    __shared__ float Bs[16][68];
    const int bh = blockIdx.z;
    const int b = bh >> 3, h = bh & 7;
    const float* Ab = S + (size_t)bh * SLEN * SLEN;
    const float* Bb = V + (size_t)b * SLEN * VDIM + h * HSZ;
    float*       Cb = O + (size_t)b * SLEN * VDIM + h * HSZ;
    const int bm = blockIdx.y * 64, bn = blockIdx.x * 64;
    const int tid = threadIdx.x;
    const int ty4 = (tid >> 4) * 4, tx4 = (tid & 15) * 4;
    float acc[4][4] = {};

    const int l  = tid * 4;
    const int ra = l >> 4, ca = l & 15;
    const int rb = l >> 6, cb = l & 63;

    for (int k0 = 0; k0 < SLEN; k0 += 16) {
        float4 va = *(const float4*)&Ab[(size_t)(bm + ra) * SLEN + k0 + ca];
        As[ra][ca + 0] = va.x; As[ra][ca + 1] = va.y;
        As[ra][ca + 2] = va.z; As[ra][ca + 3] = va.w;
        float4 vb = *(const float4*)&Bb[(size_t)(k0 + rb) * VDIM + bn + cb];
        *(float4*)&Bs[rb][cb] = vb;
        __syncthreads();
        mma_tile(As, Bs, acc, ty4, tx4);
        __syncthreads();
    }
#pragma unroll
    for (int i = 0; i < 4; i++) {
        float4 o = make_float4(acc[i][0], acc[i][1], acc[i][2], acc[i][3]);
        *(float4*)&Cb[(size_t)(bm + ty4 + i) * VDIM + bn + tx4] = o;
    }
}

// ---------------- xPos rotary (in-place on q or k) -------------------------
__global__ __launch_bounds__(256)
void xpos_kernel(float* __restrict__ p) {
    const int idx = blockIdx.x * 256 + threadIdx.x;   // < BSZ*SLEN*HEADS*32
    const int d2 = idx & 31;
    const int h  = (idx >> 5) & 7;
    const int s  = (idx >> 8) & 2047;
    const int b  = idx >> 19;
    const float base  = (2.f * d2 + 25.6f) / 89.6f;           // (2i+0.4d)/(1.4d)
    const float scale = powf(base, (float)(s - 1024) * (1.f / 512.f));
    const float invf  = powf(10000.f, -(float)d2 * (1.f / 32.f));
    float sv, cv;
    sincosf((float)s * invf, &sv, &cv);
    const float c  = cv * scale;
    const float sn = sv * scale;
    const size_t off = (((size_t)b * SLEN + s) * HEADS + h) * KD + 2 * d2;
    const float x0 = p[off], x1 = p[off + 1];
    p[off]     = x0 * c - x1 * sn;
    p[off + 1] = x1 * c + x0 * sn;
}

// ---------------- block reduction helper -----------------------------------
__device__ __forceinline__ float block_reduce(float v, float* sh, int op) {
#pragma unroll
    for (int o = 16; o; o >>= 1) {
        float t = __shfl_xor_sync(0xffffffffu, v, o);
        v = op ? fmaxf(v, t) : v + t;
    }
    if ((threadIdx.x & 31) == 0) sh[threadIdx.x >> 5] = v;
    __syncthreads();
    if (threadIdx.x < 32) {
        const int nw = blockDim.x >> 5;
        float t = (threadIdx.x < nw) ? sh[threadIdx.x] : (op ? -INFINITY : 0.f);
#pragma unroll
        for (int o = 16; o; o >>= 1) {
            float u = __shfl_xor_sync(0xffffffffu, t, o);
            t = op ? fmaxf(t, u) : t + u;
        }
        if (threadIdx.x == 0) sh[0] = t;
    }
    __syncthreads();
    float r = sh[0];
    __syncthreads();
    return r;
}

// ---------------- softmax over 2048, then *SCALING -------------------------
__global__ __launch_bounds__(256)
void softmax_scale(float* __restrict__ sc) {
    __shared__ float sh[32];
    float* p = sc + (size_t)blockIdx.x * SLEN;
    const int t = threadIdx.x;
    float v[8];
    float mx = -INFINITY;
#pragma unroll
    for (int i = 0; i < 8; i++) { v[i] = p[t + i * 256]; mx = fmaxf(mx, v[i]); }
    mx = block_reduce(mx, sh, 1);
    float sum = 0.f;
#pragma unroll
    for (int i = 0; i < 8; i++) { v[i] = __expf(v[i] - mx); sum += v[i]; }
    sum = block_reduce(sum, sh, 0);
    const float inv = SCALING / sum;
#pragma unroll
    for (int i = 0; i < 8; i++) p[t + i * 256] = v[i] * inv;
}

// ---------------- out = LN(a + b) * g + be (row = 512) ---------------------
__global__ __launch_bounds__(256)
void add_ln(const float* __restrict__ a, const float* __restrict__ b,
            const float* __restrict__ g, const float* __restrict__ be,
            float* __restrict__ out) {
    __shared__ float sh[32];
    const size_t r = (size_t)blockIdx.x * HIDDEN;
    const int t = threadIdx.x;
    float v0 = a[r + t]       + b[r + t];
    float v1 = a[r + t + 256] + b[r + t + 256];
    float mean = block_reduce(v0 + v1, sh, 0) * (1.f / HIDDEN);
    float d0 = v0 - mean, d1 = v1 - mean;
    float var = block_reduce(d0 * d0 + d1 * d1, sh, 0) * (1.f / HIDDEN);
    float inv = rsqrtf(var + LN_EPS);
    out[r + t]       = d0 * inv * g[t]       + be[t];
    out[r + t + 256] = d1 * inv * g[t + 256] + be[t + 256];
}

// ---------------- driver ----------------------------------------------------
extern "C" void kernel_launch(void* const* d_in, const int* in_sizes, int n_in,
                              void* d_out, int out_size) {
    const float* x   = (const float*)d_in[0];
    const float* Wq  = (const float*)d_in[1];
    const float* Wk  = (const float*)d_in[2];
    const float* Wv  = (const float*)d_in[3];
    const float* Wo  = (const float*)d_in[4];
    const float* W1  = (const float*)d_in[5];
    const float* b1  = (const float*)d_in[6];
    const float* W2  = (const float*)d_in[7];
    const float* b2  = (const float*)d_in[8];
    const float* g1  = (const float*)d_in[9];
    const float* be1 = (const float*)d_in[10];
    const float* g2  = (const float*)d_in[11];
    const float* be2 = (const float*)d_in[12];

    float *q, *k, *v, *att, *proj, *y, *f1, *xb, *sc;
    cudaGetSymbolAddress((void**)&q,    g_q);
    cudaGetSymbolAddress((void**)&k,    g_k);
    cudaGetSymbolAddress((void**)&v,    g_v);
    cudaGetSymbolAddress((void**)&att,  g_att);
    cudaGetSymbolAddress((void**)&proj, g_proj);
    cudaGetSymbolAddress((void**)&y,    g_y);
    cudaGetSymbolAddress((void**)&f1,   g_f1);
    cudaGetSymbolAddress((void**)&xb,   g_x);
    cudaGetSymbolAddress((void**)&sc,   g_scores);

    const dim3 T(256);
    for (int i = 0; i < 2; i++) {
        const float* xin  = i ? xb : x;
        float*       xout = i ? (float*)d_out : xb;

        // Q, K, V projections
        gemm_nn<false, false><<<dim3(HIDDEN/64, ROWS/64), T>>>(
            xin, Wq + (size_t)i*HIDDEN*HIDDEN, nullptr, q, HIDDEN, HIDDEN, HIDDEN, HIDDEN);
        gemm_nn<false, false><<<dim3(HIDDEN/64, ROWS/64), T>>>(
            xin, Wk + (size_t)i*HIDDEN*HIDDEN, nullptr, k, HIDDEN, HIDDEN, HIDDEN, HIDDEN);
        gemm_nn<false, false><<<dim3(VDIM/64, ROWS/64), T>>>(
            xin, Wv + (size_t)i*HIDDEN*VDIM, nullptr, v, HIDDEN, HIDDEN, VDIM, VDIM);

        // xPos rotary on q and k
        xpos_kernel<<<(ROWS*HEADS*32)/256, T>>>(q);
        xpos_kernel<<<(ROWS*HEADS*32)/256, T>>>(k);

        // attention: scores -> softmax*scale -> @V
        scores_gemm<<<dim3(SLEN/64, SLEN/64, BSZ*HEADS), T>>>(q, k, sc);
        softmax_scale<<<BSZ*HEADS*SLEN, T>>>(sc);
        attv_gemm<<<dim3(HSZ/64, SLEN/64, BSZ*HEADS), T>>>(sc, v, att);

        // output projection
        gemm_nn<false, false><<<dim3(HIDDEN/64, ROWS/64), T>>>(
            att, Wo + (size_t)i*VDIM*HIDDEN, nullptr, proj, VDIM, VDIM, HIDDEN, HIDDEN);

        // y = LN(x + attn)
        add_ln<<<ROWS, T>>>(xin, proj, g1 + i*HIDDEN, be1 + i*HIDDEN, y);

        // FFN
        gemm_nn<true, true><<<dim3(FFNDIM/64, ROWS/64), T>>>(
            y, W1 + (size_t)i*HIDDEN*FFNDIM, b1 + i*FFNDIM, f1, HIDDEN, HIDDEN, FFNDIM, FFNDIM);
        gemm_nn<true, false><<<dim3(HIDDEN/64, ROWS/64), T>>>(
            f1, W2 + (size_t)i*FFNDIM*HIDDEN, b2 + i*HIDDEN, proj, FFNDIM, FFNDIM, HIDDEN, HIDDEN);

        // x = LN(y + ffn)
        add_ln<<<ROWS, T>>>(y, proj, g2 + i*HIDDEN, be2 + i*HIDDEN, xout);
    }
}

// round 3
// speedup vs baseline: 1.2616x; 1.2616x over previous
#include <cuda_runtime.h>
#include <cuda_bf16.h>
#include <math.h>

#define BSZ     2
#define SLEN    2048
#define HIDDEN  512
#define FFNDIM  2048
#define HEADS   8
#define KD      64
#define VDIM    1024
#define HSZ     128
#define ROWS    (BSZ*SLEN)          // 4096
#define SCALING 0.125f
#define LN_EPS  1e-5f

#define WT_PER_LAYER 3670016
// per-layer offsets inside g_wT
#define OFF_WQ 0
#define OFF_WK 262144
#define OFF_WV 524288
#define OFF_WO 1048576
#define OFF_W1 1572864
#define OFF_W2 2621440

// ---------------- scratch (static device globals) --------------------------
__device__ float g_q[ROWS*HIDDEN];
__device__ float g_k[ROWS*HIDDEN];
__device__ float g_vT[ROWS*VDIM];                      // [b][n=1024][s=2048]
__device__ float g_att[ROWS*VDIM];
__device__ float g_proj[ROWS*HIDDEN];
__device__ float g_y[ROWS*HIDDEN];
__device__ float g_f1[ROWS*FFNDIM];
__device__ float g_x[ROWS*HIDDEN];
__device__ float g_wT[2*WT_PER_LAYER];                 // all weights, [N][K] fp32
__device__ float g_scores[(size_t)BSZ*HEADS*SLEN*SLEN];

// ---------------- fp32 -> bf16 hi/lo pack ----------------------------------
__device__ __forceinline__ void cvt2(float x, float y, unsigned &hi, unsigned &lo) {
    __nv_bfloat16 hx = __float2bfloat16(x), hy = __float2bfloat16(y);
    float rx = x - __bfloat162float(hx);
    float ry = y - __bfloat162float(hy);
    __nv_bfloat16 lx = __float2bfloat16(rx), ly = __float2bfloat16(ry);
    hi = ((unsigned)__bfloat16_as_ushort(hy) << 16) | (unsigned)__bfloat16_as_ushort(hx);
    lo = ((unsigned)__bfloat16_as_ushort(ly) << 16) | (unsigned)__bfloat16_as_ushort(lx);
}

__device__ __forceinline__ void mma16816(float* c,
                                         unsigned a0, unsigned a1, unsigned a2, unsigned a3,
                                         unsigned b0, unsigned b1) {
    asm volatile(
        "mma.sync.aligned.m16n8k16.row.col.f32.bf16.bf16.f32 "
        "{%0,%1,%2,%3}, {%4,%5,%6,%7}, {%8,%9}, {%0,%1,%2,%3};\n"
        : "+f"(c[0]), "+f"(c[1]), "+f"(c[2]), "+f"(c[3])
        : "r"(a0), "r"(a1), "r"(a2), "r"(a3), "r"(b0), "r"(b1));
}

// ---------------- NT GEMM, bf16x2 3-pass tensor core ------------------------
// C[M,N] = A[M,K] * B[N,K]^T, fp32 in/out, bf16 hi/lo internally.
// BM=BN=128, BK=32, 256 threads (8 warps, 2x4), warp tile 64x32.
// MODE 0: plain (z unused). MODE 1: scores (A=q,B=k per head). MODE 2: attv.
// TRANSC: write C transposed as vT[b][n][s] (for V projection).
template<int MODE, bool BIAS, bool RELU, bool TRANSC>
__global__ __launch_bounds__(256)
void gemm_nt(const float* __restrict__ A, const float* __restrict__ B,
             const float* __restrict__ bias, float* __restrict__ C,
             int K, int lda, int ldb, int ldc) {
    __shared__ unsigned As_hi[128*20], As_lo[128*20];
    __shared__ unsigned Bs_hi[128*20], Bs_lo[128*20];

    const int z = blockIdx.z;
    const float* Abase = A;
    const float* Bbase = B;
    float*       Cbase = C;
    if (MODE == 1) {                      // scores: z = b*8+h
        const int b = z >> 3, h = z & 7;
        Abase = A + (size_t)b * SLEN * HIDDEN + h * KD;
        Bbase = B + (size_t)b * SLEN * HIDDEN + h * KD;
        Cbase = C + (size_t)z * SLEN * SLEN;
    } else if (MODE == 2) {               // attv: z = b*8+h
        const int b = z >> 3, h = z & 7;
        Abase = A + (size_t)z * SLEN * SLEN;
        Bbase = B + (size_t)b * VDIM * SLEN + (size_t)h * HSZ * SLEN;
        Cbase = C + (size_t)b * SLEN * VDIM + h * HSZ;
    }

    const int bm = blockIdx.y * 128, bn = blockIdx.x * 128;
    const int tid  = threadIdx.x;
    const int lane = tid & 31, warp = tid >> 5;
    const int g = lane >> 2, tig = lane & 3;
    const int wm = (warp >> 2) * 64, wn = (warp & 3) * 32;

    float acc[4][4][4] = {};

    for (int kt = 0; kt < K; kt += 32) {
        if (kt) __syncthreads();
        // -------- fill: load fp32, split to bf16 hi/lo --------
#pragma unroll
        for (int f = 0; f < 4; f++) {
            const int lin = f * 256 + tid;
            const int row = lin >> 3;
            const int kq  = (lin & 7) << 2;           // 0..28 step 4
            const int si  = row * 20 + (kq >> 1);
            unsigned h0, l0, h1, l1;
            const float4 va = *(const float4*)&Abase[(size_t)(bm + row) * lda + kt + kq];
            cvt2(va.x, va.y, h0, l0); cvt2(va.z, va.w, h1, l1);
            As_hi[si] = h0; As_hi[si + 1] = h1;
            As_lo[si] = l0; As_lo[si + 1] = l1;
            const float4 vb = *(const float4*)&Bbase[(size_t)(bn + row) * ldb + kt + kq];
            cvt2(vb.x, vb.y, h0, l0); cvt2(vb.z, vb.w, h1, l1);
            Bs_hi[si] = h0; Bs_hi[si + 1] = h1;
            Bs_lo[si] = l0; Bs_lo[si + 1] = l1;
        }
        __syncthreads();

        // -------- compute: 2 k16 steps, 3-pass mma --------
#pragma unroll
        for (int ks = 0; ks < 2; ks++) {
            unsigned ah[4][4], al[4][4], bh2[4][2], bl2[4][2];
#pragma unroll
            for (int mt = 0; mt < 4; mt++) {
                const int i0 = (wm + mt * 16 + g) * 20 + ks * 8 + tig;
                ah[mt][0] = As_hi[i0];        al[mt][0] = As_lo[i0];
                ah[mt][1] = As_hi[i0 + 160];  al[mt][1] = As_lo[i0 + 160];
                ah[mt][2] = As_hi[i0 + 4];    al[mt][2] = As_lo[i0 + 4];
                ah[mt][3] = As_hi[i0 + 164];  al[mt][3] = As_lo[i0 + 164];
            }
#pragma unroll
            for (int nt = 0; nt < 4; nt++) {
                const int i0 = (wn + nt * 8 + g) * 20 + ks * 8 + tig;
                bh2[nt][0] = Bs_hi[i0];     bh2[nt][1] = Bs_hi[i0 + 4];
                bl2[nt][0] = Bs_lo[i0];     bl2[nt][1] = Bs_lo[i0 + 4];
            }
#pragma unroll
            for (int mt = 0; mt < 4; mt++)
#pragma unroll
                for (int nt = 0; nt < 4; nt++) {
                    float* c = acc[mt][nt];
                    mma16816(c, ah[mt][0], ah[mt][1], ah[mt][2], ah[mt][3], bh2[nt][0], bh2[nt][1]);
                    mma16816(c, al[mt][0], al[mt][1], al[mt][2], al[mt][3], bh2[nt][0], bh2[nt][1]);
                    mma16816(c, ah[mt][0], ah[mt][1], ah[mt][2], ah[mt][3], bl2[nt][0], bl2[nt][1]);
                }
        }
    }

    // -------- epilogue --------
#pragma unroll
    for (int mt = 0; mt < 4; mt++) {
#pragma unroll
        for (int nt = 0; nt < 4; nt++) {
            const int row = bm + wm + mt * 16 + g;
            const int col = bn + wn + nt * 8 + tig * 2;
            float c0 = acc[mt][nt][0], c1 = acc[mt][nt][1];
            float c2 = acc[mt][nt][2], c3 = acc[mt][nt][3];
            if (BIAS) {
                const float b0 = bias[col], b1 = bias[col + 1];
                c0 += b0; c1 += b1; c2 += b0; c3 += b1;
            }
            if (RELU) {
                c0 = fmaxf(c0, 0.f); c1 = fmaxf(c1, 0.f);
                c2 = fmaxf(c2, 0.f); c3 = fmaxf(c3, 0.f);
            }
            if (TRANSC) {
                // vT[b][col][s] layout: b = row>>11, s = row&2047
                const size_t base = (size_t)(row >> 11) * VDIM * SLEN;
                Cbase[base + (size_t)col       * SLEN + (row & 2047)]       = c0;
                Cbase[base + (size_t)(col + 1) * SLEN + (row & 2047)]       = c1;
                Cbase[base + (size_t)col       * SLEN + ((row + 8) & 2047)] = c2;
                Cbase[base + (size_t)(col + 1) * SLEN + ((row + 8) & 2047)] = c3;
            } else {
                *(float2*)&Cbase[(size_t)row * ldc + col]       = make_float2(c0, c1);
                *(float2*)&Cbase[(size_t)(row + 8) * ldc + col] = make_float2(c2, c3);
            }
        }
    }
}

// ---------------- 32x32 weight transpose: WT[n][k] = W[k][n] ----------------
__global__ __launch_bounds__(256)
void transpose32(const float* __restrict__ src, float* __restrict__ dst, int K, int N) {
    __shared__ float t[32][33];
    const int kb = blockIdx.y * 32, nb = blockIdx.x * 32;
    const int tx = threadIdx.x & 31, ty = threadIdx.x >> 5;   // 32x8
#pragma unroll
    for (int i = ty; i < 32; i += 8)
        t[i][tx] = src[(size_t)(kb + i) * N + nb + tx];
    __syncthreads();
#pragma unroll
    for (int i = ty; i < 32; i += 8)
        dst[(size_t)(nb + i) * K + kb + tx] = t[tx][i];
}

// ---------------- xPos rotary (in-place on q or k) -------------------------
__global__ __launch_bounds__(256)
void xpos_kernel(float* __restrict__ p) {
    const int idx = blockIdx.x * 256 + threadIdx.x;
    const int d2 = idx & 31;
    const int h  = (idx >> 5) & 7;
    const int s  = (idx >> 8) & 2047;
    const int b  = idx >> 19;
    const float base  = (2.f * d2 + 25.6f) / 89.6f;
    const float scale = powf(base, (float)(s - 1024) * (1.f / 512.f));
    const float invf  = powf(10000.f, -(float)d2 * (1.f / 32.f));
    float sv, cv;
    sincosf((float)s * invf, &sv, &cv);
    const float c  = cv * scale;
    const float sn = sv * scale;
    const size_t off = (((size_t)b * SLEN + s) * HEADS + h) * KD + 2 * d2;
    const float x0 = p[off], x1 = p[off + 1];
    p[off]     = x0 * c - x1 * sn;
    p[off + 1] = x1 * c + x0 * sn;
}

// ---------------- block reduction helper -----------------------------------
__device__ __forceinline__ float block_reduce(float v, float* sh, int op) {
#pragma unroll
    for (int o = 16; o; o >>= 1) {
        float t = __shfl_xor_sync(0xffffffffu, v, o);
        v = op ? fmaxf(v, t) : v + t;
    }
    if ((threadIdx.x & 31) == 0) sh[threadIdx.x >> 5] = v;
    __syncthreads();
    if (threadIdx.x < 32) {
        const int nw = blockDim.x >> 5;
        float t = (threadIdx.x < nw) ? sh[threadIdx.x] : (op ? -INFINITY : 0.f);
#pragma unroll
        for (int o = 16; o; o >>= 1) {
            float u = __shfl_xor_sync(0xffffffffu, t, o);
            t = op ? fmaxf(t, u) : t + u;
        }
        if (threadIdx.x == 0) sh[0] = t;
    }
    __syncthreads();
    float r = sh[0];
    __syncthreads();
    return r;
}

// ---------------- softmax over 2048, then *SCALING -------------------------
__global__ __launch_bounds__(256)
void softmax_scale(float* __restrict__ sc) {
    __shared__ float sh[32];
    float* p = sc + (size_t)blockIdx.x * SLEN;
    const int t = threadIdx.x;
    float v[8];
    float mx = -INFINITY;
#pragma unroll
    for (int i = 0; i < 8; i++) { v[i] = p[t + i * 256]; mx = fmaxf(mx, v[i]); }
    mx = block_reduce(mx, sh, 1);
    float sum = 0.f;
#pragma unroll
    for (int i = 0; i < 8; i++) { v[i] = __expf(v[i] - mx); sum += v[i]; }
    sum = block_reduce(sum, sh, 0);
    const float inv = SCALING / sum;
#pragma unroll
    for (int i = 0; i < 8; i++) p[t + i * 256] = v[i] * inv;
}

// ---------------- out = LN(a + b) * g + be (row = 512) ---------------------
__global__ __launch_bounds__(256)
void add_ln(const float* __restrict__ a, const float* __restrict__ b,
            const float* __restrict__ g, const float* __restrict__ be,
            float* __restrict__ out) {
    __shared__ float sh[32];
    const size_t r = (size_t)blockIdx.x * HIDDEN;
    const int t = threadIdx.x;
    float v0 = a[r + t]       + b[r + t];
    float v1 = a[r + t + 256] + b[r + t + 256];
    float mean = block_reduce(v0 + v1, sh, 0) * (1.f / HIDDEN);
    float d0 = v0 - mean, d1 = v1 - mean;
    float var = block_reduce(d0 * d0 + d1 * d1, sh, 0) * (1.f / HIDDEN);
    float inv = rsqrtf(var + LN_EPS);
    out[r + t]       = d0 * inv * g[t]       + be[t];
    out[r + t + 256] = d1 * inv * g[t + 256] + be[t + 256];
}

// ---------------- driver ----------------------------------------------------
extern "C" void kernel_launch(void* const* d_in, const int* in_sizes, int n_in,
                              void* d_out, int out_size) {
    const float* x   = (const float*)d_in[0];
    const float* Wq  = (const float*)d_in[1];
    const float* Wk  = (const float*)d_in[2];
    const float* Wv  = (const float*)d_in[3];
    const float* Wo  = (const float*)d_in[4];
    const float* W1  = (const float*)d_in[5];
    const float* b1  = (const float*)d_in[6];
    const float* W2  = (const float*)d_in[7];
    const float* b2  = (const float*)d_in[8];
    const float* g1  = (const float*)d_in[9];
    const float* be1 = (const float*)d_in[10];
    const float* g2  = (const float*)d_in[11];
    const float* be2 = (const float*)d_in[12];

    float *q, *k, *vT, *att, *proj, *y, *f1, *xb, *sc, *wT;
    cudaGetSymbolAddress((void**)&q,    g_q);
    cudaGetSymbolAddress((void**)&k,    g_k);
    cudaGetSymbolAddress((void**)&vT,   g_vT);
    cudaGetSymbolAddress((void**)&att,  g_att);
    cudaGetSymbolAddress((void**)&proj, g_proj);
    cudaGetSymbolAddress((void**)&y,    g_y);
    cudaGetSymbolAddress((void**)&f1,   g_f1);
    cudaGetSymbolAddress((void**)&xb,   g_x);
    cudaGetSymbolAddress((void**)&sc,   g_scores);
    cudaGetSymbolAddress((void**)&wT,   g_wT);

    const dim3 T(256);

    // ---- pre-transpose all weights to [N][K] (once per call) ----
    for (int l = 0; l < 2; l++) {
        float* base = wT + (size_t)l * WT_PER_LAYER;
        transpose32<<<dim3(HIDDEN/32, HIDDEN/32), T>>>(Wq + (size_t)l*HIDDEN*HIDDEN, base + OFF_WQ, HIDDEN, HIDDEN);
        transpose32<<<dim3(HIDDEN/32, HIDDEN/32), T>>>(Wk + (size_t)l*HIDDEN*HIDDEN, base + OFF_WK, HIDDEN, HIDDEN);
        transpose32<<<dim3(VDIM/32,   HIDDEN/32), T>>>(Wv + (size_t)l*HIDDEN*VDIM,   base + OFF_WV, HIDDEN, VDIM);
        transpose32<<<dim3(HIDDEN/32, VDIM/32),   T>>>(Wo + (size_t)l*VDIM*HIDDEN,   base + OFF_WO, VDIM,   HIDDEN);
        transpose32<<<dim3(FFNDIM/32, HIDDEN/32), T>>>(W1 + (size_t)l*HIDDEN*FFNDIM, base + OFF_W1, HIDDEN, FFNDIM);
        transpose32<<<dim3(HIDDEN/32, FFNDIM/32), T>>>(W2 + (size_t)l*FFNDIM*HIDDEN, base + OFF_W2, FFNDIM, HIDDEN);
    }

    for (int i = 0; i < 2; i++) {
        const float* xin  = i ? xb : x;
        float*       xout = i ? (float*)d_out : xb;
        float* base = wT + (size_t)i * WT_PER_LAYER;

        // Q, K projections; V projection written transposed
        gemm_nt<0,false,false,false><<<dim3(HIDDEN/128, ROWS/128), T>>>(
            xin, base + OFF_WQ, nullptr, q, HIDDEN, HIDDEN, HIDDEN, HIDDEN);
        gemm_nt<0,false,false,false><<<dim3(HIDDEN/128, ROWS/128), T>>>(
            xin, base + OFF_WK, nullptr, k, HIDDEN, HIDDEN, HIDDEN, HIDDEN);
        gemm_nt<0,false,false,true><<<dim3(VDIM/128, ROWS/128), T>>>(
            xin, base + OFF_WV, nullptr, vT, HIDDEN, HIDDEN, HIDDEN, 0);

        // xPos rotary
        xpos_kernel<<<(ROWS*HEADS*32)/256, T>>>(q);
        xpos_kernel<<<(ROWS*HEADS*32)/256, T>>>(k);

        // attention
        gemm_nt<1,false,false,false><<<dim3(SLEN/128, SLEN/128, BSZ*HEADS), T>>>(
            q, k, nullptr, sc, KD, HIDDEN, HIDDEN, SLEN);
        softmax_scale<<<BSZ*HEADS*SLEN, T>>>(sc);
        gemm_nt<2,false,false,false><<<dim3(HSZ/128, SLEN/128, BSZ*HEADS), T>>>(
            sc, vT, nullptr, att, SLEN, SLEN, SLEN, VDIM);

        // output projection
        gemm_nt<0,false,false,false><<<dim3(HIDDEN/128, ROWS/128), T>>>(
            att, base + OFF_WO, nullptr, proj, VDIM, VDIM, VDIM, HIDDEN);

        // y = LN(x + attn)
        add_ln<<<ROWS, T>>>(xin, proj, g1 + i*HIDDEN, be1 + i*HIDDEN, y);

        // FFN
        gemm_nt<0,true,true,false><<<dim3(FFNDIM/128, ROWS/128), T>>>(
            y, base + OFF_W1, b1 + i*FFNDIM, f1, HIDDEN, HIDDEN, HIDDEN, FFNDIM);
        gemm_nt<0,true,false,false><<<dim3(HIDDEN/128, ROWS/128), T>>>(
            f1, base + OFF_W2, b2 + i*HIDDEN, proj, FFNDIM, FFNDIM, FFNDIM, HIDDEN);

        // x = LN(y + ffn)
        add_ln<<<ROWS, T>>>(y, proj, g2 + i*HIDDEN, be2 + i*HIDDEN, xout);
    }
}

// round 8
// speedup vs baseline: 1.8479x; 1.4647x over previous
#include <cuda_runtime.h>
#include <cuda_bf16.h>
#include <math.h>

#define BSZ     2
#define SLEN    2048
#define HIDDEN  512
#define FFNDIM  2048
#define HEADS   8
#define KD      64
#define VDIM    1024
#define HSZ     128
#define ROWS    (BSZ*SLEN)          // 4096
#define SCALING 0.125f
#define LN_EPS  1e-5f

#define WT_PER_LAYER 3670016
#define OFF_WQ 0
#define OFF_WK 262144
#define OFF_WV 524288
#define OFF_WO 1048576
#define OFF_W1 1572864
#define OFF_W2 2621440

typedef __nv_bfloat16 bf16;

// ---------------- scratch ---------------------------------------------------
__device__ float g_q[ROWS*HIDDEN];
__device__ float g_k[ROWS*HIDDEN];
__device__ float g_proj[ROWS*HIDDEN];
__device__ float g_y[ROWS*HIDDEN];
__device__ float g_x[ROWS*HIDDEN];
__device__ float g_scores[(size_t)BSZ*HEADS*SLEN*SLEN];      // 268 MB

__device__ bf16 g_xh[ROWS*HIDDEN],  g_xl[ROWS*HIDDEN];
__device__ bf16 g_qh[ROWS*HIDDEN],  g_ql[ROWS*HIDDEN];
__device__ bf16 g_kh[ROWS*HIDDEN],  g_kl[ROWS*HIDDEN];
__device__ bf16 g_vth[ROWS*VDIM],   g_vtl[ROWS*VDIM];        // [b][n][s]
__device__ bf16 g_atth[ROWS*VDIM],  g_attl[ROWS*VDIM];
__device__ bf16 g_yh[ROWS*HIDDEN],  g_yl[ROWS*HIDDEN];
__device__ bf16 g_f1h[ROWS*FFNDIM], g_f1l[ROWS*FFNDIM];
__device__ bf16 g_sch[(size_t)BSZ*HEADS*SLEN*SLEN];
__device__ bf16 g_scl[(size_t)BSZ*HEADS*SLEN*SLEN];
__device__ bf16 g_wth[2*WT_PER_LAYER], g_wtl[2*WT_PER_LAYER];

// ---------------- helpers ---------------------------------------------------
__device__ __forceinline__ void split_bf(float x, bf16 &hi, bf16 &lo) {
    hi = __float2bfloat16(x);
    lo = __float2bfloat16(x - __bfloat162float(hi));
}

__device__ __forceinline__ void mma16816(float* c,
                                         unsigned a0, unsigned a1, unsigned a2, unsigned a3,
                                         unsigned b0, unsigned b1) {
    asm volatile(
        "mma.sync.aligned.m16n8k16.row.col.f32.bf16.bf16.f32 "
        "{%0,%1,%2,%3}, {%4,%5,%6,%7}, {%8,%9}, {%0,%1,%2,%3};\n"
        : "+f"(c[0]), "+f"(c[1]), "+f"(c[2]), "+f"(c[3])
        : "r"(a0), "r"(a1), "r"(a2), "r"(a3), "r"(b0), "r"(b1));
}

__device__ __forceinline__ void ldsm4(unsigned* r, unsigned a) {
    asm volatile("ldmatrix.sync.aligned.m8n8.x4.shared.b16 {%0,%1,%2,%3}, [%4];\n"
                 : "=r"(r[0]), "=r"(r[1]), "=r"(r[2]), "=r"(r[3]) : "r"(a));
}

__device__ __forceinline__ void cp16(unsigned dst, const void* src) {
    asm volatile("cp.async.cg.shared.global [%0], [%1], 16;\n" :: "r"(dst), "l"(src));
}

// ---------------- NT GEMM: C[M,N] = A[M,K] @ B[N,K]^T ----------------------
// Operands pre-split bf16 hi/lo. BM=BN=128, BK=32, 256 thr, warp 64x32.
// smem per stage: A[128 rows x 128B] (hi chunks 0-3, lo 4-7, XOR swizzle) + B.
// MODE 0 plain, 1 scores (z=b*8+h), 2 attv (z=b*8+h).
// OUT 0: fp32 C. 1: bf16 hi/lo C. 2: bf16 hi/lo transposed into vT[b][n][s].
template<int MODE, bool BIAS, bool RELU, int OUT>
__global__ __launch_bounds__(256)
void gemm_bf(const bf16* __restrict__ Ah, const bf16* __restrict__ Al,
             const bf16* __restrict__ Bh, const bf16* __restrict__ Bl,
             const float* __restrict__ bias,
             float* __restrict__ Cf, bf16* __restrict__ Ch, bf16* __restrict__ Cl,
             int K, int lda, int ldb, int ldc) {
    extern __shared__ char smem[];
    const unsigned s0 = (unsigned)__cvta_generic_to_shared(smem);

    const int z = blockIdx.z;
    if (MODE == 1) {
        const size_t off = (size_t)(z >> 3) * SLEN * HIDDEN + (size_t)(z & 7) * KD;
        Ah += off; Al += off; Bh += off; Bl += off;
        Cf += (size_t)z * SLEN * SLEN;
    } else if (MODE == 2) {
        const size_t aoff = (size_t)z * SLEN * SLEN;
        const size_t boff = ((size_t)(z >> 3) * VDIM + (size_t)(z & 7) * HSZ) * SLEN;
        const size_t coff = (size_t)(z >> 3) * SLEN * VDIM + (size_t)(z & 7) * HSZ;
        Ah += aoff; Al += aoff; Bh += boff; Bl += boff; Ch += coff; Cl += coff;
    }

    const int bm = blockIdx.y * 128, bn = blockIdx.x * 128;
    const int tid = threadIdx.x, lane = tid & 31, warp = tid >> 5;
    const int wm = (warp >> 2) * 64, wn = (warp & 3) * 32;
    const int g = lane >> 2, tig = lane & 3;

    float acc[4][4][4] = {};

    auto issue = [&](int kt, unsigned sA, unsigned sB) {
#pragma unroll
        for (int i = 0; i < 4; i++) {
            const int lin = tid * 4 + i;          // 0..1023
            const int row = lin >> 3, c = lin & 7;
            const unsigned d = (unsigned)(row * 128 + ((c ^ (row & 7)) << 4));
            const int ke = (c & 3) * 8;
            const bf16* as = (c < 4) ? Ah + (size_t)(bm + row) * lda + kt + ke
                                     : Al + (size_t)(bm + row) * lda + kt + ke;
            cp16(sA + d, as);
            const bf16* bs = (c < 4) ? Bh + (size_t)(bn + row) * ldb + kt + ke
                                     : Bl + (size_t)(bn + row) * ldb + kt + ke;
            cp16(sB + d, bs);
        }
        asm volatile("cp.async.commit_group;\n");
    };

    const int nk = K >> 5;
    issue(0, s0, s0 + 16384);

    for (int t = 0; t < nk; t++) {
        const unsigned sA = s0 + (t & 1) * 32768, sB = sA + 16384;
        if (t + 1 < nk) {
            const unsigned pA = s0 + ((t + 1) & 1) * 32768;
            issue((t + 1) * 32, pA, pA + 16384);
            asm volatile("cp.async.wait_group 1;\n");
        } else {
            asm volatile("cp.async.wait_group 0;\n");
        }
        __syncthreads();

#pragma unroll
        for (int ks = 0; ks < 2; ks++) {
            unsigned ah[4][4], al[4][4], bh[4][2], bl[4][2];
#pragma unroll
            for (int mt = 0; mt < 4; mt++) {
                const int r  = wm + mt * 16 + (lane & 15);
                const int lc = 2 * ks + (lane >> 4);
                ldsm4(ah[mt], sA + r * 128 + (( lc      ^ (r & 7)) << 4));
                ldsm4(al[mt], sA + r * 128 + (((lc + 4) ^ (r & 7)) << 4));
            }
#pragma unroll
            for (int p = 0; p < 2; p++) {
                const int r  = wn + p * 16 + (lane & 7) + ((lane >> 4) << 3);
                const int lc = 2 * ks + ((lane >> 3) & 1);
                unsigned th[4], tl[4];
                ldsm4(th, sB + r * 128 + (( lc      ^ (r & 7)) << 4));
                ldsm4(tl, sB + r * 128 + (((lc + 4) ^ (r & 7)) << 4));
                bh[2*p][0] = th[0]; bh[2*p][1] = th[1];
                bh[2*p+1][0] = th[2]; bh[2*p+1][1] = th[3];
                bl[2*p][0] = tl[0]; bl[2*p][1] = tl[1];
                bl[2*p+1][0] = tl[2]; bl[2*p+1][1] = tl[3];
            }
#pragma unroll
            for (int mt = 0; mt < 4; mt++)
#pragma unroll
                for (int nt = 0; nt < 4; nt++) {
                    float* c = acc[mt][nt];
                    mma16816(c, ah[mt][0], ah[mt][1], ah[mt][2], ah[mt][3], bh[nt][0], bh[nt][1]);
                    mma16816(c, al[mt][0], al[mt][1], al[mt][2], al[mt][3], bh[nt][0], bh[nt][1]);
                    mma16816(c, ah[mt][0], ah[mt][1], ah[mt][2], ah[mt][3], bl[nt][0], bl[nt][1]);
                }
        }
        __syncthreads();
    }

    // ---------------- epilogue ----------------
#pragma unroll
    for (int mt = 0; mt < 4; mt++) {
#pragma unroll
        for (int nt = 0; nt < 4; nt++) {
            const int row = bm + wm + mt * 16 + g;
            const int col = bn + wn + nt * 8 + tig * 2;
            float c0 = acc[mt][nt][0], c1 = acc[mt][nt][1];
            float c2 = acc[mt][nt][2], c3 = acc[mt][nt][3];
            if (BIAS) {
                const float b0 = bias[col], b1 = bias[col + 1];
                c0 += b0; c1 += b1; c2 += b0; c3 += b1;
            }
            if (RELU) {
                c0 = fmaxf(c0, 0.f); c1 = fmaxf(c1, 0.f);
                c2 = fmaxf(c2, 0.f); c3 = fmaxf(c3, 0.f);
            }
            if (OUT == 0) {
                *(float2*)&Cf[(size_t)row * ldc + col]       = make_float2(c0, c1);
                *(float2*)&Cf[(size_t)(row + 8) * ldc + col] = make_float2(c2, c3);
            } else if (OUT == 1) {
                bf16 h0, l0, h1, l1, h2, l2, h3, l3;
                split_bf(c0, h0, l0); split_bf(c1, h1, l1);
                split_bf(c2, h2, l2); split_bf(c3, h3, l3);
                *(__nv_bfloat162*)&Ch[(size_t)row * ldc + col]       = __nv_bfloat162(h0, h1);
                *(__nv_bfloat162*)&Cl[(size_t)row * ldc + col]       = __nv_bfloat162(l0, l1);
                *(__nv_bfloat162*)&Ch[(size_t)(row + 8) * ldc + col] = __nv_bfloat162(h2, h3);
                *(__nv_bfloat162*)&Cl[(size_t)(row + 8) * ldc + col] = __nv_bfloat162(l2, l3);
            } else {
                // vT[b][col][s]: b = row>>11, s = row&2047
                const size_t base = (size_t)(row >> 11) * VDIM * SLEN;
                const int s1 = row & 2047, s2 = (row + 8) & 2047;
                bf16 h, l;
                split_bf(c0, h, l);
                Ch[base + (size_t)col * SLEN + s1] = h; Cl[base + (size_t)col * SLEN + s1] = l;
                split_bf(c1, h, l);
                Ch[base + (size_t)(col+1) * SLEN + s1] = h; Cl[base + (size_t)(col+1) * SLEN + s1] = l;
                split_bf(c2, h, l);
                Ch[base + (size_t)col * SLEN + s2] = h; Cl[base + (size_t)col * SLEN + s2] = l;
                split_bf(c3, h, l);
                Ch[base + (size_t)(col+1) * SLEN + s2] = h; Cl[base + (size_t)(col+1) * SLEN + s2] = l;
            }
        }
    }
}

// ---------------- weight transpose + bf16 split: WT[n][k] <- W[k][n] --------
__global__ __launch_bounds__(256)
void transpose_cvt(const float* __restrict__ src, bf16* __restrict__ dh,
                   bf16* __restrict__ dl, int K, int N) {
    __shared__ float t[32][33];
    const int kb = blockIdx.y * 32, nb = blockIdx.x * 32;
    const int tx = threadIdx.x & 31, ty = threadIdx.x >> 5;
#pragma unroll
    for (int i = ty; i < 32; i += 8)
        t[i][tx] = src[(size_t)(kb + i) * N + nb + tx];
    __syncthreads();
#pragma unroll
    for (int i = ty; i < 32; i += 8) {
        bf16 h, l;
        split_bf(t[tx][i], h, l);
        dh[(size_t)(nb + i) * K + kb + tx] = h;
        dl[(size_t)(nb + i) * K + kb + tx] = l;
    }
}

// ---------------- elementwise fp32 -> bf16 hi/lo ----------------------------
__global__ __launch_bounds__(256)
void cvt_split(const float* __restrict__ src, bf16* __restrict__ dh,
               bf16* __restrict__ dl) {
    const int i = blockIdx.x * 256 + threadIdx.x;
    bf16 h, l;
    split_bf(src[i], h, l);
    dh[i] = h; dl[i] = l;
}

// ---------------- xPos rotary: fp32 in -> bf16 hi/lo out --------------------
__global__ __launch_bounds__(256)
void xpos_kernel(const float* __restrict__ p, bf16* __restrict__ oh,
                 bf16* __restrict__ ol) {
    const int idx = blockIdx.x * 256 + threadIdx.x;
    const int d2 = idx & 31;
    const int h  = (idx >> 5) & 7;
    const int s  = (idx >> 8) & 2047;
    const int b  = idx >> 19;
    const float base  = (2.f * d2 + 25.6f) / 89.6f;
    const float scale = powf(base, (float)(s - 1024) * (1.f / 512.f));
    const float invf  = powf(10000.f, -(float)d2 * (1.f / 32.f));
    float sv, cv;
    sincosf((float)s * invf, &sv, &cv);
    const float c  = cv * scale;
    const float sn = sv * scale;
    const size_t off = (((size_t)b * SLEN + s) * HEADS + h) * KD + 2 * d2;
    const float x0 = p[off], x1 = p[off + 1];
    const float r0 = x0 * c - x1 * sn;
    const float r1 = x1 * c + x0 * sn;
    bf16 h0, l0, h1, l1;
    split_bf(r0, h0, l0); split_bf(r1, h1, l1);
    *(__nv_bfloat162*)&oh[off] = __nv_bfloat162(h0, h1);
    *(__nv_bfloat162*)&ol[off] = __nv_bfloat162(l0, l1);
}

// ---------------- block reduce ---------------------------------------------
__device__ __forceinline__ float block_reduce(float v, float* sh, int op) {
#pragma unroll
    for (int o = 16; o; o >>= 1) {
        float t = __shfl_xor_sync(0xffffffffu, v, o);
        v = op ? fmaxf(v, t) : v + t;
    }
    if ((threadIdx.x & 31) == 0) sh[threadIdx.x >> 5] = v;
    __syncthreads();
    if (threadIdx.x < 32) {
        const int nw = blockDim.x >> 5;
        float t = (threadIdx.x < nw) ? sh[threadIdx.x] : (op ? -INFINITY : 0.f);
#pragma unroll
        for (int o = 16; o; o >>= 1) {
            float u = __shfl_xor_sync(0xffffffffu, t, o);
            t = op ? fmaxf(t, u) : t + u;
        }
        if (threadIdx.x == 0) sh[0] = t;
    }
    __syncthreads();
    float r = sh[0];
    __syncthreads();
    return r;
}

// ---------------- softmax * SCALING -> bf16 hi/lo ---------------------------
__global__ __launch_bounds__(256)
void softmax_scale(const float* __restrict__ sc, bf16* __restrict__ oh,
                   bf16* __restrict__ ol) {
    __shared__ float sh[32];
    const size_t r = (size_t)blockIdx.x * SLEN;
    const float* p = sc + r;
    const int t = threadIdx.x;
    float v[8];
    float mx = -INFINITY;
#pragma unroll
    for (int i = 0; i < 8; i++) { v[i] = p[t + i * 256]; mx = fmaxf(mx, v[i]); }
    mx = block_reduce(mx, sh, 1);
    float sum = 0.f;
#pragma unroll
    for (int i = 0; i < 8; i++) { v[i] = __expf(v[i] - mx); sum += v[i]; }
    sum = block_reduce(sum, sh, 0);
    const float inv = SCALING / sum;
#pragma unroll
    for (int i = 0; i < 8; i++) {
        bf16 h, l;
        split_bf(v[i] * inv, h, l);
        oh[r + t + i * 256] = h;
        ol[r + t + i * 256] = l;
    }
}

// ---------------- add + LN -> fp32 out + bf16 hi/lo -------------------------
__global__ __launch_bounds__(256)
void add_ln(const float* __restrict__ a, const float* __restrict__ b,
            const float* __restrict__ g, const float* __restrict__ be,
            float* __restrict__ out, bf16* __restrict__ oh, bf16* __restrict__ ol) {
    __shared__ float sh[32];
    const size_t r = (size_t)blockIdx.x * HIDDEN;
    const int t = threadIdx.x;
    float v0 = a[r + t]       + b[r + t];
    float v1 = a[r + t + 256] + b[r + t + 256];
    float mean = block_reduce(v0 + v1, sh, 0) * (1.f / HIDDEN);
    float d0 = v0 - mean, d1 = v1 - mean;
    float var = block_reduce(d0 * d0 + d1 * d1, sh, 0) * (1.f / HIDDEN);
    float inv = rsqrtf(var + LN_EPS);
    const float o0 = d0 * inv * g[t]       + be[t];
    const float o1 = d1 * inv * g[t + 256] + be[t + 256];
    out[r + t]       = o0;
    out[r + t + 256] = o1;
    bf16 h, l;
    split_bf(o0, h, l); oh[r + t] = h;       ol[r + t] = l;
    split_bf(o1, h, l); oh[r + t + 256] = h; ol[r + t + 256] = l;
}

// ---------------- driver ----------------------------------------------------
#define SMEM_GEMM 65536

extern "C" void kernel_launch(void* const* d_in, const int* in_sizes, int n_in,
                              void* d_out, int out_size) {
    const float* x   = (const float*)d_in[0];
    const float* Wq  = (const float*)d_in[1];
    const float* Wk  = (const float*)d_in[2];
    const float* Wv  = (const float*)d_in[3];
    const float* Wo  = (const float*)d_in[4];
    const float* W1  = (const float*)d_in[5];
    const float* b1  = (const float*)d_in[6];
    const float* W2  = (const float*)d_in[7];
    const float* b2  = (const float*)d_in[8];
    const float* g1  = (const float*)d_in[9];
    const float* be1 = (const float*)d_in[10];
    const float* g2  = (const float*)d_in[11];
    const float* be2 = (const float*)d_in[12];

    float *q, *k, *proj, *y, *xb, *sc;
    bf16 *xh, *xl, *qh, *ql, *kh, *kl, *vth, *vtl, *atth, *attl;
    bf16 *yh, *yl, *f1h, *f1l, *sch, *scl, *wth, *wtl;
    cudaGetSymbolAddress((void**)&q,    g_q);
    cudaGetSymbolAddress((void**)&k,    g_k);
    cudaGetSymbolAddress((void**)&proj, g_proj);
    cudaGetSymbolAddress((void**)&y,    g_y);
    cudaGetSymbolAddress((void**)&xb,   g_x);
    cudaGetSymbolAddress((void**)&sc,   g_scores);
    cudaGetSymbolAddress((void**)&xh,   g_xh);   cudaGetSymbolAddress((void**)&xl,   g_xl);
    cudaGetSymbolAddress((void**)&qh,   g_qh);   cudaGetSymbolAddress((void**)&ql,   g_ql);
    cudaGetSymbolAddress((void**)&kh,   g_kh);   cudaGetSymbolAddress((void**)&kl,   g_kl);
    cudaGetSymbolAddress((void**)&vth,  g_vth);  cudaGetSymbolAddress((void**)&vtl,  g_vtl);
    cudaGetSymbolAddress((void**)&atth, g_atth); cudaGetSymbolAddress((void**)&attl, g_attl);
    cudaGetSymbolAddress((void**)&yh,   g_yh);   cudaGetSymbolAddress((void**)&yl,   g_yl);
    cudaGetSymbolAddress((void**)&f1h,  g_f1h);  cudaGetSymbolAddress((void**)&f1l,  g_f1l);
    cudaGetSymbolAddress((void**)&sch,  g_sch);  cudaGetSymbolAddress((void**)&scl,  g_scl);
    cudaGetSymbolAddress((void**)&wth,  g_wth);  cudaGetSymbolAddress((void**)&wtl,  g_wtl);

    static bool attr_done = false;
    if (!attr_done) {
        cudaFuncSetAttribute((const void*)gemm_bf<0,false,false,0>, cudaFuncAttributeMaxDynamicSharedMemorySize, SMEM_GEMM);
        cudaFuncSetAttribute((const void*)gemm_bf<0,false,false,2>, cudaFuncAttributeMaxDynamicSharedMemorySize, SMEM_GEMM);
        cudaFuncSetAttribute((const void*)gemm_bf<1,false,false,0>, cudaFuncAttributeMaxDynamicSharedMemorySize, SMEM_GEMM);
        cudaFuncSetAttribute((const void*)gemm_bf<2,false,false,1>, cudaFuncAttributeMaxDynamicSharedMemorySize, SMEM_GEMM);
        cudaFuncSetAttribute((const void*)gemm_bf<0,true,true,1>,   cudaFuncAttributeMaxDynamicSharedMemorySize, SMEM_GEMM);
        cudaFuncSetAttribute((const void*)gemm_bf<0,true,false,0>,  cudaFuncAttributeMaxDynamicSharedMemorySize, SMEM_GEMM);
        attr_done = true;
    }

    const dim3 T(256);

    // weights -> transposed bf16 hi/lo
    for (int l = 0; l < 2; l++) {
        bf16* bh = wth + (size_t)l * WT_PER_LAYER;
        bf16* bl = wtl + (size_t)l * WT_PER_LAYER;
        transpose_cvt<<<dim3(HIDDEN/32, HIDDEN/32), T>>>(Wq + (size_t)l*HIDDEN*HIDDEN, bh+OFF_WQ, bl+OFF_WQ, HIDDEN, HIDDEN);
        transpose_cvt<<<dim3(HIDDEN/32, HIDDEN/32), T>>>(Wk + (size_t)l*HIDDEN*HIDDEN, bh+OFF_WK, bl+OFF_WK, HIDDEN, HIDDEN);
        transpose_cvt<<<dim3(VDIM/32,   HIDDEN/32), T>>>(Wv + (size_t)l*HIDDEN*VDIM,   bh+OFF_WV, bl+OFF_WV, HIDDEN, VDIM);
        transpose_cvt<<<dim3(HIDDEN/32, VDIM/32),   T>>>(Wo + (size_t)l*VDIM*HIDDEN,   bh+OFF_WO, bl+OFF_WO, VDIM,   HIDDEN);
        transpose_cvt<<<dim3(FFNDIM/32, HIDDEN/32), T>>>(W1 + (size_t)l*HIDDEN*FFNDIM, bh+OFF_W1, bl+OFF_W1, HIDDEN, FFNDIM);
        transpose_cvt<<<dim3(HIDDEN/32, FFNDIM/32), T>>>(W2 + (size_t)l*FFNDIM*HIDDEN, bh+OFF_W2, bl+OFF_W2, FFNDIM, HIDDEN);
    }

    // initial x -> bf16 hi/lo
    cvt_split<<<(ROWS*HIDDEN)/256, T>>>(x, xh, xl);

    for (int i = 0; i < 2; i++) {
        const float* xin  = i ? xb : x;
        float*       xout = i ? (float*)d_out : xb;
        bf16* bh = wth + (size_t)i * WT_PER_LAYER;
        bf16* bl = wtl + (size_t)i * WT_PER_LAYER;

        // Q, K (fp32 out), V (bf16 transposed out)
        gemm_bf<0,false,false,0><<<dim3(HIDDEN/128, ROWS/128), T, SMEM_GEMM>>>(
            xh, xl, bh+OFF_WQ, bl+OFF_WQ, nullptr, q, nullptr, nullptr, HIDDEN, HIDDEN, HIDDEN, HIDDEN);
        gemm_bf<0,false,false,0><<<dim3(HIDDEN/128, ROWS/128), T, SMEM_GEMM>>>(
            xh, xl, bh+OFF_WK, bl+OFF_WK, nullptr, k, nullptr, nullptr, HIDDEN, HIDDEN, HIDDEN, HIDDEN);
        gemm_bf<0,false,false,2><<<dim3(VDIM/128, ROWS/128), T, SMEM_GEMM>>>(
            xh, xl, bh+OFF_WV, bl+OFF_WV, nullptr, nullptr, vth, vtl, HIDDEN, HIDDEN, HIDDEN, 0);

        // rotary -> bf16 hi/lo q,k
        xpos_kernel<<<(ROWS*HEADS*32)/256, T>>>(q, qh, ql);
        xpos_kernel<<<(ROWS*HEADS*32)/256, T>>>(k, kh, kl);

        // attention
        gemm_bf<1,false,false,0><<<dim3(SLEN/128, SLEN/128, BSZ*HEADS), T, SMEM_GEMM>>>(
            qh, ql, kh, kl, nullptr, sc, nullptr, nullptr, KD, HIDDEN, HIDDEN, SLEN);
        softmax_scale<<<BSZ*HEADS*SLEN, T>>>(sc, sch, scl);
        gemm_bf<2,false,false,1><<<dim3(HSZ/128, SLEN/128, BSZ*HEADS), T, SMEM_GEMM>>>(
            sch, scl, vth, vtl, nullptr, nullptr, atth, attl, SLEN, SLEN, SLEN, VDIM);

        // output projection
        gemm_bf<0,false,false,0><<<dim3(HIDDEN/128, ROWS/128), T, SMEM_GEMM>>>(
            atth, attl, bh+OFF_WO, bl+OFF_WO, nullptr, proj, nullptr, nullptr, VDIM, VDIM, VDIM, HIDDEN);

        // y = LN(x + attn)
        add_ln<<<ROWS, T>>>(xin, proj, g1 + i*HIDDEN, be1 + i*HIDDEN, y, yh, yl);

        // FFN
        gemm_bf<0,true,true,1><<<dim3(FFNDIM/128, ROWS/128), T, SMEM_GEMM>>>(
            yh, yl, bh+OFF_W1, bl+OFF_W1, b1 + i*FFNDIM, nullptr, f1h, f1l, HIDDEN, HIDDEN, HIDDEN, FFNDIM);
        gemm_bf<0,true,false,0><<<dim3(HIDDEN/128, ROWS/128), T, SMEM_GEMM>>>(
            f1h, f1l, bh+OFF_W2, bl+OFF_W2, b2 + i*HIDDEN, proj, nullptr, nullptr, FFNDIM, FFNDIM, FFNDIM, HIDDEN);

        // x = LN(y + ffn)
        add_ln<<<ROWS, T>>>(y, proj, g2 + i*HIDDEN, be2 + i*HIDDEN, xout, xh, xl);
    }
}

// round 11
// speedup vs baseline: 3.5540x; 1.9233x over previous
#include <cuda_runtime.h>
#include <cuda_fp16.h>
#include <math.h>
#include <stdint.h>

#define BSZ     2
#define SLEN    2048
#define HIDDEN  512
#define FFNDIM  2048
#define HEADS   8
#define KD      64
#define VDIM    1024
#define HSZ     128
#define ROWS    (BSZ*SLEN)          // 4096
#define SCALING 0.125f
#define LN_EPS  1e-5f

#define WT_PER_LAYER 3670016
#define OFF_WQ 0
#define OFF_WK 262144
#define OFF_WV 524288
#define OFF_WO 1048576
#define OFF_W1 1572864
#define OFF_W2 2621440

typedef __half f16;

// ---------------- scratch ---------------------------------------------------
__device__ float g_q[ROWS*HIDDEN];
__device__ float g_k[ROWS*HIDDEN];
__device__ float g_proj[ROWS*HIDDEN];
__device__ float g_y[ROWS*HIDDEN];
__device__ float g_x[ROWS*HIDDEN];
__device__ float g_scores[(size_t)BSZ*HEADS*SLEN*SLEN];      // 268 MB

__device__ f16 g_xh[ROWS*HIDDEN],  g_xl[ROWS*HIDDEN];
__device__ f16 g_qh[ROWS*HIDDEN],  g_ql[ROWS*HIDDEN];
__device__ f16 g_kh[ROWS*HIDDEN];                            // B side: single
__device__ f16 g_vt[ROWS*VDIM];                              // [b][n][s] single
__device__ f16 g_atth[ROWS*VDIM],  g_attl[ROWS*VDIM];
__device__ f16 g_yh[ROWS*HIDDEN],  g_yl[ROWS*HIDDEN];
__device__ f16 g_f1h[ROWS*FFNDIM], g_f1l[ROWS*FFNDIM];
__device__ f16 g_sch[(size_t)BSZ*HEADS*SLEN*SLEN];
__device__ f16 g_scl[(size_t)BSZ*HEADS*SLEN*SLEN];
__device__ f16 g_wt[2*WT_PER_LAYER];                         // weights single

// ---------------- helpers ---------------------------------------------------
__device__ __forceinline__ void split_h(float x, f16 &hi, f16 &lo) {
    hi = __float2half_rn(x);
    lo = __float2half_rn(x - __half2float(hi));
}

__device__ __forceinline__ void mma16816(float* c,
                                         unsigned a0, unsigned a1, unsigned a2, unsigned a3,
                                         unsigned b0, unsigned b1) {
    asm volatile(
        "mma.sync.aligned.m16n8k16.row.col.f32.f16.f16.f32 "
        "{%0,%1,%2,%3}, {%4,%5,%6,%7}, {%8,%9}, {%0,%1,%2,%3};\n"
        : "+f"(c[0]), "+f"(c[1]), "+f"(c[2]), "+f"(c[3])
        : "r"(a0), "r"(a1), "r"(a2), "r"(a3), "r"(b0), "r"(b1));
}

__device__ __forceinline__ void ldsm4(unsigned* r, unsigned a) {
    asm volatile("ldmatrix.sync.aligned.m8n8.x4.shared.b16 {%0,%1,%2,%3}, [%4];\n"
                 : "=r"(r[0]), "=r"(r[1]), "=r"(r[2]), "=r"(r[3]) : "r"(a));
}

__device__ __forceinline__ void cp16(unsigned dst, const void* src) {
    asm volatile("cp.async.cg.shared.global [%0], [%1], 16;\n" :: "r"(dst), "l"(src));
}

// ---------------- NT GEMM: C[M,N] = A[M,K] @ B[N,K]^T ----------------------
// A pre-split fp16 hi/lo, B single fp16. 2-pass MMA.
// BM=BN=128, BK=32, 256 thr (8 warps 2x4), warp tile 64x32.
// Stage (24KB): A 128 rows x 128B (hi c0-3, lo c4-7, swz c^(r&7));
//               B 128 rows x 64B  (c0-3, swz c^((r>>1)&3)).
// MODE 0 plain, 1 scores (z=b*8+h), 2 attv (z=b*8+h).
// OUT 0: fp32. 1: fp16 hi/lo. 2: single fp16 transposed vT[b][n][s].
template<int MODE, bool BIAS, bool RELU, int OUT>
__global__ __launch_bounds__(256)
void gemm_f16(const f16* __restrict__ Ah, const f16* __restrict__ Al,
              const f16* __restrict__ B,
              const float* __restrict__ bias,
              float* __restrict__ Cf, f16* __restrict__ Ch, f16* __restrict__ Cl,
              int K, int lda, int ldb, int ldc) {
    extern __shared__ char dsm[];
    unsigned s0 = (unsigned)__cvta_generic_to_shared(dsm);
    s0 = (s0 + 1023) & ~1023u;

    const int z = blockIdx.z;
    if (MODE == 1) {
        const size_t off = (size_t)(z >> 3) * SLEN * HIDDEN + (size_t)(z & 7) * KD;
        Ah += off; Al += off; B += off;
        Cf += (size_t)z * SLEN * SLEN;
    } else if (MODE == 2) {
        const size_t aoff = (size_t)z * SLEN * SLEN;
        const size_t boff = ((size_t)(z >> 3) * VDIM + (size_t)(z & 7) * HSZ) * SLEN;
        const size_t coff = (size_t)(z >> 3) * SLEN * VDIM + (size_t)(z & 7) * HSZ;
        Ah += aoff; Al += aoff; B += boff; Ch += coff; Cl += coff;
    }

    const int bm = blockIdx.y * 128, bn = blockIdx.x * 128;
    const int tid = threadIdx.x, lane = tid & 31, warp = tid >> 5;
    const int wm = (warp >> 2) * 64, wn = (warp & 3) * 32;
    const int g = lane >> 2, tig = lane & 3;

    float acc[4][4][4] = {};

    auto issue = [&](int kt, unsigned SA) {
        const unsigned SB = SA + 16384;
#pragma unroll
        for (int i = 0; i < 6; i++) {
            const int lin = i * 256 + tid;            // 0..1535
            if (i < 4) {                              // A: 1024 chunks
                const int row = lin >> 3, c = lin & 7;
                const unsigned d = SA + row * 128 + ((c ^ (row & 7)) << 4);
                const f16* src = (c < 4) ? Ah + (size_t)(bm + row) * lda + kt + (c & 3) * 8
                                         : Al + (size_t)(bm + row) * lda + kt + (c & 3) * 8;
                cp16(d, src);
            } else {                                  // B: 512 chunks
                const int idx = lin - 1024;
                const int row = idx >> 2, c = idx & 3;
                const unsigned d = SB + row * 64 + ((c ^ ((row >> 1) & 3)) << 4);
                cp16(d, B + (size_t)(bn + row) * ldb + kt + c * 8);
            }
        }
        asm volatile("cp.async.commit_group;\n");
    };

    const int nk = K >> 5;
    issue(0, s0);

    for (int t = 0; t < nk; t++) {
        const unsigned SA = s0 + (t & 1) * 24576;
        const unsigned SB = SA + 16384;
        if (t + 1 < nk) {
            issue((t + 1) * 32, s0 + ((t + 1) & 1) * 24576);
            asm volatile("cp.async.wait_group 1;\n");
        } else {
            asm volatile("cp.async.wait_group 0;\n");
        }
        __syncthreads();

#pragma unroll
        for (int ks = 0; ks < 2; ks++) {
            unsigned ah[4][4], al[4][4], bh[4][2];
#pragma unroll
            for (int mt = 0; mt < 4; mt++) {
                const int r  = wm + mt * 16 + (lane & 15);
                const int lc = 2 * ks + (lane >> 4);
                ldsm4(ah[mt], SA + r * 128 + (( lc      ^ (r & 7)) << 4));
                ldsm4(al[mt], SA + r * 128 + (((lc + 4) ^ (r & 7)) << 4));
            }
#pragma unroll
            for (int p = 0; p < 2; p++) {
                const int r  = wn + p * 16 + (lane & 7) + ((lane >> 4) << 3);
                const int lc = 2 * ks + ((lane >> 3) & 1);
                unsigned th[4];
                ldsm4(th, SB + r * 64 + ((lc ^ ((r >> 1) & 3)) << 4));
                bh[2*p][0]   = th[0]; bh[2*p][1]   = th[1];
                bh[2*p+1][0] = th[2]; bh[2*p+1][1] = th[3];
            }
#pragma unroll
            for (int mt = 0; mt < 4; mt++)
#pragma unroll
                for (int nt = 0; nt < 4; nt++) {
                    float* c = acc[mt][nt];
                    mma16816(c, ah[mt][0], ah[mt][1], ah[mt][2], ah[mt][3], bh[nt][0], bh[nt][1]);
                    mma16816(c, al[mt][0], al[mt][1], al[mt][2], al[mt][3], bh[nt][0], bh[nt][1]);
                }
        }
        __syncthreads();
    }

    // ---------------- epilogue ----------------
#pragma unroll
    for (int mt = 0; mt < 4; mt++) {
#pragma unroll
        for (int nt = 0; nt < 4; nt++) {
            const int row = bm + wm + mt * 16 + g;
            const int col = bn + wn + nt * 8 + tig * 2;
            float c0 = acc[mt][nt][0], c1 = acc[mt][nt][1];
            float c2 = acc[mt][nt][2], c3 = acc[mt][nt][3];
            if (BIAS) {
                const float b0 = bias[col], b1 = bias[col + 1];
                c0 += b0; c1 += b1; c2 += b0; c3 += b1;
            }
            if (RELU) {
                c0 = fmaxf(c0, 0.f); c1 = fmaxf(c1, 0.f);
                c2 = fmaxf(c2, 0.f); c3 = fmaxf(c3, 0.f);
            }
            if (OUT == 0) {
                *(float2*)&Cf[(size_t)row * ldc + col]       = make_float2(c0, c1);
                *(float2*)&Cf[(size_t)(row + 8) * ldc + col] = make_float2(c2, c3);
            } else if (OUT == 1) {
                f16 h0, l0, h1, l1, h2, l2, h3, l3;
                split_h(c0, h0, l0); split_h(c1, h1, l1);
                split_h(c2, h2, l2); split_h(c3, h3, l3);
                *(__half2*)&Ch[(size_t)row * ldc + col]       = __halves2half2(h0, h1);
                *(__half2*)&Cl[(size_t)row * ldc + col]       = __halves2half2(l0, l1);
                *(__half2*)&Ch[(size_t)(row + 8) * ldc + col] = __halves2half2(h2, h3);
                *(__half2*)&Cl[(size_t)(row + 8) * ldc + col] = __halves2half2(l2, l3);
            } else {
                // vT[b][col][s]: b = row>>11, s = row&2047 (single fp16)
                const size_t base = (size_t)(row >> 11) * VDIM * SLEN;
                const int s1 = row & 2047, s2 = (row + 8) & 2047;
                Ch[base + (size_t)col       * SLEN + s1] = __float2half_rn(c0);
                Ch[base + (size_t)(col + 1) * SLEN + s1] = __float2half_rn(c1);
                Ch[base + (size_t)col       * SLEN + s2] = __float2half_rn(c2);
                Ch[base + (size_t)(col + 1) * SLEN + s2] = __float2half_rn(c3);
            }
        }
    }
}

// ---------------- weight transpose + fp16: WT[n][k] <- W[k][n] --------------
__global__ __launch_bounds__(256)
void transpose_cvt(const float* __restrict__ src, f16* __restrict__ dst, int K, int N) {
    __shared__ float t[32][33];
    const int kb = blockIdx.y * 32, nb = blockIdx.x * 32;
    const int tx = threadIdx.x & 31, ty = threadIdx.x >> 5;
#pragma unroll
    for (int i = ty; i < 32; i += 8)
        t[i][tx] = src[(size_t)(kb + i) * N + nb + tx];
    __syncthreads();
#pragma unroll
    for (int i = ty; i < 32; i += 8)
        dst[(size_t)(nb + i) * K + kb + tx] = __float2half_rn(t[tx][i]);
}

// ---------------- elementwise fp32 -> fp16 hi/lo ----------------------------
__global__ __launch_bounds__(256)
void cvt_split(const float* __restrict__ src, f16* __restrict__ dh,
               f16* __restrict__ dl) {
    const int i = blockIdx.x * 256 + threadIdx.x;
    f16 h, l;
    split_h(src[i], h, l);
    dh[i] = h; dl[i] = l;
}

// ---------------- xPos rotary: fp32 in -> fp16 out --------------------------
// SPLIT: write hi/lo (for q). else single fp16 (for k).
template<bool SPLIT>
__global__ __launch_bounds__(256)
void xpos_kernel(const float* __restrict__ p, f16* __restrict__ oh,
                 f16* __restrict__ ol) {
    const int idx = blockIdx.x * 256 + threadIdx.x;
    const int d2 = idx & 31;
    const int h  = (idx >> 5) & 7;
    const int s  = (idx >> 8) & 2047;
    const int b  = idx >> 19;
    const float base  = (2.f * d2 + 25.6f) / 89.6f;
    const float scale = powf(base, (float)(s - 1024) * (1.f / 512.f));
    const float invf  = powf(10000.f, -(float)d2 * (1.f / 32.f));
    float sv, cv;
    sincosf((float)s * invf, &sv, &cv);
    const float c  = cv * scale;
    const float sn = sv * scale;
    const size_t off = (((size_t)b * SLEN + s) * HEADS + h) * KD + 2 * d2;
    const float x0 = p[off], x1 = p[off + 1];
    const float r0 = x0 * c - x1 * sn;
    const float r1 = x1 * c + x0 * sn;
    if (SPLIT) {
        f16 h0, l0, h1, l1;
        split_h(r0, h0, l0); split_h(r1, h1, l1);
        *(__half2*)&oh[off] = __halves2half2(h0, h1);
        *(__half2*)&ol[off] = __halves2half2(l0, l1);
    } else {
        *(__half2*)&oh[off] = __halves2half2(__float2half_rn(r0), __float2half_rn(r1));
    }
}

// ---------------- block reduce ---------------------------------------------
__device__ __forceinline__ float block_reduce(float v, float* sh, int op) {
#pragma unroll
    for (int o = 16; o; o >>= 1) {
        float t = __shfl_xor_sync(0xffffffffu, v, o);
        v = op ? fmaxf(v, t) : v + t;
    }
    if ((threadIdx.x & 31) == 0) sh[threadIdx.x >> 5] = v;
    __syncthreads();
    if (threadIdx.x < 32) {
        const int nw = blockDim.x >> 5;
        float t = (threadIdx.x < nw) ? sh[threadIdx.x] : (op ? -INFINITY : 0.f);
#pragma unroll
        for (int o = 16; o; o >>= 1) {
            float u = __shfl_xor_sync(0xffffffffu, t, o);
            t = op ? fmaxf(t, u) : t + u;
        }
        if (threadIdx.x == 0) sh[0] = t;
    }
    __syncthreads();
    float r = sh[0];
    __syncthreads();
    return r;
}

// ---------------- softmax * SCALING -> fp16 hi/lo ---------------------------
__global__ __launch_bounds__(256)
void softmax_scale(const float* __restrict__ sc, f16* __restrict__ oh,
                   f16* __restrict__ ol) {
    __shared__ float sh[32];
    const size_t r = (size_t)blockIdx.x * SLEN;
    const float* p = sc + r;
    const int t = threadIdx.x;
    float v[8];
    float mx = -INFINITY;
#pragma unroll
    for (int i = 0; i < 8; i++) { v[i] = p[t + i * 256]; mx = fmaxf(mx, v[i]); }
    mx = block_reduce(mx, sh, 1);
    float sum = 0.f;
#pragma unroll
    for (int i = 0; i < 8; i++) { v[i] = __expf(v[i] - mx); sum += v[i]; }
    sum = block_reduce(sum, sh, 0);
    const float inv = SCALING / sum;
#pragma unroll
    for (int i = 0; i < 8; i++) {
        f16 h, l;
        split_h(v[i] * inv, h, l);
        oh[r + t + i * 256] = h;
        ol[r + t + i * 256] = l;
    }
}

// ---------------- add + LN -> fp32 out + fp16 hi/lo -------------------------
__global__ __launch_bounds__(256)
void add_ln(const float* __restrict__ a, const float* __restrict__ b,
            const float* __restrict__ g, const float* __restrict__ be,
            float* __restrict__ out, f16* __restrict__ oh, f16* __restrict__ ol) {
    __shared__ float sh[32];
    const size_t r = (size_t)blockIdx.x * HIDDEN;
    const int t = threadIdx.x;
    float v0 = a[r + t]       + b[r + t];
    float v1 = a[r + t + 256] + b[r + t + 256];
    float mean = block_reduce(v0 + v1, sh, 0) * (1.f / HIDDEN);
    float d0 = v0 - mean, d1 = v1 - mean;
    float var = block_reduce(d0 * d0 + d1 * d1, sh, 0) * (1.f / HIDDEN);
    float inv = rsqrtf(var + LN_EPS);
    const float o0 = d0 * inv * g[t]       + be[t];
    const float o1 = d1 * inv * g[t + 256] + be[t + 256];
    out[r + t]       = o0;
    out[r + t + 256] = o1;
    f16 h, l;
    split_h(o0, h, l); oh[r + t] = h;       ol[r + t] = l;
    split_h(o1, h, l); oh[r + t + 256] = h; ol[r + t + 256] = l;
}

// ---------------- driver ----------------------------------------------------
#define SMEM_GEMM (2*24576 + 1024)

extern "C" void kernel_launch(void* const* d_in, const int* in_sizes, int n_in,
                              void* d_out, int out_size) {
    const float* x   = (const float*)d_in[0];
    const float* Wq  = (const float*)d_in[1];
    const float* Wk  = (const float*)d_in[2];
    const float* Wv  = (const float*)d_in[3];
    const float* Wo  = (const float*)d_in[4];
    const float* W1  = (const float*)d_in[5];
    const float* b1  = (const float*)d_in[6];
    const float* W2  = (const float*)d_in[7];
    const float* b2  = (const float*)d_in[8];
    const float* g1  = (const float*)d_in[9];
    const float* be1 = (const float*)d_in[10];
    const float* g2  = (const float*)d_in[11];
    const float* be2 = (const float*)d_in[12];

    float *q, *k, *proj, *y, *xb, *sc;
    f16 *xh, *xl, *qh, *ql, *kh, *vt, *atth, *attl;
    f16 *yh, *yl, *f1h, *f1l, *sch, *scl, *wt;
    cudaGetSymbolAddress((void**)&q,    g_q);
    cudaGetSymbolAddress((void**)&k,    g_k);
    cudaGetSymbolAddress((void**)&proj, g_proj);
    cudaGetSymbolAddress((void**)&y,    g_y);
    cudaGetSymbolAddress((void**)&xb,   g_x);
    cudaGetSymbolAddress((void**)&sc,   g_scores);
    cudaGetSymbolAddress((void**)&xh,   g_xh);   cudaGetSymbolAddress((void**)&xl,   g_xl);
    cudaGetSymbolAddress((void**)&qh,   g_qh);   cudaGetSymbolAddress((void**)&ql,   g_ql);
    cudaGetSymbolAddress((void**)&kh,   g_kh);
    cudaGetSymbolAddress((void**)&vt,   g_vt);
    cudaGetSymbolAddress((void**)&atth, g_atth); cudaGetSymbolAddress((void**)&attl, g_attl);
    cudaGetSymbolAddress((void**)&yh,   g_yh);   cudaGetSymbolAddress((void**)&yl,   g_yl);
    cudaGetSymbolAddress((void**)&f1h,  g_f1h);  cudaGetSymbolAddress((void**)&f1l,  g_f1l);
    cudaGetSymbolAddress((void**)&sch,  g_sch);  cudaGetSymbolAddress((void**)&scl,  g_scl);
    cudaGetSymbolAddress((void**)&wt,   g_wt);

    static bool attr_done = false;
    if (!attr_done) {
        cudaFuncSetAttribute((const void*)gemm_f16<0,false,false,0>, cudaFuncAttributeMaxDynamicSharedMemorySize, SMEM_GEMM);
        cudaFuncSetAttribute((const void*)gemm_f16<0,false,false,2>, cudaFuncAttributeMaxDynamicSharedMemorySize, SMEM_GEMM);
        cudaFuncSetAttribute((const void*)gemm_f16<1,false,false,0>, cudaFuncAttributeMaxDynamicSharedMemorySize, SMEM_GEMM);
        cudaFuncSetAttribute((const void*)gemm_f16<2,false,false,1>, cudaFuncAttributeMaxDynamicSharedMemorySize, SMEM_GEMM);
        cudaFuncSetAttribute((const void*)gemm_f16<0,true,true,1>,   cudaFuncAttributeMaxDynamicSharedMemorySize, SMEM_GEMM);
        cudaFuncSetAttribute((const void*)gemm_f16<0,true,false,0>,  cudaFuncAttributeMaxDynamicSharedMemorySize, SMEM_GEMM);
        attr_done = true;
    }

    const dim3 T(256);

    // weights -> transposed single fp16
    for (int l = 0; l < 2; l++) {
        f16* base = wt + (size_t)l * WT_PER_LAYER;
        transpose_cvt<<<dim3(HIDDEN/32, HIDDEN/32), T>>>(Wq + (size_t)l*HIDDEN*HIDDEN, base+OFF_WQ, HIDDEN, HIDDEN);
        transpose_cvt<<<dim3(HIDDEN/32, HIDDEN/32), T>>>(Wk + (size_t)l*HIDDEN*HIDDEN, base+OFF_WK, HIDDEN, HIDDEN);
        transpose_cvt<<<dim3(VDIM/32,   HIDDEN/32), T>>>(Wv + (size_t)l*HIDDEN*VDIM,   base+OFF_WV, HIDDEN, VDIM);
        transpose_cvt<<<dim3(HIDDEN/32, VDIM/32),   T>>>(Wo + (size_t)l*VDIM*HIDDEN,   base+OFF_WO, VDIM,   HIDDEN);
        transpose_cvt<<<dim3(FFNDIM/32, HIDDEN/32), T>>>(W1 + (size_t)l*HIDDEN*FFNDIM, base+OFF_W1, HIDDEN, FFNDIM);
        transpose_cvt<<<dim3(HIDDEN/32, FFNDIM/32), T>>>(W2 + (size_t)l*FFNDIM*HIDDEN, base+OFF_W2, FFNDIM, HIDDEN);
    }

    // initial x -> fp16 hi/lo
    cvt_split<<<(ROWS*HIDDEN)/256, T>>>(x, xh, xl);

    for (int i = 0; i < 2; i++) {
        const float* xin  = i ? xb : x;
        float*       xout = i ? (float*)d_out : xb;
        f16* base = wt + (size_t)i * WT_PER_LAYER;

        // Q, K (fp32 out), V (single fp16 transposed out)
        gemm_f16<0,false,false,0><<<dim3(HIDDEN/128, ROWS/128), T, SMEM_GEMM>>>(
            xh, xl, base+OFF_WQ, nullptr, q, nullptr, nullptr, HIDDEN, HIDDEN, HIDDEN, HIDDEN);
        gemm_f16<0,false,false,0><<<dim3(HIDDEN/128, ROWS/128), T, SMEM_GEMM>>>(
            xh, xl, base+OFF_WK, nullptr, k, nullptr, nullptr, HIDDEN, HIDDEN, HIDDEN, HIDDEN);
        gemm_f16<0,false,false,2><<<dim3(VDIM/128, ROWS/128), T, SMEM_GEMM>>>(
            xh, xl, base+OFF_WV, nullptr, nullptr, vt, nullptr, HIDDEN, HIDDEN, HIDDEN, 0);

        // rotary: q -> hi/lo, k -> single
        xpos_kernel<true><<<(ROWS*HEADS*32)/256, T>>>(q, qh, ql);
        xpos_kernel<false><<<(ROWS*HEADS*32)/256, T>>>(k, kh, nullptr);

        // attention
        gemm_f16<1,false,false,0><<<dim3(SLEN/128, SLEN/128, BSZ*HEADS), T, SMEM_GEMM>>>(
            qh, ql, kh, nullptr, sc, nullptr, nullptr, KD, HIDDEN, HIDDEN, SLEN);
        softmax_scale<<<BSZ*HEADS*SLEN, T>>>(sc, sch, scl);
        gemm_f16<2,false,false,1><<<dim3(HSZ/128, SLEN/128, BSZ*HEADS), T, SMEM_GEMM>>>(
            sch, scl, vt, nullptr, nullptr, atth, attl, SLEN, SLEN, SLEN, VDIM);

        // output projection
        gemm_f16<0,false,false,0><<<dim3(HIDDEN/128, ROWS/128), T, SMEM_GEMM>>>(
            atth, attl, base+OFF_WO, nullptr, proj, nullptr, nullptr, VDIM, VDIM, VDIM, HIDDEN);

        // y = LN(x + attn)
        add_ln<<<ROWS, T>>>(xin, proj, g1 + i*HIDDEN, be1 + i*HIDDEN, y, yh, yl);

        // FFN
        gemm_f16<0,true,true,1><<<dim3(FFNDIM/128, ROWS/128), T, SMEM_GEMM>>>(
            yh, yl, base+OFF_W1, b1 + i*FFNDIM, nullptr, f1h, f1l, HIDDEN, HIDDEN, HIDDEN, FFNDIM);
        gemm_f16<0,true,false,0><<<dim3(HIDDEN/128, ROWS/128), T, SMEM_GEMM>>>(
            f1h, f1l, base+OFF_W2, b2 + i*HIDDEN, proj, nullptr, nullptr, FFNDIM, FFNDIM, FFNDIM, HIDDEN);

        // x = LN(y + ffn)
        add_ln<<<ROWS, T>>>(y, proj, g2 + i*HIDDEN, be2 + i*HIDDEN, xout, xh, xl);
    }
}

// round 12
// speedup vs baseline: 5.3411x; 1.5028x over previous
#include <cuda_runtime.h>
#include <cuda_fp16.h>
#include <math.h>
#include <stdint.h>

#define BSZ     2
#define SLEN    2048
#define HIDDEN  512
#define FFNDIM  2048
#define HEADS   8
#define KD      64
#define VDIM    1024
#define HSZ     128
#define ROWS    (BSZ*SLEN)          // 4096
#define SCALING 0.125f
#define LN_EPS  1e-5f

#define WT_PER_LAYER 3670016
#define OFF_WQ 0
#define OFF_WK 262144
#define OFF_WV 524288
#define OFF_WO 1048576
#define OFF_W1 1572864
#define OFF_W2 2621440

typedef __half f16;

// ---------------- scratch ---------------------------------------------------
__device__ float g_q[ROWS*HIDDEN];
__device__ float g_k[ROWS*HIDDEN];
__device__ float g_proj[ROWS*HIDDEN];
__device__ float g_y[ROWS*HIDDEN];
__device__ float g_x[ROWS*HIDDEN];

__device__ f16 g_xh[ROWS*HIDDEN],  g_xl[ROWS*HIDDEN];
__device__ f16 g_qh[ROWS*HIDDEN];                            // single fp16
__device__ f16 g_kh[ROWS*HIDDEN];                            // single fp16
__device__ f16 g_vt[ROWS*VDIM];                              // [b][n][s] single
__device__ f16 g_atth[ROWS*VDIM],  g_attl[ROWS*VDIM];
__device__ f16 g_yh[ROWS*HIDDEN],  g_yl[ROWS*HIDDEN];
__device__ f16 g_f1h[ROWS*FFNDIM], g_f1l[ROWS*FFNDIM];
__device__ f16 g_wt[2*WT_PER_LAYER];                         // weights single

// ---------------- helpers ---------------------------------------------------
__device__ __forceinline__ void split_h(float x, f16 &hi, f16 &lo) {
    hi = __float2half_rn(x);
    lo = __float2half_rn(x - __half2float(hi));
}

__device__ __forceinline__ unsigned h2pack(float lo, float hi) {
    unsigned r;
    asm("cvt.rn.f16x2.f32 %0, %1, %2;" : "=r"(r) : "f"(hi), "f"(lo));
    return r;
}

__device__ __forceinline__ void mma16816(float* c,
                                         unsigned a0, unsigned a1, unsigned a2, unsigned a3,
                                         unsigned b0, unsigned b1) {
    asm volatile(
        "mma.sync.aligned.m16n8k16.row.col.f32.f16.f16.f32 "
        "{%0,%1,%2,%3}, {%4,%5,%6,%7}, {%8,%9}, {%0,%1,%2,%3};\n"
        : "+f"(c[0]), "+f"(c[1]), "+f"(c[2]), "+f"(c[3])
        : "r"(a0), "r"(a1), "r"(a2), "r"(a3), "r"(b0), "r"(b1));
}

__device__ __forceinline__ void ldsm4(unsigned* r, unsigned a) {
    asm volatile("ldmatrix.sync.aligned.m8n8.x4.shared.b16 {%0,%1,%2,%3}, [%4];\n"
                 : "=r"(r[0]), "=r"(r[1]), "=r"(r[2]), "=r"(r[3]) : "r"(a));
}

__device__ __forceinline__ void cp16(unsigned dst, const void* src) {
    asm volatile("cp.async.cg.shared.global [%0], [%1], 16;\n" :: "r"(dst), "l"(src));
}

// ---------------- NT GEMM: C[M,N] = A[M,K] @ B[N,K]^T ----------------------
// A pre-split fp16 hi/lo, B single fp16. 2-pass MMA. (unchanged from R11)
template<int MODE, bool BIAS, bool RELU, int OUT>
__global__ __launch_bounds__(256)
void gemm_f16(const f16* __restrict__ Ah, const f16* __restrict__ Al,
              const f16* __restrict__ B,
              const float* __restrict__ bias,
              float* __restrict__ Cf, f16* __restrict__ Ch, f16* __restrict__ Cl,
              int K, int lda, int ldb, int ldc) {
    extern __shared__ char dsm[];
    unsigned s0 = (unsigned)__cvta_generic_to_shared(dsm);
    s0 = (s0 + 1023) & ~1023u;

    const int bm = blockIdx.y * 128, bn = blockIdx.x * 128;
    const int tid = threadIdx.x, lane = tid & 31, warp = tid >> 5;
    const int wm = (warp >> 2) * 64, wn = (warp & 3) * 32;
    const int g = lane >> 2, tig = lane & 3;

    float acc[4][4][4] = {};

    auto issue = [&](int kt, unsigned SA) {
        const unsigned SB = SA + 16384;
#pragma unroll
        for (int i = 0; i < 6; i++) {
            const int lin = i * 256 + tid;
            if (i < 4) {
                const int row = lin >> 3, c = lin & 7;
                const unsigned d = SA + row * 128 + ((c ^ (row & 7)) << 4);
                const f16* src = (c < 4) ? Ah + (size_t)(bm + row) * lda + kt + (c & 3) * 8
                                         : Al + (size_t)(bm + row) * lda + kt + (c & 3) * 8;
                cp16(d, src);
            } else {
                const int idx = lin - 1024;
                const int row = idx >> 2, c = idx & 3;
                const unsigned d = SB + row * 64 + ((c ^ ((row >> 1) & 3)) << 4);
                cp16(d, B + (size_t)(bn + row) * ldb + kt + c * 8);
            }
        }
        asm volatile("cp.async.commit_group;\n");
    };

    const int nk = K >> 5;
    issue(0, s0);

    for (int t = 0; t < nk; t++) {
        const unsigned SA = s0 + (t & 1) * 24576;
        const unsigned SB = SA + 16384;
        if (t + 1 < nk) {
            issue((t + 1) * 32, s0 + ((t + 1) & 1) * 24576);
            asm volatile("cp.async.wait_group 1;\n");
        } else {
            asm volatile("cp.async.wait_group 0;\n");
        }
        __syncthreads();

#pragma unroll
        for (int ks = 0; ks < 2; ks++) {
            unsigned ah[4][4], al[4][4], bh[4][2];
#pragma unroll
            for (int mt = 0; mt < 4; mt++) {
                const int r  = wm + mt * 16 + (lane & 15);
                const int lc = 2 * ks + (lane >> 4);
                ldsm4(ah[mt], SA + r * 128 + (( lc      ^ (r & 7)) << 4));
                ldsm4(al[mt], SA + r * 128 + (((lc + 4) ^ (r & 7)) << 4));
            }
#pragma unroll
            for (int p = 0; p < 2; p++) {
                const int r  = wn + p * 16 + (lane & 7) + ((lane >> 4) << 3);
                const int lc = 2 * ks + ((lane >> 3) & 1);
                unsigned th[4];
                ldsm4(th, SB + r * 64 + ((lc ^ ((r >> 1) & 3)) << 4));
                bh[2*p][0]   = th[0]; bh[2*p][1]   = th[1];
                bh[2*p+1][0] = th[2]; bh[2*p+1][1] = th[3];
            }
#pragma unroll
            for (int mt = 0; mt < 4; mt++)
#pragma unroll
                for (int nt = 0; nt < 4; nt++) {
                    float* c = acc[mt][nt];
                    mma16816(c, ah[mt][0], ah[mt][1], ah[mt][2], ah[mt][3], bh[nt][0], bh[nt][1]);
                    mma16816(c, al[mt][0], al[mt][1], al[mt][2], al[mt][3], bh[nt][0], bh[nt][1]);
                }
        }
        __syncthreads();
    }

#pragma unroll
    for (int mt = 0; mt < 4; mt++) {
#pragma unroll
        for (int nt = 0; nt < 4; nt++) {
            const int row = bm + wm + mt * 16 + g;
            const int col = bn + wn + nt * 8 + tig * 2;
            float c0 = acc[mt][nt][0], c1 = acc[mt][nt][1];
            float c2 = acc[mt][nt][2], c3 = acc[mt][nt][3];
            if (BIAS) {
                const float b0 = bias[col], b1 = bias[col + 1];
                c0 += b0; c1 += b1; c2 += b0; c3 += b1;
            }
            if (RELU) {
                c0 = fmaxf(c0, 0.f); c1 = fmaxf(c1, 0.f);
                c2 = fmaxf(c2, 0.f); c3 = fmaxf(c3, 0.f);
            }
            if (OUT == 0) {
                *(float2*)&Cf[(size_t)row * ldc + col]       = make_float2(c0, c1);
                *(float2*)&Cf[(size_t)(row + 8) * ldc + col] = make_float2(c2, c3);
            } else if (OUT == 1) {
                f16 h0, l0, h1, l1, h2, l2, h3, l3;
                split_h(c0, h0, l0); split_h(c1, h1, l1);
                split_h(c2, h2, l2); split_h(c3, h3, l3);
                *(__half2*)&Ch[(size_t)row * ldc + col]       = __halves2half2(h0, h1);
                *(__half2*)&Cl[(size_t)row * ldc + col]       = __halves2half2(l0, l1);
                *(__half2*)&Ch[(size_t)(row + 8) * ldc + col] = __halves2half2(h2, h3);
                *(__half2*)&Cl[(size_t)(row + 8) * ldc + col] = __halves2half2(l2, l3);
            } else {
                const size_t base = (size_t)(row >> 11) * VDIM * SLEN;
                const int s1 = row & 2047, s2 = (row + 8) & 2047;
                Ch[base + (size_t)col       * SLEN + s1] = __float2half_rn(c0);
                Ch[base + (size_t)(col + 1) * SLEN + s1] = __float2half_rn(c1);
                Ch[base + (size_t)col       * SLEN + s2] = __float2half_rn(c2);
                Ch[base + (size_t)(col + 1) * SLEN + s2] = __float2half_rn(c3);
            }
        }
    }
}

// ---------------- flash attention: one CTA = (128 q rows) x (one head) ------
// 8 warps, each owns 16 q rows end-to-end. K-tile 128 (16 tiles over SLEN).
// Q single fp16 (resident smem), K single, V single; P single. O fp32 regs.
__global__ __launch_bounds__(256, 1)
void flash_attn(const f16* __restrict__ Q, const f16* __restrict__ Kp,
                const f16* __restrict__ V, f16* __restrict__ Oh, f16* __restrict__ Ol) {
    extern __shared__ char dsm[];
    unsigned s0 = (unsigned)__cvta_generic_to_shared(dsm);
    s0 = (s0 + 1023) & ~1023u;
    const int qt = blockIdx.x, z = blockIdx.y;
    const int b = z >> 3, h = z & 7;
    const int tid = threadIdx.x, lane = tid & 31, warp = tid >> 5;

    const f16* Qb = Q + ((size_t)(b * SLEN + qt * 128)) * HIDDEN + h * KD;
    const f16* Kb = Kp + (size_t)b * SLEN * HIDDEN + h * KD;
    const f16* Vb = V + ((size_t)b * VDIM + h * HSZ) * SLEN;

    const unsigned SQ = s0;          // 16 KB: 128 rows x 128B (swz c^(r&7))

    // Q load folded into first commit group
#pragma unroll
    for (int i = 0; i < 4; i++) {
        const int lin = i * 256 + tid;
        const int row = lin >> 3, c = lin & 7;
        cp16(SQ + row * 128 + ((c ^ (row & 7)) << 4), Qb + (size_t)row * HIDDEN + c * 8);
    }
    auto issue_kv = [&](int kt, int st) {
        const unsigned SK = s0 + 16384 + st * 49152;
        const unsigned SV = SK + 16384;
#pragma unroll
        for (int i = 0; i < 12; i++) {
            const int lin = i * 256 + tid;          // 0..3071
            if (lin < 1024) {                       // K: 128 x 128B
                const int row = lin >> 3, c = lin & 7;
                cp16(SK + row * 128 + ((c ^ (row & 7)) << 4),
                     Kb + (size_t)(kt * 128 + row) * HIDDEN + c * 8);
            } else {                                // V: 128 x 256B
                const int idx = lin - 1024;
                const int n = idx >> 4, c = idx & 15;
                cp16(SV + n * 256 + ((c ^ (n & 7)) << 4),
                     Vb + (size_t)n * SLEN + kt * 128 + c * 8);
            }
        }
        asm volatile("cp.async.commit_group;\n");
    };
    issue_kv(0, 0);

    float O[16][4] = {};
    float m0 = -INFINITY, m1 = -INFINITY, l0 = 0.f, l1 = 0.f;

    const int rA = warp * 16 + (lane & 15);
    const int rB = (lane & 7) + ((lane >> 4) << 3);
    const int cBsel = (lane >> 3) & 1;

    for (int t = 0; t < 16; t++) {
        const int st = t & 1;
        const unsigned SK = s0 + 16384 + st * 49152;
        const unsigned SV = SK + 16384;
        if (t < 15) {
            issue_kv(t + 1, st ^ 1);
            asm volatile("cp.async.wait_group 1;\n");
        } else {
            asm volatile("cp.async.wait_group 0;\n");
        }
        __syncthreads();

        // ---- S = Q K^T (16 x 128 per warp) ----
        float S[16][4] = {};
#pragma unroll
        for (int ks = 0; ks < 4; ks++) {
            unsigned aq[4];
            const int lcA = ks * 2 + (lane >> 4);
            ldsm4(aq, SQ + rA * 128 + ((lcA ^ (rA & 7)) << 4));
            const int lcB = ks * 2 + cBsel;
#pragma unroll
            for (int p = 0; p < 8; p++) {
                const int r2 = p * 16 + rB;
                unsigned tb[4];
                ldsm4(tb, SK + r2 * 128 + ((lcB ^ (r2 & 7)) << 4));
                mma16816(S[2*p],   aq[0], aq[1], aq[2], aq[3], tb[0], tb[1]);
                mma16816(S[2*p+1], aq[0], aq[1], aq[2], aq[3], tb[2], tb[3]);
            }
        }

        // ---- online softmax (rows g and g+8; quad shuffles) ----
        float mx0 = -INFINITY, mx1 = -INFINITY;
#pragma unroll
        for (int nt = 0; nt < 16; nt++) {
            mx0 = fmaxf(mx0, fmaxf(S[nt][0], S[nt][1]));
            mx1 = fmaxf(mx1, fmaxf(S[nt][2], S[nt][3]));
        }
        mx0 = fmaxf(mx0, __shfl_xor_sync(0xffffffffu, mx0, 1));
        mx0 = fmaxf(mx0, __shfl_xor_sync(0xffffffffu, mx0, 2));
        mx1 = fmaxf(mx1, __shfl_xor_sync(0xffffffffu, mx1, 1));
        mx1 = fmaxf(mx1, __shfl_xor_sync(0xffffffffu, mx1, 2));
        const float nm0 = fmaxf(m0, mx0), nm1 = fmaxf(m1, mx1);
        const float sc0 = __expf(m0 - nm0), sc1 = __expf(m1 - nm1);
        m0 = nm0; m1 = nm1;
        float rs0 = 0.f, rs1 = 0.f;
#pragma unroll
        for (int nt = 0; nt < 16; nt++) {
            S[nt][0] = __expf(S[nt][0] - nm0);
            S[nt][1] = __expf(S[nt][1] - nm0);
            S[nt][2] = __expf(S[nt][2] - nm1);
            S[nt][3] = __expf(S[nt][3] - nm1);
            rs0 += S[nt][0] + S[nt][1];
            rs1 += S[nt][2] + S[nt][3];
            O[nt][0] *= sc0; O[nt][1] *= sc0;
            O[nt][2] *= sc1; O[nt][3] *= sc1;
        }
        rs0 += __shfl_xor_sync(0xffffffffu, rs0, 1);
        rs0 += __shfl_xor_sync(0xffffffffu, rs0, 2);
        rs1 += __shfl_xor_sync(0xffffffffu, rs1, 1);
        rs1 += __shfl_xor_sync(0xffffffffu, rs1, 2);
        l0 = l0 * sc0 + rs0;
        l1 = l1 * sc1 + rs1;

        // ---- O += P V (P from S regs: C-frag == A-frag layout) ----
#pragma unroll
        for (int j = 0; j < 8; j++) {
            const unsigned a0 = h2pack(S[2*j][0],   S[2*j][1]);
            const unsigned a1 = h2pack(S[2*j][2],   S[2*j][3]);
            const unsigned a2 = h2pack(S[2*j+1][0], S[2*j+1][1]);
            const unsigned a3 = h2pack(S[2*j+1][2], S[2*j+1][3]);
            const int lcV = j * 2 + cBsel;
#pragma unroll
            for (int p = 0; p < 8; p++) {
                const int r2 = p * 16 + rB;
                unsigned tb[4];
                ldsm4(tb, SV + r2 * 256 + ((lcV ^ (r2 & 7)) << 4));
                mma16816(O[2*p],   a0, a1, a2, a3, tb[0], tb[1]);
                mma16816(O[2*p+1], a0, a1, a2, a3, tb[2], tb[3]);
            }
        }
        __syncthreads();
    }

    // ---- epilogue: att = (O / l) * SCALING, hi/lo split ----
    const float inv0 = SCALING / l0, inv1 = SCALING / l1;
    const int g = lane >> 2, tg = lane & 3;
    const int srow = qt * 128 + warp * 16 + g;
    const size_t base0 = ((size_t)(b * SLEN) + srow) * VDIM + h * HSZ;
    const size_t base1 = base0 + (size_t)8 * VDIM;
#pragma unroll
    for (int nt = 0; nt < 16; nt++) {
        const int col = nt * 8 + tg * 2;
        f16 ha, la, hb, lb;
        split_h(O[nt][0] * inv0, ha, la); split_h(O[nt][1] * inv0, hb, lb);
        *(__half2*)&Oh[base0 + col] = __halves2half2(ha, hb);
        *(__half2*)&Ol[base0 + col] = __halves2half2(la, lb);
        split_h(O[nt][2] * inv1, ha, la); split_h(O[nt][3] * inv1, hb, lb);
        *(__half2*)&Oh[base1 + col] = __halves2half2(ha, hb);
        *(__half2*)&Ol[base1 + col] = __halves2half2(la, lb);
    }
}

// ---------------- weight transpose + fp16 ----------------------------------
__global__ __launch_bounds__(256)
void transpose_cvt(const float* __restrict__ src, f16* __restrict__ dst, int K, int N) {
    __shared__ float t[32][33];
    const int kb = blockIdx.y * 32, nb = blockIdx.x * 32;
    const int tx = threadIdx.x & 31, ty = threadIdx.x >> 5;
#pragma unroll
    for (int i = ty; i < 32; i += 8)
        t[i][tx] = src[(size_t)(kb + i) * N + nb + tx];
    __syncthreads();
#pragma unroll
    for (int i = ty; i < 32; i += 8)
        dst[(size_t)(nb + i) * K + kb + tx] = __float2half_rn(t[tx][i]);
}

__global__ __launch_bounds__(256)
void cvt_split(const float* __restrict__ src, f16* __restrict__ dh,
               f16* __restrict__ dl) {
    const int i = blockIdx.x * 256 + threadIdx.x;
    f16 h, l;
    split_h(src[i], h, l);
    dh[i] = h; dl[i] = l;
}

// ---------------- xPos rotary: fp32 in -> single fp16 out -------------------
__global__ __launch_bounds__(256)
void xpos_kernel(const float* __restrict__ p, f16* __restrict__ oh) {
    const int idx = blockIdx.x * 256 + threadIdx.x;
    const int d2 = idx & 31;
    const int h  = (idx >> 5) & 7;
    const int s  = (idx >> 8) & 2047;
    const int b  = idx >> 19;
    const float base  = (2.f * d2 + 25.6f) / 89.6f;
    const float scale = powf(base, (float)(s - 1024) * (1.f / 512.f));
    const float invf  = powf(10000.f, -(float)d2 * (1.f / 32.f));
    float sv, cv;
    sincosf((float)s * invf, &sv, &cv);
    const float c  = cv * scale;
    const float sn = sv * scale;
    const size_t off = (((size_t)b * SLEN + s) * HEADS + h) * KD + 2 * d2;
    const float x0 = p[off], x1 = p[off + 1];
    *(__half2*)&oh[off] = __halves2half2(__float2half_rn(x0 * c - x1 * sn),
                                         __float2half_rn(x1 * c + x0 * sn));
}

// ---------------- block reduce / add_ln ------------------------------------
__device__ __forceinline__ float block_reduce(float v, float* sh, int op) {
#pragma unroll
    for (int o = 16; o; o >>= 1) {
        float t = __shfl_xor_sync(0xffffffffu, v, o);
        v = op ? fmaxf(v, t) : v + t;
    }
    if ((threadIdx.x & 31) == 0) sh[threadIdx.x >> 5] = v;
    __syncthreads();
    if (threadIdx.x < 32) {
        const int nw = blockDim.x >> 5;
        float t = (threadIdx.x < nw) ? sh[threadIdx.x] : (op ? -INFINITY : 0.f);
#pragma unroll
        for (int o = 16; o; o >>= 1) {
            float u = __shfl_xor_sync(0xffffffffu, t, o);
            t = op ? fmaxf(t, u) : t + u;
        }
        if (threadIdx.x == 0) sh[0] = t;
    }
    __syncthreads();
    float r = sh[0];
    __syncthreads();
    return r;
}

__global__ __launch_bounds__(256)
void add_ln(const float* __restrict__ a, const float* __restrict__ b,
            const float* __restrict__ g, const float* __restrict__ be,
            float* __restrict__ out, f16* __restrict__ oh, f16* __restrict__ ol) {
    __shared__ float sh[32];
    const size_t r = (size_t)blockIdx.x * HIDDEN;
    const int t = threadIdx.x;
    float v0 = a[r + t]       + b[r + t];
    float v1 = a[r + t + 256] + b[r + t + 256];
    float mean = block_reduce(v0 + v1, sh, 0) * (1.f / HIDDEN);
    float d0 = v0 - mean, d1 = v1 - mean;
    float var = block_reduce(d0 * d0 + d1 * d1, sh, 0) * (1.f / HIDDEN);
    float inv = rsqrtf(var + LN_EPS);
    const float o0 = d0 * inv * g[t]       + be[t];
    const float o1 = d1 * inv * g[t + 256] + be[t + 256];
    out[r + t]       = o0;
    out[r + t + 256] = o1;
    f16 h, l;
    split_h(o0, h, l); oh[r + t] = h;       ol[r + t] = l;
    split_h(o1, h, l); oh[r + t + 256] = h; ol[r + t + 256] = l;
}

// ---------------- driver ----------------------------------------------------
#define SMEM_GEMM  (2*24576 + 1024)
#define SMEM_FLASH (16384 + 2*49152 + 1024)

extern "C" void kernel_launch(void* const* d_in, const int* in_sizes, int n_in,
                              void* d_out, int out_size) {
    const float* x   = (const float*)d_in[0];
    const float* Wq  = (const float*)d_in[1];
    const float* Wk  = (const float*)d_in[2];
    const float* Wv  = (const float*)d_in[3];
    const float* Wo  = (const float*)d_in[4];
    const float* W1  = (const float*)d_in[5];
    const float* b1  = (const float*)d_in[6];
    const float* W2  = (const float*)d_in[7];
    const float* b2  = (const float*)d_in[8];
    const float* g1  = (const float*)d_in[9];
    const float* be1 = (const float*)d_in[10];
    const float* g2  = (const float*)d_in[11];
    const float* be2 = (const float*)d_in[12];

    float *q, *k, *proj, *y, *xb;
    f16 *xh, *xl, *qh, *kh, *vt, *atth, *attl, *yh, *yl, *f1h, *f1l, *wt;
    cudaGetSymbolAddress((void**)&q,    g_q);
    cudaGetSymbolAddress((void**)&k,    g_k);
    cudaGetSymbolAddress((void**)&proj, g_proj);
    cudaGetSymbolAddress((void**)&y,    g_y);
    cudaGetSymbolAddress((void**)&xb,   g_x);
    cudaGetSymbolAddress((void**)&xh,   g_xh);   cudaGetSymbolAddress((void**)&xl,   g_xl);
    cudaGetSymbolAddress((void**)&qh,   g_qh);
    cudaGetSymbolAddress((void**)&kh,   g_kh);
    cudaGetSymbolAddress((void**)&vt,   g_vt);
    cudaGetSymbolAddress((void**)&atth, g_atth); cudaGetSymbolAddress((void**)&attl, g_attl);
    cudaGetSymbolAddress((void**)&yh,   g_yh);   cudaGetSymbolAddress((void**)&yl,   g_yl);
    cudaGetSymbolAddress((void**)&f1h,  g_f1h);  cudaGetSymbolAddress((void**)&f1l,  g_f1l);
    cudaGetSymbolAddress((void**)&wt,   g_wt);

    static bool attr_done = false;
    if (!attr_done) {
        cudaFuncSetAttribute((const void*)gemm_f16<0,false,false,0>, cudaFuncAttributeMaxDynamicSharedMemorySize, SMEM_GEMM);
        cudaFuncSetAttribute((const void*)gemm_f16<0,false,false,2>, cudaFuncAttributeMaxDynamicSharedMemorySize, SMEM_GEMM);
        cudaFuncSetAttribute((const void*)gemm_f16<0,true,true,1>,   cudaFuncAttributeMaxDynamicSharedMemorySize, SMEM_GEMM);
        cudaFuncSetAttribute((const void*)gemm_f16<0,true,false,0>,  cudaFuncAttributeMaxDynamicSharedMemorySize, SMEM_GEMM);
        cudaFuncSetAttribute((const void*)flash_attn,                cudaFuncAttributeMaxDynamicSharedMemorySize, SMEM_FLASH);
        attr_done = true;
    }

    const dim3 T(256);

    for (int l = 0; l < 2; l++) {
        f16* base = wt + (size_t)l * WT_PER_LAYER;
        transpose_cvt<<<dim3(HIDDEN/32, HIDDEN/32), T>>>(Wq + (size_t)l*HIDDEN*HIDDEN, base+OFF_WQ, HIDDEN, HIDDEN);
        transpose_cvt<<<dim3(HIDDEN/32, HIDDEN/32), T>>>(Wk + (size_t)l*HIDDEN*HIDDEN, base+OFF_WK, HIDDEN, HIDDEN);
        transpose_cvt<<<dim3(VDIM/32,   HIDDEN/32), T>>>(Wv + (size_t)l*HIDDEN*VDIM,   base+OFF_WV, HIDDEN, VDIM);
        transpose_cvt<<<dim3(HIDDEN/32, VDIM/32),   T>>>(Wo + (size_t)l*VDIM*HIDDEN,   base+OFF_WO, VDIM,   HIDDEN);
        transpose_cvt<<<dim3(FFNDIM/32, HIDDEN/32), T>>>(W1 + (size_t)l*HIDDEN*FFNDIM, base+OFF_W1, HIDDEN, FFNDIM);
        transpose_cvt<<<dim3(HIDDEN/32, FFNDIM/32), T>>>(W2 + (size_t)l*FFNDIM*HIDDEN, base+OFF_W2, FFNDIM, HIDDEN);
    }

    cvt_split<<<(ROWS*HIDDEN)/256, T>>>(x, xh, xl);

    for (int i = 0; i < 2; i++) {
        const float* xin  = i ? xb : x;
        float*       xout = i ? (float*)d_out : xb;
        f16* base = wt + (size_t)i * WT_PER_LAYER;

        gemm_f16<0,false,false,0><<<dim3(HIDDEN/128, ROWS/128), T, SMEM_GEMM>>>(
            xh, xl, base+OFF_WQ, nullptr, q, nullptr, nullptr, HIDDEN, HIDDEN, HIDDEN, HIDDEN);
        gemm_f16<0,false,false,0><<<dim3(HIDDEN/128, ROWS/128), T, SMEM_GEMM>>>(
            xh, xl, base+OFF_WK, nullptr, k, nullptr, nullptr, HIDDEN, HIDDEN, HIDDEN, HIDDEN);
        gemm_f16<0,false,false,2><<<dim3(VDIM/128, ROWS/128), T, SMEM_GEMM>>>(
            xh, xl, base+OFF_WV, nullptr, nullptr, vt, nullptr, HIDDEN, HIDDEN, HIDDEN, 0);

        xpos_kernel<<<(ROWS*HEADS*32)/256, T>>>(q, qh);
        xpos_kernel<<<(ROWS*HEADS*32)/256, T>>>(k, kh);

        flash_attn<<<dim3(SLEN/128, BSZ*HEADS), T, SMEM_FLASH>>>(qh, kh, vt, atth, attl);

        gemm_f16<0,false,false,0><<<dim3(HIDDEN/128, ROWS/128), T, SMEM_GEMM>>>(
            atth, attl, base+OFF_WO, nullptr, proj, nullptr, nullptr, VDIM, VDIM, VDIM, HIDDEN);

        add_ln<<<ROWS, T>>>(xin, proj, g1 + i*HIDDEN, be1 + i*HIDDEN, y, yh, yl);

        gemm_f16<0,true,true,1><<<dim3(FFNDIM/128, ROWS/128), T, SMEM_GEMM>>>(
            yh, yl, base+OFF_W1, b1 + i*FFNDIM, nullptr, f1h, f1l, HIDDEN, HIDDEN, HIDDEN, FFNDIM);
        gemm_f16<0,true,false,0><<<dim3(HIDDEN/128, ROWS/128), T, SMEM_GEMM>>>(
            f1h, f1l, base+OFF_W2, b2 + i*HIDDEN, proj, nullptr, nullptr, FFNDIM, FFNDIM, FFNDIM, HIDDEN);

        add_ln<<<ROWS, T>>>(y, proj, g2 + i*HIDDEN, be2 + i*HIDDEN, xout, xh, xl);
    }
}

// round 13
// speedup vs baseline: 6.4290x; 1.2037x over previous
#include <cuda_runtime.h>
#include <cuda_fp16.h>
#include <math.h>
#include <stdint.h>

#define BSZ     2
#define SLEN    2048
#define HIDDEN  512
#define FFNDIM  2048
#define HEADS   8
#define KD      64
#define VDIM    1024
#define HSZ     128
#define ROWS    (BSZ*SLEN)          // 4096
#define SCALING 0.125f
#define LN_EPS  1e-5f

#define WT_PER_LAYER 3670016
#define OFF_WQ 0
#define OFF_WK 262144
#define OFF_WV 524288
#define OFF_WO 1048576
#define OFF_W1 1572864
#define OFF_W2 2621440

typedef __half f16;

// ---------------- scratch ---------------------------------------------------
__device__ float g_proj[ROWS*HIDDEN];
__device__ float g_y[ROWS*HIDDEN];
__device__ float g_x[ROWS*HIDDEN];

__device__ f16 g_xh[ROWS*HIDDEN],  g_xl[ROWS*HIDDEN];
__device__ f16 g_qh[ROWS*HIDDEN];                            // rotary'd, single
__device__ f16 g_kh[ROWS*HIDDEN];                            // rotary'd, single
__device__ f16 g_vt[ROWS*VDIM];                              // [b][n][s] single
__device__ f16 g_att[ROWS*VDIM];                             // single
__device__ f16 g_yh[ROWS*HIDDEN];                            // single
__device__ f16 g_f1h[ROWS*FFNDIM];                           // single
__device__ f16 g_wt[2*WT_PER_LAYER];                         // weights single
__device__ float2 g_rope[SLEN*32];                           // (cos,sin)*scale

// ---------------- helpers ---------------------------------------------------
__device__ __forceinline__ void split_h(float x, f16 &hi, f16 &lo) {
    hi = __float2half_rn(x);
    lo = __float2half_rn(x - __half2float(hi));
}

__device__ __forceinline__ unsigned h2pack(float lo, float hi) {
    unsigned r;
    asm("cvt.rn.f16x2.f32 %0, %1, %2;" : "=r"(r) : "f"(hi), "f"(lo));
    return r;
}

__device__ __forceinline__ void mma16816(float* c,
                                         unsigned a0, unsigned a1, unsigned a2, unsigned a3,
                                         unsigned b0, unsigned b1) {
    asm volatile(
        "mma.sync.aligned.m16n8k16.row.col.f32.f16.f16.f32 "
        "{%0,%1,%2,%3}, {%4,%5,%6,%7}, {%8,%9}, {%0,%1,%2,%3};\n"
        : "+f"(c[0]), "+f"(c[1]), "+f"(c[2]), "+f"(c[3])
        : "r"(a0), "r"(a1), "r"(a2), "r"(a3), "r"(b0), "r"(b1));
}

__device__ __forceinline__ void ldsm4(unsigned* r, unsigned a) {
    asm volatile("ldmatrix.sync.aligned.m8n8.x4.shared.b16 {%0,%1,%2,%3}, [%4];\n"
                 : "=r"(r[0]), "=r"(r[1]), "=r"(r[2]), "=r"(r[3]) : "r"(a));
}

__device__ __forceinline__ void cp16(unsigned dst, const void* src) {
    asm volatile("cp.async.cg.shared.global [%0], [%1], 16;\n" :: "r"(dst), "l"(src));
}

// ---------------- NT GEMM: C[M,N] = A[M,K] @ B[N,K]^T ----------------------
// SPLIT_A: A fp16 hi/lo 2-pass (128B rows). else single (64B rows). B single.
// BM=BN=128, BK=32, 256 thr, warp 64x32.
// OUT 0: fp32. 1: single f16. 2: single f16 transposed vT[b][n][s].
//     3: rotary (rope table) single f16.
template<bool SPLIT_A, bool BIAS, bool RELU, int OUT>
__global__ __launch_bounds__(256)
void gemm_f16(const f16* __restrict__ Ah, const f16* __restrict__ Al,
              const f16* __restrict__ B,
              const float* __restrict__ bias, const float2* __restrict__ rope,
              float* __restrict__ Cf, f16* __restrict__ Ch,
              int K, int lda, int ldb, int ldc) {
    extern __shared__ char dsm[];
    unsigned s0 = (unsigned)__cvta_generic_to_shared(dsm);
    s0 = (s0 + 1023) & ~1023u;

    constexpr int ABYTES = SPLIT_A ? 16384 : 8192;
    constexpr int STAGE  = ABYTES + 8192;

    const int bm = blockIdx.y * 128, bn = blockIdx.x * 128;
    const int tid = threadIdx.x, lane = tid & 31, warp = tid >> 5;
    const int wm = (warp >> 2) * 64, wn = (warp & 3) * 32;
    const int g = lane >> 2, tig = lane & 3;

    float acc[4][4][4] = {};

    auto issue = [&](int kt, unsigned SA) {
        const unsigned SB = SA + ABYTES;
        constexpr int NCH = SPLIT_A ? 6 : 4;
#pragma unroll
        for (int i = 0; i < NCH; i++) {
            const int lin = i * 256 + tid;
            if (SPLIT_A) {
                if (lin < 1024) {
                    const int row = lin >> 3, c = lin & 7;
                    const unsigned d = SA + row * 128 + ((c ^ (row & 7)) << 4);
                    const f16* src = (c < 4) ? Ah + (size_t)(bm + row) * lda + kt + (c & 3) * 8
                                             : Al + (size_t)(bm + row) * lda + kt + (c & 3) * 8;
                    cp16(d, src);
                } else {
                    const int idx = lin - 1024;
                    const int row = idx >> 2, c = idx & 3;
                    cp16(SB + row * 64 + ((c ^ ((row >> 1) & 3)) << 4),
                         B + (size_t)(bn + row) * ldb + kt + c * 8);
                }
            } else {
                if (lin < 512) {
                    const int row = lin >> 2, c = lin & 3;
                    cp16(SA + row * 64 + ((c ^ ((row >> 1) & 3)) << 4),
                         Ah + (size_t)(bm + row) * lda + kt + c * 8);
                } else {
                    const int idx = lin - 512;
                    const int row = idx >> 2, c = idx & 3;
                    cp16(SB + row * 64 + ((c ^ ((row >> 1) & 3)) << 4),
                         B + (size_t)(bn + row) * ldb + kt + c * 8);
                }
            }
        }
        asm volatile("cp.async.commit_group;\n");
    };

    const int nk = K >> 5;
    issue(0, s0);

    for (int t = 0; t < nk; t++) {
        const unsigned SA = s0 + (t & 1) * STAGE;
        const unsigned SB = SA + ABYTES;
        if (t + 1 < nk) {
            issue((t + 1) * 32, s0 + ((t + 1) & 1) * STAGE);
            asm volatile("cp.async.wait_group 1;\n");
        } else {
            asm volatile("cp.async.wait_group 0;\n");
        }
        __syncthreads();

#pragma unroll
        for (int ks = 0; ks < 2; ks++) {
            unsigned ah[4][4], al[4][4], bh[4][2];
#pragma unroll
            for (int mt = 0; mt < 4; mt++) {
                const int r  = wm + mt * 16 + (lane & 15);
                const int lc = 2 * ks + (lane >> 4);
                if (SPLIT_A) {
                    ldsm4(ah[mt], SA + r * 128 + (( lc      ^ (r & 7)) << 4));
                    ldsm4(al[mt], SA + r * 128 + (((lc + 4) ^ (r & 7)) << 4));
                } else {
                    ldsm4(ah[mt], SA + r * 64 + ((lc ^ ((r >> 1) & 3)) << 4));
                }
            }
#pragma unroll
            for (int p = 0; p < 2; p++) {
                const int r  = wn + p * 16 + (lane & 7) + ((lane >> 4) << 3);
                const int lc = 2 * ks + ((lane >> 3) & 1);
                unsigned th[4];
                ldsm4(th, SB + r * 64 + ((lc ^ ((r >> 1) & 3)) << 4));
                bh[2*p][0]   = th[0]; bh[2*p][1]   = th[1];
                bh[2*p+1][0] = th[2]; bh[2*p+1][1] = th[3];
            }
#pragma unroll
            for (int mt = 0; mt < 4; mt++)
#pragma unroll
                for (int nt = 0; nt < 4; nt++) {
                    float* c = acc[mt][nt];
                    mma16816(c, ah[mt][0], ah[mt][1], ah[mt][2], ah[mt][3], bh[nt][0], bh[nt][1]);
                    if (SPLIT_A)
                        mma16816(c, al[mt][0], al[mt][1], al[mt][2], al[mt][3], bh[nt][0], bh[nt][1]);
                }
        }
        __syncthreads();
    }

    // ---------------- epilogue ----------------
#pragma unroll
    for (int mt = 0; mt < 4; mt++) {
#pragma unroll
        for (int nt = 0; nt < 4; nt++) {
            const int row = bm + wm + mt * 16 + g;
            const int col = bn + wn + nt * 8 + tig * 2;
            float c0 = acc[mt][nt][0], c1 = acc[mt][nt][1];
            float c2 = acc[mt][nt][2], c3 = acc[mt][nt][3];
            if (BIAS) {
                const float b0 = bias[col], b1 = bias[col + 1];
                c0 += b0; c1 += b1; c2 += b0; c3 += b1;
            }
            if (RELU) {
                c0 = fmaxf(c0, 0.f); c1 = fmaxf(c1, 0.f);
                c2 = fmaxf(c2, 0.f); c3 = fmaxf(c3, 0.f);
            }
            if (OUT == 0) {
                *(float2*)&Cf[(size_t)row * ldc + col]       = make_float2(c0, c1);
                *(float2*)&Cf[(size_t)(row + 8) * ldc + col] = make_float2(c2, c3);
            } else if (OUT == 1) {
                *(__half2*)&Ch[(size_t)row * ldc + col] =
                    __halves2half2(__float2half_rn(c0), __float2half_rn(c1));
                *(__half2*)&Ch[(size_t)(row + 8) * ldc + col] =
                    __halves2half2(__float2half_rn(c2), __float2half_rn(c3));
            } else if (OUT == 2) {
                const size_t base = (size_t)(row >> 11) * VDIM * SLEN;
                const int s1 = row & 2047, s2 = (row + 8) & 2047;
                Ch[base + (size_t)col       * SLEN + s1] = __float2half_rn(c0);
                Ch[base + (size_t)(col + 1) * SLEN + s1] = __float2half_rn(c1);
                Ch[base + (size_t)col       * SLEN + s2] = __float2half_rn(c2);
                Ch[base + (size_t)(col + 1) * SLEN + s2] = __float2half_rn(c3);
            } else {
                const int d2 = (col & 63) >> 1;
                const float2 r0 = rope[(size_t)(row & 2047) * 32 + d2];
                const float2 r1 = rope[(size_t)((row + 8) & 2047) * 32 + d2];
                *(__half2*)&Ch[(size_t)row * ldc + col] =
                    __halves2half2(__float2half_rn(c0 * r0.x - c1 * r0.y),
                                   __float2half_rn(c1 * r0.x + c0 * r0.y));
                *(__half2*)&Ch[(size_t)(row + 8) * ldc + col] =
                    __halves2half2(__float2half_rn(c2 * r1.x - c3 * r1.y),
                                   __float2half_rn(c3 * r1.x + c2 * r1.y));
            }
        }
    }
}

// ---------------- flash attention (unchanged core; single f16 out) ----------
__global__ __launch_bounds__(256, 1)
void flash_attn(const f16* __restrict__ Q, const f16* __restrict__ Kp,
                const f16* __restrict__ V, f16* __restrict__ Oh) {
    extern __shared__ char dsm[];
    unsigned s0 = (unsigned)__cvta_generic_to_shared(dsm);
    s0 = (s0 + 1023) & ~1023u;
    const int qt = blockIdx.x, z = blockIdx.y;
    const int b = z >> 3, h = z & 7;
    const int tid = threadIdx.x, lane = tid & 31, warp = tid >> 5;

    const f16* Qb = Q + ((size_t)(b * SLEN + qt * 128)) * HIDDEN + h * KD;
    const f16* Kb = Kp + (size_t)b * SLEN * HIDDEN + h * KD;
    const f16* Vb = V + ((size_t)b * VDIM + h * HSZ) * SLEN;

    const unsigned SQ = s0;

#pragma unroll
    for (int i = 0; i < 4; i++) {
        const int lin = i * 256 + tid;
        const int row = lin >> 3, c = lin & 7;
        cp16(SQ + row * 128 + ((c ^ (row & 7)) << 4), Qb + (size_t)row * HIDDEN + c * 8);
    }
    auto issue_kv = [&](int kt, int st) {
        const unsigned SK = s0 + 16384 + st * 49152;
        const unsigned SV = SK + 16384;
#pragma unroll
        for (int i = 0; i < 12; i++) {
            const int lin = i * 256 + tid;
            if (lin < 1024) {
                const int row = lin >> 3, c = lin & 7;
                cp16(SK + row * 128 + ((c ^ (row & 7)) << 4),
                     Kb + (size_t)(kt * 128 + row) * HIDDEN + c * 8);
            } else {
                const int idx = lin - 1024;
                const int n = idx >> 4, c = idx & 15;
                cp16(SV + n * 256 + ((c ^ (n & 7)) << 4),
                     Vb + (size_t)n * SLEN + kt * 128 + c * 8);
            }
        }
        asm volatile("cp.async.commit_group;\n");
    };
    issue_kv(0, 0);

    float O[16][4] = {};
    float m0 = -INFINITY, m1 = -INFINITY, l0 = 0.f, l1 = 0.f;

    const int rA = warp * 16 + (lane & 15);
    const int rB = (lane & 7) + ((lane >> 4) << 3);
    const int cBsel = (lane >> 3) & 1;

    for (int t = 0; t < 16; t++) {
        const int st = t & 1;
        const unsigned SK = s0 + 16384 + st * 49152;
        const unsigned SV = SK + 16384;
        if (t < 15) {
            issue_kv(t + 1, st ^ 1);
            asm volatile("cp.async.wait_group 1;\n");
        } else {
            asm volatile("cp.async.wait_group 0;\n");
        }
        __syncthreads();

        float S[16][4] = {};
#pragma unroll
        for (int ks = 0; ks < 4; ks++) {
            unsigned aq[4];
            const int lcA = ks * 2 + (lane >> 4);
            ldsm4(aq, SQ + rA * 128 + ((lcA ^ (rA & 7)) << 4));
            const int lcB = ks * 2 + cBsel;
#pragma unroll
            for (int p = 0; p < 8; p++) {
                const int r2 = p * 16 + rB;
                unsigned tb[4];
                ldsm4(tb, SK + r2 * 128 + ((lcB ^ (r2 & 7)) << 4));
                mma16816(S[2*p],   aq[0], aq[1], aq[2], aq[3], tb[0], tb[1]);
                mma16816(S[2*p+1], aq[0], aq[1], aq[2], aq[3], tb[2], tb[3]);
            }
        }

        float mx0 = -INFINITY, mx1 = -INFINITY;
#pragma unroll
        for (int nt = 0; nt < 16; nt++) {
            mx0 = fmaxf(mx0, fmaxf(S[nt][0], S[nt][1]));
            mx1 = fmaxf(mx1, fmaxf(S[nt][2], S[nt][3]));
        }
        mx0 = fmaxf(mx0, __shfl_xor_sync(0xffffffffu, mx0, 1));
        mx0 = fmaxf(mx0, __shfl_xor_sync(0xffffffffu, mx0, 2));
        mx1 = fmaxf(mx1, __shfl_xor_sync(0xffffffffu, mx1, 1));
        mx1 = fmaxf(mx1, __shfl_xor_sync(0xffffffffu, mx1, 2));
        const float nm0 = fmaxf(m0, mx0), nm1 = fmaxf(m1, mx1);
        const float sc0 = __expf(m0 - nm0), sc1 = __expf(m1 - nm1);
        m0 = nm0; m1 = nm1;
        float rs0 = 0.f, rs1 = 0.f;
#pragma unroll
        for (int nt = 0; nt < 16; nt++) {
            S[nt][0] = __expf(S[nt][0] - nm0);
            S[nt][1] = __expf(S[nt][1] - nm0);
            S[nt][2] = __expf(S[nt][2] - nm1);
            S[nt][3] = __expf(S[nt][3] - nm1);
            rs0 += S[nt][0] + S[nt][1];
            rs1 += S[nt][2] + S[nt][3];
            O[nt][0] *= sc0; O[nt][1] *= sc0;
            O[nt][2] *= sc1; O[nt][3] *= sc1;
        }
        rs0 += __shfl_xor_sync(0xffffffffu, rs0, 1);
        rs0 += __shfl_xor_sync(0xffffffffu, rs0, 2);
        rs1 += __shfl_xor_sync(0xffffffffu, rs1, 1);
        rs1 += __shfl_xor_sync(0xffffffffu, rs1, 2);
        l0 = l0 * sc0 + rs0;
        l1 = l1 * sc1 + rs1;

#pragma unroll
        for (int j = 0; j < 8; j++) {
            const unsigned a0 = h2pack(S[2*j][0],   S[2*j][1]);
            const unsigned a1 = h2pack(S[2*j][2],   S[2*j][3]);
            const unsigned a2 = h2pack(S[2*j+1][0], S[2*j+1][1]);
            const unsigned a3 = h2pack(S[2*j+1][2], S[2*j+1][3]);
            const int lcV = j * 2 + cBsel;
#pragma unroll
            for (int p = 0; p < 8; p++) {
                const int r2 = p * 16 + rB;
                unsigned tb[4];
                ldsm4(tb, SV + r2 * 256 + ((lcV ^ (r2 & 7)) << 4));
                mma16816(O[2*p],   a0, a1, a2, a3, tb[0], tb[1]);
                mma16816(O[2*p+1], a0, a1, a2, a3, tb[2], tb[3]);
            }
        }
        __syncthreads();
    }

    const float inv0 = SCALING / l0, inv1 = SCALING / l1;
    const int g = lane >> 2, tg = lane & 3;
    const int srow = qt * 128 + warp * 16 + g;
    const size_t base0 = ((size_t)(b * SLEN) + srow) * VDIM + h * HSZ;
    const size_t base1 = base0 + (size_t)8 * VDIM;
#pragma unroll
    for (int nt = 0; nt < 16; nt++) {
        const int col = nt * 8 + tg * 2;
        *(__half2*)&Oh[base0 + col] =
            __halves2half2(__float2half_rn(O[nt][0] * inv0), __float2half_rn(O[nt][1] * inv0));
        *(__half2*)&Oh[base1 + col] =
            __halves2half2(__float2half_rn(O[nt][2] * inv1), __float2half_rn(O[nt][3] * inv1));
    }
}

// ---------------- batched weight transpose + fp16 ---------------------------
struct TSegs {
    const float* src[12];
    int dstoff[12];
    int K[12], N[12], tile0[12];
};

__global__ __launch_bounds__(256)
void transpose_cvt_all(TSegs segs, f16* __restrict__ dstbase) {
    __shared__ float t[32][33];
    const int tb = blockIdx.x;
    int s = 0;
#pragma unroll
    for (int i = 1; i < 12; i++) if (tb >= segs.tile0[i]) s = i;
    const int local = tb - segs.tile0[s];
    const int tilesX = segs.N[s] >> 5;
    const int nb = (local % tilesX) << 5;
    const int kb = (local / tilesX) << 5;
    const float* src = segs.src[s];
    f16* dst = dstbase + segs.dstoff[s];
    const int K = segs.K[s], N = segs.N[s];
    const int tx = threadIdx.x & 31, ty = threadIdx.x >> 5;
#pragma unroll
    for (int i = ty; i < 32; i += 8)
        t[i][tx] = src[(size_t)(kb + i) * N + nb + tx];
    __syncthreads();
#pragma unroll
    for (int i = ty; i < 32; i += 8)
        dst[(size_t)(nb + i) * K + kb + tx] = __float2half_rn(t[tx][i]);
}

// ---------------- rope table -------------------------------------------------
__global__ __launch_bounds__(256)
void build_rope(float2* __restrict__ rope) {
    const int idx = blockIdx.x * 256 + threadIdx.x;   // s*32 + d2
    const int d2 = idx & 31, s = idx >> 5;
    const float base  = (2.f * d2 + 25.6f) / 89.6f;
    const float scale = powf(base, (float)(s - 1024) * (1.f / 512.f));
    const float invf  = powf(10000.f, -(float)d2 * (1.f / 32.f));
    float sv, cv;
    sincosf((float)s * invf, &sv, &cv);
    rope[idx] = make_float2(cv * scale, sv * scale);
}

// ---------------- elementwise fp32 -> fp16 hi/lo ----------------------------
__global__ __launch_bounds__(256)
void cvt_split(const float* __restrict__ src, f16* __restrict__ dh,
               f16* __restrict__ dl) {
    const int i = blockIdx.x * 256 + threadIdx.x;
    f16 h, l;
    split_h(src[i], h, l);
    dh[i] = h; dl[i] = l;
}

// ---------------- block reduce / add_ln ------------------------------------
__device__ __forceinline__ float block_reduce(float v, float* sh, int op) {
#pragma unroll
    for (int o = 16; o; o >>= 1) {
        float t = __shfl_xor_sync(0xffffffffu, v, o);
        v = op ? fmaxf(v, t) : v + t;
    }
    if ((threadIdx.x & 31) == 0) sh[threadIdx.x >> 5] = v;
    __syncthreads();
    if (threadIdx.x < 32) {
        const int nw = blockDim.x >> 5;
        float t = (threadIdx.x < nw) ? sh[threadIdx.x] : (op ? -INFINITY : 0.f);
#pragma unroll
        for (int o = 16; o; o >>= 1) {
            float u = __shfl_xor_sync(0xffffffffu, t, o);
            t = op ? fmaxf(t, u) : t + u;
        }
        if (threadIdx.x == 0) sh[0] = t;
    }
    __syncthreads();
    float r = sh[0];
    __syncthreads();
    return r;
}

// LO: also write lo-residual array (for 2-pass consumers)
template<bool LO>
__global__ __launch_bounds__(256)
void add_ln(const float* __restrict__ a, const float* __restrict__ b,
            const float* __restrict__ g, const float* __restrict__ be,
            float* __restrict__ out, f16* __restrict__ oh, f16* __restrict__ ol) {
    __shared__ float sh[32];
    const size_t r = (size_t)blockIdx.x * HIDDEN;
    const int t = threadIdx.x;
    float v0 = a[r + t]       + b[r + t];
    float v1 = a[r + t + 256] + b[r + t + 256];
    float mean = block_reduce(v0 + v1, sh, 0) * (1.f / HIDDEN);
    float d0 = v0 - mean, d1 = v1 - mean;
    float var = block_reduce(d0 * d0 + d1 * d1, sh, 0) * (1.f / HIDDEN);
    float inv = rsqrtf(var + LN_EPS);
    const float o0 = d0 * inv * g[t]       + be[t];
    const float o1 = d1 * inv * g[t + 256] + be[t + 256];
    out[r + t]       = o0;
    out[r + t + 256] = o1;
    if (LO) {
        f16 h, l;
        split_h(o0, h, l); oh[r + t] = h;       ol[r + t] = l;
        split_h(o1, h, l); oh[r + t + 256] = h; ol[r + t + 256] = l;
    } else {
        oh[r + t]       = __float2half_rn(o0);
        oh[r + t + 256] = __float2half_rn(o1);
    }
}

// ---------------- driver ----------------------------------------------------
#define SMEM_GEMM_S (2*24576 + 1024)
#define SMEM_GEMM_N (2*16384 + 1024)
#define SMEM_FLASH  (16384 + 2*49152 + 1024)

extern "C" void kernel_launch(void* const* d_in, const int* in_sizes, int n_in,
                              void* d_out, int out_size) {
    const float* x   = (const float*)d_in[0];
    const float* Wq  = (const float*)d_in[1];
    const float* Wk  = (const float*)d_in[2];
    const float* Wv  = (const float*)d_in[3];
    const float* Wo  = (const float*)d_in[4];
    const float* W1  = (const float*)d_in[5];
    const float* b1  = (const float*)d_in[6];
    const float* W2  = (const float*)d_in[7];
    const float* b2  = (const float*)d_in[8];
    const float* g1  = (const float*)d_in[9];
    const float* be1 = (const float*)d_in[10];
    const float* g2  = (const float*)d_in[11];
    const float* be2 = (const float*)d_in[12];

    float *proj, *y, *xb;
    f16 *xh, *xl, *qh, *kh, *vt, *att, *yh, *f1h, *wt;
    float2* rope;
    cudaGetSymbolAddress((void**)&proj, g_proj);
    cudaGetSymbolAddress((void**)&y,    g_y);
    cudaGetSymbolAddress((void**)&xb,   g_x);
    cudaGetSymbolAddress((void**)&xh,   g_xh);   cudaGetSymbolAddress((void**)&xl,   g_xl);
    cudaGetSymbolAddress((void**)&qh,   g_qh);
    cudaGetSymbolAddress((void**)&kh,   g_kh);
    cudaGetSymbolAddress((void**)&vt,   g_vt);
    cudaGetSymbolAddress((void**)&att,  g_att);
    cudaGetSymbolAddress((void**)&yh,   g_yh);
    cudaGetSymbolAddress((void**)&f1h,  g_f1h);
    cudaGetSymbolAddress((void**)&wt,   g_wt);
    cudaGetSymbolAddress((void**)&rope, g_rope);

    static bool attr_done = false;
    if (!attr_done) {
        cudaFuncSetAttribute((const void*)gemm_f16<true,false,false,3>,  cudaFuncAttributeMaxDynamicSharedMemorySize, SMEM_GEMM_S);
        cudaFuncSetAttribute((const void*)gemm_f16<true,false,false,2>,  cudaFuncAttributeMaxDynamicSharedMemorySize, SMEM_GEMM_S);
        cudaFuncSetAttribute((const void*)gemm_f16<false,false,false,0>, cudaFuncAttributeMaxDynamicSharedMemorySize, SMEM_GEMM_N);
        cudaFuncSetAttribute((const void*)gemm_f16<false,true,true,1>,   cudaFuncAttributeMaxDynamicSharedMemorySize, SMEM_GEMM_N);
        cudaFuncSetAttribute((const void*)gemm_f16<false,true,false,0>,  cudaFuncAttributeMaxDynamicSharedMemorySize, SMEM_GEMM_N);
        cudaFuncSetAttribute((const void*)flash_attn,                    cudaFuncAttributeMaxDynamicSharedMemorySize, SMEM_FLASH);
        attr_done = true;
    }

    const dim3 T(256);

    // ---- one batched transpose launch for all 12 weight matrices ----
    {
        TSegs segs;
        int tile = 0;
        int si = 0;
        for (int l = 0; l < 2; l++) {
            const float* srcs[6] = {Wq + (size_t)l*HIDDEN*HIDDEN, Wk + (size_t)l*HIDDEN*HIDDEN,
                                    Wv + (size_t)l*HIDDEN*VDIM,   Wo + (size_t)l*VDIM*HIDDEN,
                                    W1 + (size_t)l*HIDDEN*FFNDIM, W2 + (size_t)l*FFNDIM*HIDDEN};
            const int offs[6] = {OFF_WQ, OFF_WK, OFF_WV, OFF_WO, OFF_W1, OFF_W2};
            const int Ks[6]   = {HIDDEN, HIDDEN, HIDDEN, VDIM, HIDDEN, FFNDIM};
            const int Ns[6]   = {HIDDEN, HIDDEN, VDIM, HIDDEN, FFNDIM, HIDDEN};
            for (int j = 0; j < 6; j++, si++) {
                segs.src[si] = srcs[j];
                segs.dstoff[si] = l * WT_PER_LAYER + offs[j];
                segs.K[si] = Ks[j]; segs.N[si] = Ns[j];
                segs.tile0[si] = tile;
                tile += (Ks[j] >> 5) * (Ns[j] >> 5);
            }
        }
        transpose_cvt_all<<<tile, T>>>(segs, wt);
    }

    build_rope<<<(SLEN*32)/256, T>>>(rope);
    cvt_split<<<(ROWS*HIDDEN)/256, T>>>(x, xh, xl);

    for (int i = 0; i < 2; i++) {
        const float* xin  = i ? xb : x;
        float*       xout = i ? (float*)d_out : xb;
        f16* base = wt + (size_t)i * WT_PER_LAYER;

        // Q, K with fused rotary (single f16 out); V transposed single
        gemm_f16<true,false,false,3><<<dim3(HIDDEN/128, ROWS/128), T, SMEM_GEMM_S>>>(
            xh, xl, base+OFF_WQ, nullptr, rope, nullptr, qh, HIDDEN, HIDDEN, HIDDEN, HIDDEN);
        gemm_f16<true,false,false,3><<<dim3(HIDDEN/128, ROWS/128), T, SMEM_GEMM_S>>>(
            xh, xl, base+OFF_WK, nullptr, rope, nullptr, kh, HIDDEN, HIDDEN, HIDDEN, HIDDEN);
        gemm_f16<true,false,false,2><<<dim3(VDIM/128, ROWS/128), T, SMEM_GEMM_S>>>(
            xh, xl, base+OFF_WV, nullptr, nullptr, nullptr, vt, HIDDEN, HIDDEN, HIDDEN, 0);

        flash_attn<<<dim3(SLEN/128, BSZ*HEADS), T, SMEM_FLASH>>>(qh, kh, vt, att);

        // output projection (A single)
        gemm_f16<false,false,false,0><<<dim3(HIDDEN/128, ROWS/128), T, SMEM_GEMM_N>>>(
            att, nullptr, base+OFF_WO, nullptr, nullptr, proj, nullptr, VDIM, VDIM, VDIM, HIDDEN);

        add_ln<false><<<ROWS, T>>>(xin, proj, g1 + i*HIDDEN, be1 + i*HIDDEN, y, yh, nullptr);

        // FFN (A single both)
        gemm_f16<false,true,true,1><<<dim3(FFNDIM/128, ROWS/128), T, SMEM_GEMM_N>>>(
            yh, nullptr, base+OFF_W1, b1 + i*FFNDIM, nullptr, nullptr, f1h, HIDDEN, HIDDEN, HIDDEN, FFNDIM);
        gemm_f16<false,true,false,0><<<dim3(HIDDEN/128, ROWS/128), T, SMEM_GEMM_N>>>(
            f1h, nullptr, base+OFF_W2, b2 + i*HIDDEN, nullptr, proj, nullptr, FFNDIM, FFNDIM, FFNDIM, HIDDEN);

        add_ln<true><<<ROWS, T>>>(y, proj, g2 + i*HIDDEN, be2 + i*HIDDEN, xout, xh, xl);
    }
}

// round 14
// speedup vs baseline: 7.4180x; 1.1538x over previous
#include <cuda_runtime.h>
#include <cuda_fp16.h>
#include <math.h>
#include <stdint.h>

#define BSZ     2
#define SLEN    2048
#define HIDDEN  512
#define FFNDIM  2048
#define HEADS   8
#define KD      64
#define VDIM    1024
#define HSZ     128
#define ROWS    (BSZ*SLEN)          // 4096
#define SCALING 0.125f
#define LN_EPS  1e-5f

#define WT_PER_LAYER 3670016
#define OFF_WQ 0
#define OFF_WK 262144
#define OFF_WV 524288
#define OFF_WO 1048576
#define OFF_W1 1572864
#define OFF_W2 2621440

typedef __half f16;

// ---------------- scratch ---------------------------------------------------
__device__ float g_proj[ROWS*HIDDEN];
__device__ float g_y[ROWS*HIDDEN];
__device__ float g_x[ROWS*HIDDEN];

__device__ f16 g_xh[ROWS*HIDDEN],  g_xl[ROWS*HIDDEN];
__device__ f16 g_qh[ROWS*HIDDEN];                            // rotary'd, single
__device__ f16 g_kh[ROWS*HIDDEN];                            // rotary'd, single
__device__ f16 g_vt[ROWS*VDIM];                              // [b][n][s] single
__device__ f16 g_att[ROWS*VDIM];                             // single
__device__ f16 g_yh[ROWS*HIDDEN];                            // single
__device__ f16 g_f1h[ROWS*FFNDIM];                           // single
__device__ f16 g_wt[2*WT_PER_LAYER];                         // weights single
__device__ float2 g_rope[SLEN*32];                           // (cos,sin)*scale

// ---------------- helpers ---------------------------------------------------
__device__ __forceinline__ void split_h(float x, f16 &hi, f16 &lo) {
    hi = __float2half_rn(x);
    lo = __float2half_rn(x - __half2float(hi));
}

__device__ __forceinline__ unsigned h2pack(float lo, float hi) {
    unsigned r;
    asm("cvt.rn.f16x2.f32 %0, %1, %2;" : "=r"(r) : "f"(hi), "f"(lo));
    return r;
}

__device__ __forceinline__ void mma16816(float* c,
                                         unsigned a0, unsigned a1, unsigned a2, unsigned a3,
                                         unsigned b0, unsigned b1) {
    asm volatile(
        "mma.sync.aligned.m16n8k16.row.col.f32.f16.f16.f32 "
        "{%0,%1,%2,%3}, {%4,%5,%6,%7}, {%8,%9}, {%0,%1,%2,%3};\n"
        : "+f"(c[0]), "+f"(c[1]), "+f"(c[2]), "+f"(c[3])
        : "r"(a0), "r"(a1), "r"(a2), "r"(a3), "r"(b0), "r"(b1));
}

__device__ __forceinline__ void ldsm4(unsigned* r, unsigned a) {
    asm volatile("ldmatrix.sync.aligned.m8n8.x4.shared.b16 {%0,%1,%2,%3}, [%4];\n"
                 : "=r"(r[0]), "=r"(r[1]), "=r"(r[2]), "=r"(r[3]) : "r"(a));
}

__device__ __forceinline__ void cp16(unsigned dst, const void* src) {
    asm volatile("cp.async.cg.shared.global [%0], [%1], 16;\n" :: "r"(dst), "l"(src));
}

// ---------------- NT GEMM: C[M,N] = A[M,K] @ B[N,K]^T ----------------------
// BM = MT*32 (MT=4 -> 128, MT=2 -> 64), BN=128, BK=32, 256 threads.
// Warps: 2 m-groups x 4 n-groups; warp tile (MT*16) x 32.
// SPLIT_A: A fp16 hi/lo 2-pass (128B rows). else single (64B rows). B single.
// OUT 0: fp32. 1: single f16. 4: fused QKV (rope q/k, transpose v).
template<int MT, bool SPLIT_A, bool BIAS, bool RELU, int OUT>
__global__ __launch_bounds__(256)
void gemm_f16(const f16* __restrict__ Ah, const f16* __restrict__ Al,
              const f16* __restrict__ B,
              const float* __restrict__ bias, const float2* __restrict__ rope,
              float* __restrict__ Cf, f16* __restrict__ Ch,
              f16* __restrict__ Chk, f16* __restrict__ Chv,
              int K, int lda, int ldb, int ldc) {
    extern __shared__ char dsm[];
    unsigned s0 = (unsigned)__cvta_generic_to_shared(dsm);
    s0 = (s0 + 1023) & ~1023u;

    constexpr int BM     = MT * 32;
    constexpr int ABYTES = BM * (SPLIT_A ? 128 : 64);
    constexpr int STAGE  = ABYTES + 8192;
    constexpr int ACH    = BM * (SPLIT_A ? 8 : 4);
    constexpr int NCH    = (ACH + 512) / 256;

    const int bm = blockIdx.y * BM, bn = blockIdx.x * 128;
    const int tid = threadIdx.x, lane = tid & 31, warp = tid >> 5;
    const int wm = (warp >> 2) * (MT * 16), wn = (warp & 3) * 32;
    const int g = lane >> 2, tig = lane & 3;

    float acc[MT][4][4] = {};

    auto issue = [&](int kt, unsigned SA) {
        const unsigned SB = SA + ABYTES;
#pragma unroll
        for (int i = 0; i < NCH; i++) {
            const int lin = i * 256 + tid;
            if (lin < ACH) {
                if (SPLIT_A) {
                    const int row = lin >> 3, c = lin & 7;
                    const f16* src = (c < 4) ? Ah + (size_t)(bm + row) * lda + kt + (c & 3) * 8
                                             : Al + (size_t)(bm + row) * lda + kt + (c & 3) * 8;
                    cp16(SA + row * 128 + ((c ^ (row & 7)) << 4), src);
                } else {
                    const int row = lin >> 2, c = lin & 3;
                    cp16(SA + row * 64 + ((c ^ ((row >> 1) & 3)) << 4),
                         Ah + (size_t)(bm + row) * lda + kt + c * 8);
                }
            } else {
                const int idx = lin - ACH;
                const int row = idx >> 2, c = idx & 3;
                cp16(SB + row * 64 + ((c ^ ((row >> 1) & 3)) << 4),
                     B + (size_t)(bn + row) * ldb + kt + c * 8);
            }
        }
        asm volatile("cp.async.commit_group;\n");
    };

    const int nk = K >> 5;
    issue(0, s0);

    for (int t = 0; t < nk; t++) {
        const unsigned SA = s0 + (t & 1) * STAGE;
        const unsigned SB = SA + ABYTES;
        if (t + 1 < nk) {
            issue((t + 1) * 32, s0 + ((t + 1) & 1) * STAGE);
            asm volatile("cp.async.wait_group 1;\n");
        } else {
            asm volatile("cp.async.wait_group 0;\n");
        }
        __syncthreads();

#pragma unroll
        for (int ks = 0; ks < 2; ks++) {
            unsigned ah[MT][4], al[MT][4], bh[4][2];
#pragma unroll
            for (int mt = 0; mt < MT; mt++) {
                const int r  = wm + mt * 16 + (lane & 15);
                const int lc = 2 * ks + (lane >> 4);
                if (SPLIT_A) {
                    ldsm4(ah[mt], SA + r * 128 + (( lc      ^ (r & 7)) << 4));
                    ldsm4(al[mt], SA + r * 128 + (((lc + 4) ^ (r & 7)) << 4));
                } else {
                    ldsm4(ah[mt], SA + r * 64 + ((lc ^ ((r >> 1) & 3)) << 4));
                }
            }
#pragma unroll
            for (int p = 0; p < 2; p++) {
                const int r  = wn + p * 16 + (lane & 7) + ((lane >> 4) << 3);
                const int lc = 2 * ks + ((lane >> 3) & 1);
                unsigned th[4];
                ldsm4(th, SB + r * 64 + ((lc ^ ((r >> 1) & 3)) << 4));
                bh[2*p][0]   = th[0]; bh[2*p][1]   = th[1];
                bh[2*p+1][0] = th[2]; bh[2*p+1][1] = th[3];
            }
#pragma unroll
            for (int mt = 0; mt < MT; mt++)
#pragma unroll
                for (int nt = 0; nt < 4; nt++) {
                    float* c = acc[mt][nt];
                    mma16816(c, ah[mt][0], ah[mt][1], ah[mt][2], ah[mt][3], bh[nt][0], bh[nt][1]);
                    if (SPLIT_A)
                        mma16816(c, al[mt][0], al[mt][1], al[mt][2], al[mt][3], bh[nt][0], bh[nt][1]);
                }
        }
        __syncthreads();
    }

    // ---------------- epilogue ----------------
#pragma unroll
    for (int mt = 0; mt < MT; mt++) {
#pragma unroll
        for (int nt = 0; nt < 4; nt++) {
            const int row = bm + wm + mt * 16 + g;
            const int col = bn + wn + nt * 8 + tig * 2;
            float c0 = acc[mt][nt][0], c1 = acc[mt][nt][1];
            float c2 = acc[mt][nt][2], c3 = acc[mt][nt][3];
            if (BIAS) {
                const float b0 = bias[col], b1 = bias[col + 1];
                c0 += b0; c1 += b1; c2 += b0; c3 += b1;
            }
            if (RELU) {
                c0 = fmaxf(c0, 0.f); c1 = fmaxf(c1, 0.f);
                c2 = fmaxf(c2, 0.f); c3 = fmaxf(c3, 0.f);
            }
            if (OUT == 0) {
                *(float2*)&Cf[(size_t)row * ldc + col]       = make_float2(c0, c1);
                *(float2*)&Cf[(size_t)(row + 8) * ldc + col] = make_float2(c2, c3);
            } else if (OUT == 1) {
                *(__half2*)&Ch[(size_t)row * ldc + col] =
                    __halves2half2(__float2half_rn(c0), __float2half_rn(c1));
                *(__half2*)&Ch[(size_t)(row + 8) * ldc + col] =
                    __halves2half2(__float2half_rn(c2), __float2half_rn(c3));
            } else {
                // fused QKV: cols [0,512)=Q rope, [512,1024)=K rope, [1024,2048)=V^T
                if (bn < 1024) {
                    const int d2 = (col & 63) >> 1;
                    const float2 r0 = rope[(size_t)(row & 2047) * 32 + d2];
                    const float2 r1 = rope[(size_t)((row + 8) & 2047) * 32 + d2];
                    f16* dst = (bn < 512) ? Ch : Chk;
                    const int cc = col & 511;
                    *(__half2*)&dst[(size_t)row * HIDDEN + cc] =
                        __halves2half2(__float2half_rn(c0 * r0.x - c1 * r0.y),
                                       __float2half_rn(c1 * r0.x + c0 * r0.y));
                    *(__half2*)&dst[(size_t)(row + 8) * HIDDEN + cc] =
                        __halves2half2(__float2half_rn(c2 * r1.x - c3 * r1.y),
                                       __float2half_rn(c3 * r1.x + c2 * r1.y));
                } else {
                    const int n = col - 1024;
                    const size_t basev = (size_t)(row >> 11) * VDIM * SLEN;
                    const int s1 = row & 2047, s2 = (row + 8) & 2047;
                    Chv[basev + (size_t)n       * SLEN + s1] = __float2half_rn(c0);
                    Chv[basev + (size_t)(n + 1) * SLEN + s1] = __float2half_rn(c1);
                    Chv[basev + (size_t)n       * SLEN + s2] = __float2half_rn(c2);
                    Chv[basev + (size_t)(n + 1) * SLEN + s2] = __float2half_rn(c3);
                }
            }
        }
    }
}

// ---------------- flash attention (unchanged from R13) ----------------------
__global__ __launch_bounds__(256, 1)
void flash_attn(const f16* __restrict__ Q, const f16* __restrict__ Kp,
                const f16* __restrict__ V, f16* __restrict__ Oh) {
    extern __shared__ char dsm[];
    unsigned s0 = (unsigned)__cvta_generic_to_shared(dsm);
    s0 = (s0 + 1023) & ~1023u;
    const int qt = blockIdx.x, z = blockIdx.y;
    const int b = z >> 3, h = z & 7;
    const int tid = threadIdx.x, lane = tid & 31, warp = tid >> 5;

    const f16* Qb = Q + ((size_t)(b * SLEN + qt * 128)) * HIDDEN + h * KD;
    const f16* Kb = Kp + (size_t)b * SLEN * HIDDEN + h * KD;
    const f16* Vb = V + ((size_t)b * VDIM + h * HSZ) * SLEN;

    const unsigned SQ = s0;

#pragma unroll
    for (int i = 0; i < 4; i++) {
        const int lin = i * 256 + tid;
        const int row = lin >> 3, c = lin & 7;
        cp16(SQ + row * 128 + ((c ^ (row & 7)) << 4), Qb + (size_t)row * HIDDEN + c * 8);
    }
    auto issue_kv = [&](int kt, int st) {
        const unsigned SK = s0 + 16384 + st * 49152;
        const unsigned SV = SK + 16384;
#pragma unroll
        for (int i = 0; i < 12; i++) {
            const int lin = i * 256 + tid;
            if (lin < 1024) {
                const int row = lin >> 3, c = lin & 7;
                cp16(SK + row * 128 + ((c ^ (row & 7)) << 4),
                     Kb + (size_t)(kt * 128 + row) * HIDDEN + c * 8);
            } else {
                const int idx = lin - 1024;
                const int n = idx >> 4, c = idx & 15;
                cp16(SV + n * 256 + ((c ^ (n & 7)) << 4),
                     Vb + (size_t)n * SLEN + kt * 128 + c * 8);
            }
        }
        asm volatile("cp.async.commit_group;\n");
    };
    issue_kv(0, 0);

    float O[16][4] = {};
    float m0 = -INFINITY, m1 = -INFINITY, l0 = 0.f, l1 = 0.f;

    const int rA = warp * 16 + (lane & 15);
    const int rB = (lane & 7) + ((lane >> 4) << 3);
    const int cBsel = (lane >> 3) & 1;

    for (int t = 0; t < 16; t++) {
        const int st = t & 1;
        const unsigned SK = s0 + 16384 + st * 49152;
        const unsigned SV = SK + 16384;
        if (t < 15) {
            issue_kv(t + 1, st ^ 1);
            asm volatile("cp.async.wait_group 1;\n");
        } else {
            asm volatile("cp.async.wait_group 0;\n");
        }
        __syncthreads();

        float S[16][4] = {};
#pragma unroll
        for (int ks = 0; ks < 4; ks++) {
            unsigned aq[4];
            const int lcA = ks * 2 + (lane >> 4);
            ldsm4(aq, SQ + rA * 128 + ((lcA ^ (rA & 7)) << 4));
            const int lcB = ks * 2 + cBsel;
#pragma unroll
            for (int p = 0; p < 8; p++) {
                const int r2 = p * 16 + rB;
                unsigned tb[4];
                ldsm4(tb, SK + r2 * 128 + ((lcB ^ (r2 & 7)) << 4));
                mma16816(S[2*p],   aq[0], aq[1], aq[2], aq[3], tb[0], tb[1]);
                mma16816(S[2*p+1], aq[0], aq[1], aq[2], aq[3], tb[2], tb[3]);
            }
        }

        float mx0 = -INFINITY, mx1 = -INFINITY;
#pragma unroll
        for (int nt = 0; nt < 16; nt++) {
            mx0 = fmaxf(mx0, fmaxf(S[nt][0], S[nt][1]));
            mx1 = fmaxf(mx1, fmaxf(S[nt][2], S[nt][3]));
        }
        mx0 = fmaxf(mx0, __shfl_xor_sync(0xffffffffu, mx0, 1));
        mx0 = fmaxf(mx0, __shfl_xor_sync(0xffffffffu, mx0, 2));
        mx1 = fmaxf(mx1, __shfl_xor_sync(0xffffffffu, mx1, 1));
        mx1 = fmaxf(mx1, __shfl_xor_sync(0xffffffffu, mx1, 2));
        const float nm0 = fmaxf(m0, mx0), nm1 = fmaxf(m1, mx1);
        const float sc0 = __expf(m0 - nm0), sc1 = __expf(m1 - nm1);
        m0 = nm0; m1 = nm1;
        float rs0 = 0.f, rs1 = 0.f;
#pragma unroll
        for (int nt = 0; nt < 16; nt++) {
            S[nt][0] = __expf(S[nt][0] - nm0);
            S[nt][1] = __expf(S[nt][1] - nm0);
            S[nt][2] = __expf(S[nt][2] - nm1);
            S[nt][3] = __expf(S[nt][3] - nm1);
            rs0 += S[nt][0] + S[nt][1];
            rs1 += S[nt][2] + S[nt][3];
            O[nt][0] *= sc0; O[nt][1] *= sc0;
            O[nt][2] *= sc1; O[nt][3] *= sc1;
        }
        rs0 += __shfl_xor_sync(0xffffffffu, rs0, 1);
        rs0 += __shfl_xor_sync(0xffffffffu, rs0, 2);
        rs1 += __shfl_xor_sync(0xffffffffu, rs1, 1);
        rs1 += __shfl_xor_sync(0xffffffffu, rs1, 2);
        l0 = l0 * sc0 + rs0;
        l1 = l1 * sc1 + rs1;

#pragma unroll
        for (int j = 0; j < 8; j++) {
            const unsigned a0 = h2pack(S[2*j][0],   S[2*j][1]);
            const unsigned a1 = h2pack(S[2*j][2],   S[2*j][3]);
            const unsigned a2 = h2pack(S[2*j+1][0], S[2*j+1][1]);
            const unsigned a3 = h2pack(S[2*j+1][2], S[2*j+1][3]);
            const int lcV = j * 2 + cBsel;
#pragma unroll
            for (int p = 0; p < 8; p++) {
                const int r2 = p * 16 + rB;
                unsigned tb[4];
                ldsm4(tb, SV + r2 * 256 + ((lcV ^ (r2 & 7)) << 4));
                mma16816(O[2*p],   a0, a1, a2, a3, tb[0], tb[1]);
                mma16816(O[2*p+1], a0, a1, a2, a3, tb[2], tb[3]);
            }
        }
        __syncthreads();
    }

    const float inv0 = SCALING / l0, inv1 = SCALING / l1;
    const int g = lane >> 2, tg = lane & 3;
    const int srow = qt * 128 + warp * 16 + g;
    const size_t base0 = ((size_t)(b * SLEN) + srow) * VDIM + h * HSZ;
    const size_t base1 = base0 + (size_t)8 * VDIM;
#pragma unroll
    for (int nt = 0; nt < 16; nt++) {
        const int col = nt * 8 + tg * 2;
        *(__half2*)&Oh[base0 + col] =
            __halves2half2(__float2half_rn(O[nt][0] * inv0), __float2half_rn(O[nt][1] * inv0));
        *(__half2*)&Oh[base1 + col] =
            __halves2half2(__float2half_rn(O[nt][2] * inv1), __float2half_rn(O[nt][3] * inv1));
    }
}

// ---------------- batched weight transpose + fp16 ---------------------------
struct TSegs {
    const float* src[12];
    int dstoff[12];
    int K[12], N[12], tile0[12];
};

__global__ __launch_bounds__(256)
void transpose_cvt_all(TSegs segs, f16* __restrict__ dstbase) {
    __shared__ float t[32][33];
    const int tb = blockIdx.x;
    int s = 0;
#pragma unroll
    for (int i = 1; i < 12; i++) if (tb >= segs.tile0[i]) s = i;
    const int local = tb - segs.tile0[s];
    const int tilesX = segs.N[s] >> 5;
    const int nb = (local % tilesX) << 5;
    const int kb = (local / tilesX) << 5;
    const float* src = segs.src[s];
    f16* dst = dstbase + segs.dstoff[s];
    const int K = segs.K[s], N = segs.N[s];
    const int tx = threadIdx.x & 31, ty = threadIdx.x >> 5;
#pragma unroll
    for (int i = ty; i < 32; i += 8)
        t[i][tx] = src[(size_t)(kb + i) * N + nb + tx];
    __syncthreads();
#pragma unroll
    for (int i = ty; i < 32; i += 8)
        dst[(size_t)(nb + i) * K + kb + tx] = __float2half_rn(t[tx][i]);
}

// ---------------- rope table -------------------------------------------------
__global__ __launch_bounds__(256)
void build_rope(float2* __restrict__ rope) {
    const int idx = blockIdx.x * 256 + threadIdx.x;
    const int d2 = idx & 31, s = idx >> 5;
    const float base  = (2.f * d2 + 25.6f) / 89.6f;
    const float scale = powf(base, (float)(s - 1024) * (1.f / 512.f));
    const float invf  = powf(10000.f, -(float)d2 * (1.f / 32.f));
    float sv, cv;
    sincosf((float)s * invf, &sv, &cv);
    rope[idx] = make_float2(cv * scale, sv * scale);
}

// ---------------- elementwise fp32 -> fp16 hi/lo ----------------------------
__global__ __launch_bounds__(256)
void cvt_split(const float* __restrict__ src, f16* __restrict__ dh,
               f16* __restrict__ dl) {
    const int i = blockIdx.x * 256 + threadIdx.x;
    f16 h, l;
    split_h(src[i], h, l);
    dh[i] = h; dl[i] = l;
}

// ---------------- block reduce / add_ln ------------------------------------
__device__ __forceinline__ float block_reduce(float v, float* sh, int op) {
#pragma unroll
    for (int o = 16; o; o >>= 1) {
        float t = __shfl_xor_sync(0xffffffffu, v, o);
        v = op ? fmaxf(v, t) : v + t;
    }
    if ((threadIdx.x & 31) == 0) sh[threadIdx.x >> 5] = v;
    __syncthreads();
    if (threadIdx.x < 32) {
        const int nw = blockDim.x >> 5;
        float t = (threadIdx.x < nw) ? sh[threadIdx.x] : (op ? -INFINITY : 0.f);
#pragma unroll
        for (int o = 16; o; o >>= 1) {
            float u = __shfl_xor_sync(0xffffffffu, t, o);
            t = op ? fmaxf(t, u) : t + u;
        }
        if (threadIdx.x == 0) sh[0] = t;
    }
    __syncthreads();
    float r = sh[0];
    __syncthreads();
    return r;
}

template<bool LO>
__global__ __launch_bounds__(256)
void add_ln(const float* __restrict__ a, const float* __restrict__ b,
            const float* __restrict__ g, const float* __restrict__ be,
            float* __restrict__ out, f16* __restrict__ oh, f16* __restrict__ ol) {
    __shared__ float sh[32];
    const size_t r = (size_t)blockIdx.x * HIDDEN;
    const int t = threadIdx.x;
    float v0 = a[r + t]       + b[r + t];
    float v1 = a[r + t + 256] + b[r + t + 256];
    float mean = block_reduce(v0 + v1, sh, 0) * (1.f / HIDDEN);
    float d0 = v0 - mean, d1 = v1 - mean;
    float var = block_reduce(d0 * d0 + d1 * d1, sh, 0) * (1.f / HIDDEN);
    float inv = rsqrtf(var + LN_EPS);
    const float o0 = d0 * inv * g[t]       + be[t];
    const float o1 = d1 * inv * g[t + 256] + be[t + 256];
    out[r + t]       = o0;
    out[r + t + 256] = o1;
    if (LO) {
        f16 h, l;
        split_h(o0, h, l); oh[r + t] = h;       ol[r + t] = l;
        split_h(o1, h, l); oh[r + t + 256] = h; ol[r + t + 256] = l;
    } else {
        oh[r + t]       = __float2half_rn(o0);
        oh[r + t + 256] = __float2half_rn(o1);
    }
}

// ---------------- driver ----------------------------------------------------
#define SMEM_QKV   (2*24576 + 1024)   // MT4 split: stage 24K
#define SMEM_FFN1  (2*16384 + 1024)   // MT4 nonsplit: stage 16K
#define SMEM_N512  (2*12288 + 1024)   // MT2 nonsplit: stage 12K
#define SMEM_FLASH (16384 + 2*49152 + 1024)

extern "C" void kernel_launch(void* const* d_in, const int* in_sizes, int n_in,
                              void* d_out, int out_size) {
    const float* x   = (const float*)d_in[0];
    const float* Wq  = (const float*)d_in[1];
    const float* Wk  = (const float*)d_in[2];
    const float* Wv  = (const float*)d_in[3];
    const float* Wo  = (const float*)d_in[4];
    const float* W1  = (const float*)d_in[5];
    const float* b1  = (const float*)d_in[6];
    const float* W2  = (const float*)d_in[7];
    const float* b2  = (const float*)d_in[8];
    const float* g1  = (const float*)d_in[9];
    const float* be1 = (const float*)d_in[10];
    const float* g2  = (const float*)d_in[11];
    const float* be2 = (const float*)d_in[12];

    float *proj, *y, *xb;
    f16 *xh, *xl, *qh, *kh, *vt, *att, *yh, *f1h, *wt;
    float2* rope;
    cudaGetSymbolAddress((void**)&proj, g_proj);
    cudaGetSymbolAddress((void**)&y,    g_y);
    cudaGetSymbolAddress((void**)&xb,   g_x);
    cudaGetSymbolAddress((void**)&xh,   g_xh);   cudaGetSymbolAddress((void**)&xl,   g_xl);
    cudaGetSymbolAddress((void**)&qh,   g_qh);
    cudaGetSymbolAddress((void**)&kh,   g_kh);
    cudaGetSymbolAddress((void**)&vt,   g_vt);
    cudaGetSymbolAddress((void**)&att,  g_att);
    cudaGetSymbolAddress((void**)&yh,   g_yh);
    cudaGetSymbolAddress((void**)&f1h,  g_f1h);
    cudaGetSymbolAddress((void**)&wt,   g_wt);
    cudaGetSymbolAddress((void**)&rope, g_rope);

    static bool attr_done = false;
    if (!attr_done) {
        cudaFuncSetAttribute((const void*)gemm_f16<4,true,false,false,4>,  cudaFuncAttributeMaxDynamicSharedMemorySize, SMEM_QKV);
        cudaFuncSetAttribute((const void*)gemm_f16<2,false,false,false,0>, cudaFuncAttributeMaxDynamicSharedMemorySize, SMEM_N512);
        cudaFuncSetAttribute((const void*)gemm_f16<4,false,true,true,1>,   cudaFuncAttributeMaxDynamicSharedMemorySize, SMEM_FFN1);
        cudaFuncSetAttribute((const void*)gemm_f16<2,false,true,false,0>,  cudaFuncAttributeMaxDynamicSharedMemorySize, SMEM_N512);
        cudaFuncSetAttribute((const void*)flash_attn,                      cudaFuncAttributeMaxDynamicSharedMemorySize, SMEM_FLASH);
        attr_done = true;
    }

    const dim3 T(256);

    // ---- one batched transpose launch for all 12 weight matrices ----
    {
        TSegs segs;
        int tile = 0;
        int si = 0;
        for (int l = 0; l < 2; l++) {
            const float* srcs[6] = {Wq + (size_t)l*HIDDEN*HIDDEN, Wk + (size_t)l*HIDDEN*HIDDEN,
                                    Wv + (size_t)l*HIDDEN*VDIM,   Wo + (size_t)l*VDIM*HIDDEN,
                                    W1 + (size_t)l*HIDDEN*FFNDIM, W2 + (size_t)l*FFNDIM*HIDDEN};
            const int offs[6] = {OFF_WQ, OFF_WK, OFF_WV, OFF_WO, OFF_W1, OFF_W2};
            const int Ks[6]   = {HIDDEN, HIDDEN, HIDDEN, VDIM, HIDDEN, FFNDIM};
            const int Ns[6]   = {HIDDEN, HIDDEN, VDIM, HIDDEN, FFNDIM, HIDDEN};
            for (int j = 0; j < 6; j++, si++) {
                segs.src[si] = srcs[j];
                segs.dstoff[si] = l * WT_PER_LAYER + offs[j];
                segs.K[si] = Ks[j]; segs.N[si] = Ns[j];
                segs.tile0[si] = tile;
                tile += (Ks[j] >> 5) * (Ns[j] >> 5);
            }
        }
        transpose_cvt_all<<<tile, T>>>(segs, wt);
    }

    build_rope<<<(SLEN*32)/256, T>>>(rope);
    cvt_split<<<(ROWS*HIDDEN)/256, T>>>(x, xh, xl);

    for (int i = 0; i < 2; i++) {
        const float* xin  = i ? xb : x;
        float*       xout = i ? (float*)d_out : xb;
        f16* base = wt + (size_t)i * WT_PER_LAYER;

        // fused QKV projection: N=2048 = [Q|K|V], rope + transpose in epilogue
        gemm_f16<4,true,false,false,4><<<dim3(16, ROWS/128), T, SMEM_QKV>>>(
            xh, xl, base+OFF_WQ, nullptr, rope, nullptr, qh, kh, vt,
            HIDDEN, HIDDEN, HIDDEN, 0);

        flash_attn<<<dim3(SLEN/128, BSZ*HEADS), T, SMEM_FLASH>>>(qh, kh, vt, att);

        // output projection (A single, BM=64)
        gemm_f16<2,false,false,false,0><<<dim3(4, ROWS/64), T, SMEM_N512>>>(
            att, nullptr, base+OFF_WO, nullptr, nullptr, proj, nullptr, nullptr, nullptr,
            VDIM, VDIM, VDIM, HIDDEN);

        add_ln<false><<<ROWS, T>>>(xin, proj, g1 + i*HIDDEN, be1 + i*HIDDEN, y, yh, nullptr);

        // FFN
        gemm_f16<4,false,true,true,1><<<dim3(16, ROWS/128), T, SMEM_FFN1>>>(
            yh, nullptr, base+OFF_W1, b1 + i*FFNDIM, nullptr, nullptr, f1h, nullptr, nullptr,
            HIDDEN, HIDDEN, HIDDEN, FFNDIM);
        gemm_f16<2,false,true,false,0><<<dim3(4, ROWS/64), T, SMEM_N512>>>(
            f1h, nullptr, base+OFF_W2, b2 + i*HIDDEN, nullptr, proj, nullptr, nullptr, nullptr,
            FFNDIM, FFNDIM, FFNDIM, HIDDEN);

        add_ln<true><<<ROWS, T>>>(y, proj, g2 + i*HIDDEN, be2 + i*HIDDEN, xout, xh, xl);
    }
}

// round 15
// speedup vs baseline: 7.9213x; 1.0678x over previous
#include <cuda_runtime.h>
#include <cuda_fp16.h>
#include <math.h>
#include <stdint.h>

#define BSZ     2
#define SLEN    2048
#define HIDDEN  512
#define FFNDIM  2048
#define HEADS   8
#define KD      64
#define VDIM    1024
#define HSZ     128
#define ROWS    (BSZ*SLEN)          // 4096
#define SCALING 0.125f
#define LN_EPS  1e-5f

#define WT_PER_LAYER 3670016
#define OFF_WQ 0
#define OFF_WK 262144
#define OFF_WV 524288
#define OFF_WO 1048576
#define OFF_W1 1572864
#define OFF_W2 2621440

typedef __half f16;

// ---------------- scratch ---------------------------------------------------
__device__ float g_proj[ROWS*HIDDEN];
__device__ float g_y[ROWS*HIDDEN];
__device__ float g_x[ROWS*HIDDEN];

__device__ f16 g_xh[ROWS*HIDDEN];                            // single
__device__ f16 g_qh[ROWS*HIDDEN];                            // rotary'd, single
__device__ f16 g_kh[ROWS*HIDDEN];                            // rotary'd, single
__device__ f16 g_vt[ROWS*VDIM];                              // [b][n][s] single
__device__ f16 g_att[ROWS*VDIM];                             // single
__device__ f16 g_yh[ROWS*HIDDEN];                            // single
__device__ f16 g_f1h[ROWS*FFNDIM];                           // single
__device__ f16 g_wt[2*WT_PER_LAYER];                         // weights single
__device__ float2 g_rope[SLEN*32];                           // (cos,sin)*scale

// ---------------- helpers ---------------------------------------------------
__device__ __forceinline__ unsigned h2pack(float lo, float hi) {
    unsigned r;
    asm("cvt.rn.f16x2.f32 %0, %1, %2;" : "=r"(r) : "f"(hi), "f"(lo));
    return r;
}

__device__ __forceinline__ void mma16816(float* c,
                                         unsigned a0, unsigned a1, unsigned a2, unsigned a3,
                                         unsigned b0, unsigned b1) {
    asm volatile(
        "mma.sync.aligned.m16n8k16.row.col.f32.f16.f16.f32 "
        "{%0,%1,%2,%3}, {%4,%5,%6,%7}, {%8,%9}, {%0,%1,%2,%3};\n"
        : "+f"(c[0]), "+f"(c[1]), "+f"(c[2]), "+f"(c[3])
        : "r"(a0), "r"(a1), "r"(a2), "r"(a3), "r"(b0), "r"(b1));
}

__device__ __forceinline__ void ldsm4(unsigned* r, unsigned a) {
    asm volatile("ldmatrix.sync.aligned.m8n8.x4.shared.b16 {%0,%1,%2,%3}, [%4];\n"
                 : "=r"(r[0]), "=r"(r[1]), "=r"(r[2]), "=r"(r[3]) : "r"(a));
}

__device__ __forceinline__ void cp16(unsigned dst, const void* src) {
    asm volatile("cp.async.cg.shared.global [%0], [%1], 16;\n" :: "r"(dst), "l"(src));
}

// ---------------- NT GEMM: C[M,N] = A[M,K] @ B[N,K]^T ----------------------
// BM = MT*32, BN=128, BK=32, 256 threads; A and B single fp16 (64B rows).
// OUT 0: fp32. 1: single f16. 4: fused QKV (rope q/k, transpose v).
template<int MT, bool BIAS, bool RELU, int OUT>
__global__ __launch_bounds__(256)
void gemm_f16(const f16* __restrict__ A, const f16* __restrict__ B,
              const float* __restrict__ bias, const float2* __restrict__ rope,
              float* __restrict__ Cf, f16* __restrict__ Ch,
              f16* __restrict__ Chk, f16* __restrict__ Chv,
              int K, int lda, int ldb, int ldc) {
    extern __shared__ char dsm[];
    unsigned s0 = (unsigned)__cvta_generic_to_shared(dsm);
    s0 = (s0 + 1023) & ~1023u;

    constexpr int BM     = MT * 32;
    constexpr int ABYTES = BM * 64;
    constexpr int STAGE  = ABYTES + 8192;
    constexpr int ACH    = BM * 4;
    constexpr int NCH    = (ACH + 512) / 256;

    const int bm = blockIdx.y * BM, bn = blockIdx.x * 128;
    const int tid = threadIdx.x, lane = tid & 31, warp = tid >> 5;
    const int wm = (warp >> 2) * (MT * 16), wn = (warp & 3) * 32;
    const int g = lane >> 2, tig = lane & 3;

    float acc[MT][4][4] = {};

    auto issue = [&](int kt, unsigned SA) {
        const unsigned SB = SA + ABYTES;
#pragma unroll
        for (int i = 0; i < NCH; i++) {
            const int lin = i * 256 + tid;
            if (lin < ACH) {
                const int row = lin >> 2, c = lin & 3;
                cp16(SA + row * 64 + ((c ^ ((row >> 1) & 3)) << 4),
                     A + (size_t)(bm + row) * lda + kt + c * 8);
            } else {
                const int idx = lin - ACH;
                const int row = idx >> 2, c = idx & 3;
                cp16(SB + row * 64 + ((c ^ ((row >> 1) & 3)) << 4),
                     B + (size_t)(bn + row) * ldb + kt + c * 8);
            }
        }
        asm volatile("cp.async.commit_group;\n");
    };

    const int nk = K >> 5;
    issue(0, s0);

    for (int t = 0; t < nk; t++) {
        const unsigned SA = s0 + (t & 1) * STAGE;
        const unsigned SB = SA + ABYTES;
        if (t + 1 < nk) {
            issue((t + 1) * 32, s0 + ((t + 1) & 1) * STAGE);
            asm volatile("cp.async.wait_group 1;\n");
        } else {
            asm volatile("cp.async.wait_group 0;\n");
        }
        __syncthreads();

#pragma unroll
        for (int ks = 0; ks < 2; ks++) {
            unsigned ah[MT][4], bh[4][2];
#pragma unroll
            for (int mt = 0; mt < MT; mt++) {
                const int r  = wm + mt * 16 + (lane & 15);
                const int lc = 2 * ks + (lane >> 4);
                ldsm4(ah[mt], SA + r * 64 + ((lc ^ ((r >> 1) & 3)) << 4));
            }
#pragma unroll
            for (int p = 0; p < 2; p++) {
                const int r  = wn + p * 16 + (lane & 7) + ((lane >> 4) << 3);
                const int lc = 2 * ks + ((lane >> 3) & 1);
                unsigned th[4];
                ldsm4(th, SB + r * 64 + ((lc ^ ((r >> 1) & 3)) << 4));
                bh[2*p][0]   = th[0]; bh[2*p][1]   = th[1];
                bh[2*p+1][0] = th[2]; bh[2*p+1][1] = th[3];
            }
#pragma unroll
            for (int mt = 0; mt < MT; mt++)
#pragma unroll
                for (int nt = 0; nt < 4; nt++)
                    mma16816(acc[mt][nt], ah[mt][0], ah[mt][1], ah[mt][2], ah[mt][3],
                             bh[nt][0], bh[nt][1]);
        }
        __syncthreads();
    }

    // ---------------- epilogue ----------------
#pragma unroll
    for (int mt = 0; mt < MT; mt++) {
#pragma unroll
        for (int nt = 0; nt < 4; nt++) {
            const int row = bm + wm + mt * 16 + g;
            const int col = bn + wn + nt * 8 + tig * 2;
            float c0 = acc[mt][nt][0], c1 = acc[mt][nt][1];
            float c2 = acc[mt][nt][2], c3 = acc[mt][nt][3];
            if (BIAS) {
                const float b0 = bias[col], b1 = bias[col + 1];
                c0 += b0; c1 += b1; c2 += b0; c3 += b1;
            }
            if (RELU) {
                c0 = fmaxf(c0, 0.f); c1 = fmaxf(c1, 0.f);
                c2 = fmaxf(c2, 0.f); c3 = fmaxf(c3, 0.f);
            }
            if (OUT == 0) {
                *(float2*)&Cf[(size_t)row * ldc + col]       = make_float2(c0, c1);
                *(float2*)&Cf[(size_t)(row + 8) * ldc + col] = make_float2(c2, c3);
            } else if (OUT == 1) {
                *(__half2*)&Ch[(size_t)row * ldc + col] =
                    __halves2half2(__float2half_rn(c0), __float2half_rn(c1));
                *(__half2*)&Ch[(size_t)(row + 8) * ldc + col] =
                    __halves2half2(__float2half_rn(c2), __float2half_rn(c3));
            } else {
                // fused QKV: cols [0,512)=Q rope, [512,1024)=K rope, [1024,2048)=V^T
                if (bn < 1024) {
                    const int d2 = (col & 63) >> 1;
                    const float2 r0 = rope[(size_t)(row & 2047) * 32 + d2];
                    const float2 r1 = rope[(size_t)((row + 8) & 2047) * 32 + d2];
                    f16* dst = (bn < 512) ? Ch : Chk;
                    const int cc = col & 511;
                    *(__half2*)&dst[(size_t)row * HIDDEN + cc] =
                        __halves2half2(__float2half_rn(c0 * r0.x - c1 * r0.y),
                                       __float2half_rn(c1 * r0.x + c0 * r0.y));
                    *(__half2*)&dst[(size_t)(row + 8) * HIDDEN + cc] =
                        __halves2half2(__float2half_rn(c2 * r1.x - c3 * r1.y),
                                       __float2half_rn(c3 * r1.x + c2 * r1.y));
                } else {
                    const int n = col - 1024;
                    const size_t basev = (size_t)(row >> 11) * VDIM * SLEN;
                    const int s1 = row & 2047, s2 = (row + 8) & 2047;
                    Chv[basev + (size_t)n       * SLEN + s1] = __float2half_rn(c0);
                    Chv[basev + (size_t)(n + 1) * SLEN + s1] = __float2half_rn(c1);
                    Chv[basev + (size_t)n       * SLEN + s2] = __float2half_rn(c2);
                    Chv[basev + (size_t)(n + 1) * SLEN + s2] = __float2half_rn(c3);
                }
            }
        }
    }
}

// ---------------- flash attention: Q in registers, 3-stage KV ---------------
// One CTA = (128 q rows) x (one head); 8 warps x 16 q rows.
__global__ __launch_bounds__(256, 1)
void flash_attn(const f16* __restrict__ Q, const f16* __restrict__ Kp,
                const f16* __restrict__ V, f16* __restrict__ Oh) {
    extern __shared__ char dsm[];
    unsigned s0 = (unsigned)__cvta_generic_to_shared(dsm);
    s0 = (s0 + 1023) & ~1023u;
    const int qt = blockIdx.x, z = blockIdx.y;
    const int b = z >> 3, h = z & 7;
    const int tid = threadIdx.x, lane = tid & 31, warp = tid >> 5;

    const f16* Qb = Q + ((size_t)(b * SLEN + qt * 128)) * HIDDEN + h * KD;
    const f16* Kb = Kp + (size_t)b * SLEN * HIDDEN + h * KD;
    const f16* Vb = V + ((size_t)b * VDIM + h * HSZ) * SLEN;

    const int rA = warp * 16 + (lane & 15);
    const int rB = (lane & 7) + ((lane >> 4) << 3);
    const int cBsel = (lane >> 3) & 1;

    // ---- stage Q through smem (stage-0 K area) into persistent regs ----
#pragma unroll
    for (int i = 0; i < 4; i++) {
        const int lin = i * 256 + tid;
        const int row = lin >> 3, c = lin & 7;
        cp16(s0 + row * 128 + ((c ^ (row & 7)) << 4), Qb + (size_t)row * HIDDEN + c * 8);
    }
    asm volatile("cp.async.commit_group;\ncp.async.wait_group 0;\n");
    __syncthreads();
    unsigned aq[4][4];
#pragma unroll
    for (int ks = 0; ks < 4; ks++) {
        const int lc = ks * 2 + (lane >> 4);
        ldsm4(aq[ks], s0 + rA * 128 + ((lc ^ (rA & 7)) << 4));
    }
    __syncthreads();

    auto issue_kv = [&](int kt) {
        const unsigned SK = s0 + (kt % 3) * 49152;
        const unsigned SV = SK + 16384;
#pragma unroll
        for (int i = 0; i < 12; i++) {
            const int lin = i * 256 + tid;
            if (lin < 1024) {
                const int row = lin >> 3, c = lin & 7;
                cp16(SK + row * 128 + ((c ^ (row & 7)) << 4),
                     Kb + (size_t)(kt * 128 + row) * HIDDEN + c * 8);
            } else {
                const int idx = lin - 1024;
                const int n = idx >> 4, c = idx & 15;
                cp16(SV + n * 256 + ((c ^ (n & 7)) << 4),
                     Vb + (size_t)n * SLEN + kt * 128 + c * 8);
            }
        }
        asm volatile("cp.async.commit_group;\n");
    };
    issue_kv(0);
    issue_kv(1);

    float O[16][4] = {};
    float m0 = -INFINITY, m1 = -INFINITY, l0 = 0.f, l1 = 0.f;

    for (int t = 0; t < 16; t++) {
        const unsigned SK = s0 + (t % 3) * 49152;
        const unsigned SV = SK + 16384;
        if (t + 2 < 16) {
            issue_kv(t + 2);
            asm volatile("cp.async.wait_group 2;\n");
        } else if (t + 1 < 16) {
            asm volatile("cp.async.wait_group 1;\n");
        } else {
            asm volatile("cp.async.wait_group 0;\n");
        }
        __syncthreads();

        // ---- S = Q K^T ----
        float S[16][4] = {};
#pragma unroll
        for (int ks = 0; ks < 4; ks++) {
            const int lcB = ks * 2 + cBsel;
#pragma unroll
            for (int p = 0; p < 8; p++) {
                const int r2 = p * 16 + rB;
                unsigned tb[4];
                ldsm4(tb, SK + r2 * 128 + ((lcB ^ (r2 & 7)) << 4));
                mma16816(S[2*p],   aq[ks][0], aq[ks][1], aq[ks][2], aq[ks][3], tb[0], tb[1]);
                mma16816(S[2*p+1], aq[ks][0], aq[ks][1], aq[ks][2], aq[ks][3], tb[2], tb[3]);
            }
        }

        // ---- online softmax ----
        float mx0 = -INFINITY, mx1 = -INFINITY;
#pragma unroll
        for (int nt = 0; nt < 16; nt++) {
            mx0 = fmaxf(mx0, fmaxf(S[nt][0], S[nt][1]));
            mx1 = fmaxf(mx1, fmaxf(S[nt][2], S[nt][3]));
        }
        mx0 = fmaxf(mx0, __shfl_xor_sync(0xffffffffu, mx0, 1));
        mx0 = fmaxf(mx0, __shfl_xor_sync(0xffffffffu, mx0, 2));
        mx1 = fmaxf(mx1, __shfl_xor_sync(0xffffffffu, mx1, 1));
        mx1 = fmaxf(mx1, __shfl_xor_sync(0xffffffffu, mx1, 2));
        const float nm0 = fmaxf(m0, mx0), nm1 = fmaxf(m1, mx1);
        const float sc0 = __expf(m0 - nm0), sc1 = __expf(m1 - nm1);
        m0 = nm0; m1 = nm1;
        float rs0 = 0.f, rs1 = 0.f;
#pragma unroll
        for (int nt = 0; nt < 16; nt++) {
            S[nt][0] = __expf(S[nt][0] - nm0);
            S[nt][1] = __expf(S[nt][1] - nm0);
            S[nt][2] = __expf(S[nt][2] - nm1);
            S[nt][3] = __expf(S[nt][3] - nm1);
            rs0 += S[nt][0] + S[nt][1];
            rs1 += S[nt][2] + S[nt][3];
            O[nt][0] *= sc0; O[nt][1] *= sc0;
            O[nt][2] *= sc1; O[nt][3] *= sc1;
        }
        rs0 += __shfl_xor_sync(0xffffffffu, rs0, 1);
        rs0 += __shfl_xor_sync(0xffffffffu, rs0, 2);
        rs1 += __shfl_xor_sync(0xffffffffu, rs1, 1);
        rs1 += __shfl_xor_sync(0xffffffffu, rs1, 2);
        l0 = l0 * sc0 + rs0;
        l1 = l1 * sc1 + rs1;

        // ---- O += P V ----
#pragma unroll
        for (int j = 0; j < 8; j++) {
            const unsigned a0 = h2pack(S[2*j][0],   S[2*j][1]);
            const unsigned a1 = h2pack(S[2*j][2],   S[2*j][3]);
            const unsigned a2 = h2pack(S[2*j+1][0], S[2*j+1][1]);
            const unsigned a3 = h2pack(S[2*j+1][2], S[2*j+1][3]);
            const int lcV = j * 2 + cBsel;
#pragma unroll
            for (int p = 0; p < 8; p++) {
                const int r2 = p * 16 + rB;
                unsigned tb[4];
                ldsm4(tb, SV + r2 * 256 + ((lcV ^ (r2 & 7)) << 4));
                mma16816(O[2*p],   a0, a1, a2, a3, tb[0], tb[1]);
                mma16816(O[2*p+1], a0, a1, a2, a3, tb[2], tb[3]);
            }
        }
        __syncthreads();
    }

    const float inv0 = SCALING / l0, inv1 = SCALING / l1;
    const int g = lane >> 2, tg = lane & 3;
    const int srow = qt * 128 + warp * 16 + g;
    const size_t base0 = ((size_t)(b * SLEN) + srow) * VDIM + h * HSZ;
    const size_t base1 = base0 + (size_t)8 * VDIM;
#pragma unroll
    for (int nt = 0; nt < 16; nt++) {
        const int col = nt * 8 + tg * 2;
        *(__half2*)&Oh[base0 + col] =
            __halves2half2(__float2half_rn(O[nt][0] * inv0), __float2half_rn(O[nt][1] * inv0));
        *(__half2*)&Oh[base1 + col] =
            __halves2half2(__float2half_rn(O[nt][2] * inv1), __float2half_rn(O[nt][3] * inv1));
    }
}

// ---------------- batched weight transpose + fp16 ---------------------------
struct TSegs {
    const float* src[12];
    int dstoff[12];
    int K[12], N[12], tile0[12];
};

__global__ __launch_bounds__(256)
void transpose_cvt_all(TSegs segs, f16* __restrict__ dstbase) {
    __shared__ float t[32][33];
    const int tb = blockIdx.x;
    int s = 0;
#pragma unroll
    for (int i = 1; i < 12; i++) if (tb >= segs.tile0[i]) s = i;
    const int local = tb - segs.tile0[s];
    const int tilesX = segs.N[s] >> 5;
    const int nb = (local % tilesX) << 5;
    const int kb = (local / tilesX) << 5;
    const float* src = segs.src[s];
    f16* dst = dstbase + segs.dstoff[s];
    const int K = segs.K[s], N = segs.N[s];
    const int tx = threadIdx.x & 31, ty = threadIdx.x >> 5;
#pragma unroll
    for (int i = ty; i < 32; i += 8)
        t[i][tx] = src[(size_t)(kb + i) * N + nb + tx];
    __syncthreads();
#pragma unroll
    for (int i = ty; i < 32; i += 8)
        dst[(size_t)(nb + i) * K + kb + tx] = __float2half_rn(t[tx][i]);
}

// ---------------- rope table -------------------------------------------------
__global__ __launch_bounds__(256)
void build_rope(float2* __restrict__ rope) {
    const int idx = blockIdx.x * 256 + threadIdx.x;
    const int d2 = idx & 31, s = idx >> 5;
    const float base  = (2.f * d2 + 25.6f) / 89.6f;
    const float scale = powf(base, (float)(s - 1024) * (1.f / 512.f));
    const float invf  = powf(10000.f, -(float)d2 * (1.f / 32.f));
    float sv, cv;
    sincosf((float)s * invf, &sv, &cv);
    rope[idx] = make_float2(cv * scale, sv * scale);
}

// ---------------- elementwise fp32 -> fp16 ----------------------------------
__global__ __launch_bounds__(256)
void cvt_f16(const float* __restrict__ src, f16* __restrict__ dh) {
    const int i = blockIdx.x * 256 + threadIdx.x;
    dh[i] = __float2half_rn(src[i]);
}

// ---------------- block reduce / add_ln ------------------------------------
__device__ __forceinline__ float block_reduce(float v, float* sh, int op) {
#pragma unroll
    for (int o = 16; o; o >>= 1) {
        float t = __shfl_xor_sync(0xffffffffu, v, o);
        v = op ? fmaxf(v, t) : v + t;
    }
    if ((threadIdx.x & 31) == 0) sh[threadIdx.x >> 5] = v;
    __syncthreads();
    if (threadIdx.x < 32) {
        const int nw = blockDim.x >> 5;
        float t = (threadIdx.x < nw) ? sh[threadIdx.x] : (op ? -INFINITY : 0.f);
#pragma unroll
        for (int o = 16; o; o >>= 1) {
            float u = __shfl_xor_sync(0xffffffffu, t, o);
            t = op ? fmaxf(t, u) : t + u;
        }
        if (threadIdx.x == 0) sh[0] = t;
    }
    __syncthreads();
    float r = sh[0];
    __syncthreads();
    return r;
}

__global__ __launch_bounds__(256)
void add_ln(const float* __restrict__ a, const float* __restrict__ b,
            const float* __restrict__ g, const float* __restrict__ be,
            float* __restrict__ out, f16* __restrict__ oh) {
    __shared__ float sh[32];
    const size_t r = (size_t)blockIdx.x * HIDDEN;
    const int t = threadIdx.x;
    float v0 = a[r + t]       + b[r + t];
    float v1 = a[r + t + 256] + b[r + t + 256];
    float mean = block_reduce(v0 + v1, sh, 0) * (1.f / HIDDEN);
    float d0 = v0 - mean, d1 = v1 - mean;
    float var = block_reduce(d0 * d0 + d1 * d1, sh, 0) * (1.f / HIDDEN);
    float inv = rsqrtf(var + LN_EPS);
    const float o0 = d0 * inv * g[t]       + be[t];
    const float o1 = d1 * inv * g[t + 256] + be[t + 256];
    out[r + t]       = o0;
    out[r + t + 256] = o1;
    oh[r + t]       = __float2half_rn(o0);
    oh[r + t + 256] = __float2half_rn(o1);
}

// ---------------- driver ----------------------------------------------------
#define SMEM_MT4   (2*16384 + 1024)
#define SMEM_MT2   (2*12288 + 1024)
#define SMEM_FLASH (3*49152 + 1024)

extern "C" void kernel_launch(void* const* d_in, const int* in_sizes, int n_in,
                              void* d_out, int out_size) {
    const float* x   = (const float*)d_in[0];
    const float* Wq  = (const float*)d_in[1];
    const float* Wk  = (const float*)d_in[2];
    const float* Wv  = (const float*)d_in[3];
    const float* Wo  = (const float*)d_in[4];
    const float* W1  = (const float*)d_in[5];
    const float* b1  = (const float*)d_in[6];
    const float* W2  = (const float*)d_in[7];
    const float* b2  = (const float*)d_in[8];
    const float* g1  = (const float*)d_in[9];
    const float* be1 = (const float*)d_in[10];
    const float* g2  = (const float*)d_in[11];
    const float* be2 = (const float*)d_in[12];

    float *proj, *y, *xb;
    f16 *xh, *qh, *kh, *vt, *att, *yh, *f1h, *wt;
    float2* rope;
    cudaGetSymbolAddress((void**)&proj, g_proj);
    cudaGetSymbolAddress((void**)&y,    g_y);
    cudaGetSymbolAddress((void**)&xb,   g_x);
    cudaGetSymbolAddress((void**)&xh,   g_xh);
    cudaGetSymbolAddress((void**)&qh,   g_qh);
    cudaGetSymbolAddress((void**)&kh,   g_kh);
    cudaGetSymbolAddress((void**)&vt,   g_vt);
    cudaGetSymbolAddress((void**)&att,  g_att);
    cudaGetSymbolAddress((void**)&yh,   g_yh);
    cudaGetSymbolAddress((void**)&f1h,  g_f1h);
    cudaGetSymbolAddress((void**)&wt,   g_wt);
    cudaGetSymbolAddress((void**)&rope, g_rope);

    static bool attr_done = false;
    if (!attr_done) {
        cudaFuncSetAttribute((const void*)gemm_f16<4,false,false,4>, cudaFuncAttributeMaxDynamicSharedMemorySize, SMEM_MT4);
        cudaFuncSetAttribute((const void*)gemm_f16<2,false,false,0>, cudaFuncAttributeMaxDynamicSharedMemorySize, SMEM_MT2);
        cudaFuncSetAttribute((const void*)gemm_f16<4,true,true,1>,   cudaFuncAttributeMaxDynamicSharedMemorySize, SMEM_MT4);
        cudaFuncSetAttribute((const void*)gemm_f16<2,true,false,0>,  cudaFuncAttributeMaxDynamicSharedMemorySize, SMEM_MT2);
        cudaFuncSetAttribute((const void*)flash_attn,                cudaFuncAttributeMaxDynamicSharedMemorySize, SMEM_FLASH);
        attr_done = true;
    }

    const dim3 T(256);

    // ---- one batched transpose launch for all 12 weight matrices ----
    {
        TSegs segs;
        int tile = 0;
        int si = 0;
        for (int l = 0; l < 2; l++) {
            const float* srcs[6] = {Wq + (size_t)l*HIDDEN*HIDDEN, Wk + (size_t)l*HIDDEN*HIDDEN,
                                    Wv + (size_t)l*HIDDEN*VDIM,   Wo + (size_t)l*VDIM*HIDDEN,
                                    W1 + (size_t)l*HIDDEN*FFNDIM, W2 + (size_t)l*FFNDIM*HIDDEN};
            const int offs[6] = {OFF_WQ, OFF_WK, OFF_WV, OFF_WO, OFF_W1, OFF_W2};
            const int Ks[6]   = {HIDDEN, HIDDEN, HIDDEN, VDIM, HIDDEN, FFNDIM};
            const int Ns[6]   = {HIDDEN, HIDDEN, VDIM, HIDDEN, FFNDIM, HIDDEN};
            for (int j = 0; j < 6; j++, si++) {
                segs.src[si] = srcs[j];
                segs.dstoff[si] = l * WT_PER_LAYER + offs[j];
                segs.K[si] = Ks[j]; segs.N[si] = Ns[j];
                segs.tile0[si] = tile;
                tile += (Ks[j] >> 5) * (Ns[j] >> 5);
            }
        }
        transpose_cvt_all<<<tile, T>>>(segs, wt);
    }

    build_rope<<<(SLEN*32)/256, T>>>(rope);
    cvt_f16<<<(ROWS*HIDDEN)/256, T>>>(x, xh);

    for (int i = 0; i < 2; i++) {
        const float* xin  = i ? xb : x;
        float*       xout = i ? (float*)d_out : xb;
        f16* base = wt + (size_t)i * WT_PER_LAYER;

        // fused QKV projection: N=2048 = [Q|K|V], rope + transpose in epilogue
        gemm_f16<4,false,false,4><<<dim3(16, ROWS/128), T, SMEM_MT4>>>(
            xh, base+OFF_WQ, nullptr, rope, nullptr, qh, kh, vt,
            HIDDEN, HIDDEN, HIDDEN, 0);

        flash_attn<<<dim3(SLEN/128, BSZ*HEADS), T, SMEM_FLASH>>>(qh, kh, vt, att);

        // output projection
        gemm_f16<2,false,false,0><<<dim3(4, ROWS/64), T, SMEM_MT2>>>(
            att, base+OFF_WO, nullptr, nullptr, proj, nullptr, nullptr, nullptr,
            VDIM, VDIM, VDIM, HIDDEN);

        add_ln<<<ROWS, T>>>(xin, proj, g1 + i*HIDDEN, be1 + i*HIDDEN, y, yh);

        // FFN
        gemm_f16<4,true,true,1><<<dim3(16, ROWS/128), T, SMEM_MT4>>>(
            yh, base+OFF_W1, b1 + i*FFNDIM, nullptr, nullptr, f1h, nullptr, nullptr,
            HIDDEN, HIDDEN, HIDDEN, FFNDIM);
        gemm_f16<2,true,false,0><<<dim3(4, ROWS/64), T, SMEM_MT2>>>(
            f1h, base+OFF_W2, b2 + i*HIDDEN, nullptr, proj, nullptr, nullptr, nullptr,
            FFNDIM, FFNDIM, FFNDIM, HIDDEN);

        add_ln<<<ROWS, T>>>(y, proj, g2 + i*HIDDEN, be2 + i*HIDDEN, xout, xh);
    }
}